// round 2
// baseline (speedup 1.0000x reference)
#include <cuda_runtime.h>
#include <cuda_bf16.h>
#include <cstdint>

// ---------------- problem constants ----------------
#define BB 8
#define TT 8
#define CC 128
#define HH 32
#define WW 32
#define NSP 1024          // H*W
#define KK 512            // kept tokens (epoch 20 -> ratio 0.5)
#define DI 256            // d_inner
#define DS 16             // d_state
#define DTR 8             // dt_rank
#define NH 4
#define DH 32
#define ROWS 32768        // B*K*T
#define BT 64             // B*T
#define NBATCH 256        // BT*NH

// ---------------- device scratch (allocation-free) ----------------
__device__ float g_xm  [BB*CC*NSP];            // mean over T
__device__ float g_h1  [BB*32*NSP];            // router conv1
__device__ float g_sc  [BB*NSP];               // sigmoid scores
__device__ int   g_idx [BB*KK];
__device__ float g_scl [BB*KK];
__device__ float g_z0  [(size_t)ROWS*CC];      // gathered + rmsnormed
__device__ float g_xz  [(size_t)ROWS*2*DI];    // in_proj out
__device__ float g_xc  [(size_t)ROWS*DI];      // conv1d+silu
__device__ float g_xdbl[(size_t)ROWS*40];      // x_proj out (dt8|B16|C16)
__device__ float g_dt  [(size_t)ROWS*DI];      // softplus dt
__device__ float g_yg  [(size_t)ROWS*DI];      // gated scan out
__device__ float g_zm  [(size_t)ROWS*CC];      // mamba out (b,k,t,c)
__device__ float g_zs  [(size_t)ROWS*CC];      // (b,t,k,c)
__device__ float g_qkv [(size_t)ROWS*3*CC];
__device__ float g_q   [(size_t)NBATCH*KK*DH];
__device__ float g_k   [(size_t)NBATCH*KK*DH];
__device__ float g_vt  [(size_t)NBATCH*DH*KK]; // V transposed
__device__ float g_S   [(size_t)NBATCH*KK*KK]; // 256 MB scores
__device__ float g_oat [(size_t)NBATCH*KK*DH];
__device__ float g_orp [(size_t)ROWS*CC];      // o repacked (bt,q,c)
__device__ float g_tmo [(size_t)ROWS*CC];      // o @ Wo + b
__device__ float g_zo  [(size_t)ROWS*CC];      // layernorm out

// ---------------- helpers ----------------
__device__ __forceinline__ float sigm(float x){ return 1.f/(1.f+__expf(-x)); }
__device__ __forceinline__ float siluf(float x){ return x*sigm(x); }
__device__ __forceinline__ float softplusf(float x){ return (x>20.f)?x:log1pf(__expf(x)); }

__device__ __forceinline__ float blockReduce128(float v, float* red){
    #pragma unroll
    for (int o=16;o>0;o>>=1) v += __shfl_xor_sync(0xffffffffu, v, o);
    int w = threadIdx.x >> 5;
    if ((threadIdx.x & 31)==0) red[w]=v;
    __syncthreads();
    return red[0]+red[1]+red[2]+red[3];
}

// ---------------- generic fp32 TN GEMM: C = A * Bw^T (+bias)(+act) ----------------
// A: M x Kd (lda), Bw: N x Kd (ldb), C: M x N (ldc). Batched via blockIdx.z.
__global__ void gemm_tn(const float* __restrict__ A, const float* __restrict__ Bw,
                        const float* __restrict__ bias, float* __restrict__ C,
                        int M, int N, int Kd, int lda, int ldb, int ldc,
                        long aS, long bS, long cS, int act)
{
    __shared__ float As[16][68];
    __shared__ float Bs[16][68];
    const float* Ab = A + (long)blockIdx.z * aS;
    const float* Bb = Bw + (long)blockIdx.z * bS;
    float* Cb = C + (long)blockIdx.z * cS;
    int m0 = blockIdx.y * 64, n0 = blockIdx.x * 64;
    int tid = threadIdx.x;
    int tx = tid & 15, ty = tid >> 4;
    float acc[4][4] = {};
    for (int k0 = 0; k0 < Kd; k0 += 16) {
        #pragma unroll
        for (int i = tid; i < 1024; i += 256) {
            int kk = i & 15, mm = i >> 4;
            int gm = m0 + mm, gk = k0 + kk;
            As[kk][mm] = (gm < M && gk < Kd) ? Ab[(long)gm*lda + gk] : 0.f;
        }
        #pragma unroll
        for (int i = tid; i < 1024; i += 256) {
            int kk = i & 15, nn = i >> 4;
            int gn = n0 + nn, gk = k0 + kk;
            Bs[kk][nn] = (gn < N && gk < Kd) ? Bb[(long)gn*ldb + gk] : 0.f;
        }
        __syncthreads();
        #pragma unroll
        for (int k = 0; k < 16; k++) {
            float4 a4 = *(const float4*)&As[k][ty*4];
            float4 b4 = *(const float4*)&Bs[k][tx*4];
            float av[4] = {a4.x,a4.y,a4.z,a4.w};
            float bv[4] = {b4.x,b4.y,b4.z,b4.w};
            #pragma unroll
            for (int i=0;i<4;i++)
                #pragma unroll
                for (int j=0;j<4;j++)
                    acc[i][j] += av[i]*bv[j];
        }
        __syncthreads();
    }
    #pragma unroll
    for (int i=0;i<4;i++){
        int gm = m0 + ty*4 + i;
        if (gm >= M) continue;
        #pragma unroll
        for (int j=0;j<4;j++){
            int gn = n0 + tx*4 + j;
            if (gn >= N) continue;
            float v = acc[i][j];
            if (bias) v += bias[gn];
            if (act==1) v = softplusf(v);
            Cb[(long)gm*ldc + gn] = v;
        }
    }
}

// ---------------- stage kernels ----------------
__global__ void k_copy(const float4* __restrict__ in, float4* __restrict__ out, int n4){
    int i = blockIdx.x*blockDim.x + threadIdx.x;
    if (i < n4) out[i] = in[i];
}

__global__ void k_mean(const float* __restrict__ x, float* __restrict__ xm){
    int i = blockIdx.x*blockDim.x + threadIdx.x;
    if (i >= BB*CC*NSP) return;
    int b = i >> 17; int rem = i & 131071;  // CC*NSP = 131072
    float s = 0.f;
    #pragma unroll
    for (int t=0;t<TT;t++) s += x[((long)b*TT+t)*131072 + rem];
    xm[i] = s * 0.125f;
}

__global__ void k_conv3(const float* __restrict__ xm, const float* __restrict__ w,
                        const float* __restrict__ bias, float* __restrict__ h1){
    __shared__ float pl[34*34];
    int bo = blockIdx.x; int b = bo >> 5; int oc = bo & 31;
    int tid = threadIdx.x;
    int h = tid >> 5, wq = tid & 31;
    float acc = 0.f;
    for (int ic=0; ic<CC; ic++){
        for (int i=tid; i<34*34; i+=1024){
            int hh = i/34 - 1, ww = i%34 - 1;
            pl[i] = (hh>=0 && hh<32 && ww>=0 && ww<32) ?
                    xm[((long)b*CC+ic)*NSP + hh*32+ww] : 0.f;
        }
        __syncthreads();
        const float* wp = w + ((long)oc*CC+ic)*9;
        #pragma unroll
        for (int kh=0;kh<3;kh++)
            #pragma unroll
            for (int kw=0;kw<3;kw++)
                acc += pl[(h+kh)*34 + (wq+kw)] * wp[kh*3+kw];
        __syncthreads();
    }
    acc += bias[oc];
    h1[(long)bo*NSP + tid] = (acc >= 0.f) ? acc : 0.01f*acc;
}

__global__ void k_score(const float* __restrict__ h1, const float* __restrict__ w2,
                        const float* __restrict__ b2, float* __restrict__ sc){
    int i = blockIdx.x*blockDim.x + threadIdx.x;
    if (i >= BB*NSP) return;
    int b = i >> 10, n = i & 1023;
    float a = 0.f;
    #pragma unroll
    for (int oc=0;oc<32;oc++) a += h1[((long)b*32+oc)*NSP + n] * w2[oc];
    a += b2[0];
    sc[i] = sigm(a);
}

__global__ void k_topk(const float* __restrict__ sc, int* __restrict__ idx,
                       float* __restrict__ scl){
    __shared__ float s[1024];
    __shared__ unsigned char keep[1024];
    int b = blockIdx.x, n = threadIdx.x;
    s[n] = sc[b*NSP + n];
    __syncthreads();
    float v = s[n];
    int cnt = 0;
    for (int m=0;m<1024;m++){ float u = s[m]; cnt += (u>v) || (u==v && m<n); }
    keep[n] = (cnt < KK) ? 1 : 0;
    __syncthreads();
    if (keep[n]){
        int pos = 0;
        for (int m=0;m<n;m++) pos += keep[m];
        idx[b*KK + pos] = n;
        scl[b*KK + pos] = v / (v + 1e-6f);
    }
}

__global__ void k_gather(const float* __restrict__ x, const int* __restrict__ idx,
                         const float* __restrict__ scl, const float* __restrict__ nw,
                         float* __restrict__ z0){
    __shared__ float red[4];
    long tok = blockIdx.x;               // (b*K + k)*T + t
    int t = tok & 7; long bk = tok >> 3;
    int b = (int)(bk >> 9); int k = (int)(bk & 511);
    int c = threadIdx.x;
    int n = idx[b*KK + k];
    float sf = scl[b*KK + k];
    float v = x[(((long)b*TT + t)*CC + c)*NSP + n] * sf;
    float ss = blockReduce128(v*v, red);
    float r = rsqrtf(ss * (1.f/128.f) + 1e-5f);
    z0[tok*CC + c] = v * r * nw[c];
}

__global__ void k_conv1d(const float* __restrict__ xz, const float* __restrict__ w,
                         const float* __restrict__ bias, float* __restrict__ xc){
    int s = blockIdx.x; int ch = threadIdx.x;   // 4096 blocks x 256 thr
    float in[TT];
    #pragma unroll
    for (int t=0;t<TT;t++) in[t] = xz[(((long)s*TT + t)*(2*DI)) + ch];
    float w0=w[ch*4+0], w1=w[ch*4+1], w2=w[ch*4+2], w3=w[ch*4+3];
    float bb = bias[ch];
    #pragma unroll
    for (int t=0;t<TT;t++){
        float a = bb + in[t]*w3;
        if (t>=1) a += in[t-1]*w2;
        if (t>=2) a += in[t-2]*w1;
        if (t>=3) a += in[t-3]*w0;
        xc[((long)s*TT + t)*DI + ch] = siluf(a);
    }
}

__global__ void k_scan(const float* __restrict__ xc, const float* __restrict__ xdbl,
                       const float* __restrict__ dtb, const float* __restrict__ Alog,
                       const float* __restrict__ Dp, const float* __restrict__ xz,
                       float* __restrict__ yg){
    int s = blockIdx.x; int ch = threadIdx.x;   // 4096 blocks x 256 thr
    float Arow[DS];
    #pragma unroll
    for (int d=0;d<DS;d++) Arow[d] = -__expf(Alog[ch*DS + d]);
    float Dv = Dp[ch];
    float h[DS];
    #pragma unroll
    for (int d=0;d<DS;d++) h[d] = 0.f;
    #pragma unroll
    for (int t=0;t<TT;t++){
        long row = (long)s*TT + t;
        float dt = dtb[row*DI + ch];
        float u  = xc[row*DI + ch];
        float du = dt*u;
        float y = 0.f;
        #pragma unroll
        for (int d=0;d<DS;d++){
            float Bv = xdbl[row*40 + DTR + d];
            float Cv = xdbl[row*40 + DTR + DS + d];
            h[d] = h[d]*__expf(dt*Arow[d]) + du*Bv;
            y += h[d]*Cv;
        }
        float zg = xz[row*(2*DI) + DI + ch];
        yg[row*DI + ch] = (y + u*Dv) * siluf(zg);
    }
}

__global__ void k_zs(const float* __restrict__ zm, float* __restrict__ zs){
    long i = (long)blockIdx.x*blockDim.x + threadIdx.x;  // 4194304
    if (i >= (long)ROWS*CC) return;
    int c = i & 127; long r = i >> 7;
    int k = (int)(r & 511); long r2 = r >> 9;
    int t = (int)(r2 & 7); int b = (int)(r2 >> 3);
    zs[i] = zm[((((long)b*KK + k)*TT + t) << 7) + c];
}

__global__ void k_qkvrp(const float* __restrict__ qkv, float* __restrict__ q,
                        float* __restrict__ kk_, float* __restrict__ vt){
    long i = (long)blockIdx.x*blockDim.x + threadIdx.x;  // 4194304
    if (i >= (long)NBATCH*KK*DH) return;
    int d = i & 31; long r = i >> 5;
    int qr = (int)(r & 511); long bh = r >> 9;     // bh in [0,256)
    int hh = (int)(bh & 3); long bt = bh >> 2;
    long src = ((bt*KK + qr)*(3*CC)) + hh*DH + d;
    q[i]   = qkv[src];
    kk_[i] = qkv[src + CC];
    vt[(bh*DH + d)*KK + qr] = qkv[src + 2*CC];
}

__global__ void k_softmax(float* __restrict__ S){
    int warp = blockIdx.x*8 + (threadIdx.x >> 5);   // 131072 rows
    int lane = threadIdx.x & 31;
    float* row = S + (long)warp*KK;
    float v[16]; float mx = -1e30f;
    #pragma unroll
    for (int i=0;i<16;i++){ v[i] = row[lane + i*32] * 0.17677669529663687f; mx = fmaxf(mx, v[i]); }
    #pragma unroll
    for (int o=16;o>0;o>>=1) mx = fmaxf(mx, __shfl_xor_sync(0xffffffffu, mx, o));
    float sum = 0.f;
    #pragma unroll
    for (int i=0;i<16;i++){ v[i] = __expf(v[i]-mx); sum += v[i]; }
    #pragma unroll
    for (int o=16;o>0;o>>=1) sum += __shfl_xor_sync(0xffffffffu, sum, o);
    float inv = 1.f/sum;
    #pragma unroll
    for (int i=0;i<16;i++) row[lane + i*32] = v[i]*inv;
}

__global__ void k_orp(const float* __restrict__ oat, float* __restrict__ orp){
    long i = (long)blockIdx.x*blockDim.x + threadIdx.x;  // 4194304 (bt,q,c)
    if (i >= (long)ROWS*CC) return;
    int c = i & 127; long r = i >> 7;
    int qr = (int)(r & 511); long bt = r >> 9;
    int hh = c >> 5, d = c & 31;
    orp[i] = oat[(((bt*NH + hh)*KK + qr) << 5) + d];
}

__global__ void k_ln(const float* __restrict__ zs, const float* __restrict__ tmo,
                     const float* __restrict__ w, const float* __restrict__ b,
                     float* __restrict__ zo){
    __shared__ float r1[4], r2[4];
    long r = blockIdx.x; int c = threadIdx.x;
    float v = zs[r*CC + c] + tmo[r*CC + c];
    float s = blockReduce128(v, r1);
    float mu = s * (1.f/128.f);
    float d = v - mu;
    float q = blockReduce128(d*d, r2);
    float var = q * (1.f/128.f);
    zo[r*CC + c] = d * rsqrtf(var + 1e-5f) * w[c] + b[c];
}

__global__ void k_scatter(const float* __restrict__ zo, const int* __restrict__ idx,
                          float* __restrict__ out){
    long i = (long)blockIdx.x*blockDim.x + threadIdx.x;  // (bt,k,c)
    if (i >= (long)ROWS*CC) return;
    int c = i & 127; long r = i >> 7;
    int k = (int)(r & 511); long bt = r >> 9;
    int b = (int)(bt >> 3);
    int n = idx[b*KK + k];
    out[((bt*CC) + c)*NSP + n] += zo[i];
}

// ---------------- host launch ----------------
static float* symf(const void* s){ void* p = nullptr; cudaGetSymbolAddress(&p, s); return (float*)p; }

static void gemm(const float* A, const float* Bw, const float* bias, float* C,
                 int M, int N, int Kd, int lda, int ldb, int ldc,
                 long aS, long bS, long cS, int nb, int act){
    dim3 g((N+63)/64, (M+63)/64, nb);
    gemm_tn<<<g, 256>>>(A, Bw, bias, C, M, N, Kd, lda, ldb, ldc, aS, bS, cS, act);
}

extern "C" void kernel_launch(void* const* d_in, const int* in_sizes, int n_in,
                              void* d_out, int out_size)
{
    const float* x_in      = (const float*)d_in[0];
    const float* norm1_w   = (const float*)d_in[1];
    const float* in_proj_w = (const float*)d_in[2];
    const float* conv1d_w  = (const float*)d_in[3];
    const float* conv1d_b  = (const float*)d_in[4];
    const float* x_proj_w  = (const float*)d_in[5];
    const float* dt_proj_w = (const float*)d_in[6];
    const float* dt_proj_b = (const float*)d_in[7];
    const float* A_log     = (const float*)d_in[8];
    const float* Dp        = (const float*)d_in[9];
    const float* out_proj_w= (const float*)d_in[10];
    const float* r1_w      = (const float*)d_in[11];
    const float* r1_b      = (const float*)d_in[12];
    const float* r2_w      = (const float*)d_in[13];
    const float* r2_b      = (const float*)d_in[14];
    const float* attn_in_w = (const float*)d_in[15];
    const float* attn_in_b = (const float*)d_in[16];
    const float* attn_out_w= (const float*)d_in[17];
    const float* attn_out_b= (const float*)d_in[18];
    const float* ln_w      = (const float*)d_in[19];
    const float* ln_b      = (const float*)d_in[20];
    float* out = (float*)d_out;

    float *xm = symf(g_xm), *h1 = symf(g_h1), *sc = symf(g_sc);
    float *scl = symf(g_scl), *z0 = symf(g_z0), *xz = symf(g_xz);
    float *xc = symf(g_xc), *xdbl = symf(g_xdbl), *dtb = symf(g_dt);
    float *yg = symf(g_yg), *zm = symf(g_zm), *zsb = symf(g_zs);
    float *qkv = symf(g_qkv), *qb = symf(g_q), *kb = symf(g_k), *vt = symf(g_vt);
    float *Sb = symf(g_S), *oat = symf(g_oat), *orp = symf(g_orp);
    float *tmo = symf(g_tmo), *zo = symf(g_zo);
    int* idx = (int*)symf(g_idx);

    // 0) out = x_in
    {
        int n4 = (BB*TT*CC*NSP)/4;   // 2097152
        k_copy<<<(n4+255)/256, 256>>>((const float4*)x_in, (float4*)out, n4);
    }
    // 1) router
    k_mean<<<(BB*CC*NSP+255)/256, 256>>>(x_in, xm);
    k_conv3<<<BB*32, 1024>>>(xm, r1_w, r1_b, h1);
    k_score<<<(BB*NSP+255)/256, 256>>>(h1, r2_w, r2_b, sc);
    k_topk<<<BB, 1024>>>(sc, idx, scl);
    // 2) gather + rmsnorm
    k_gather<<<ROWS, CC>>>(x_in, idx, scl, norm1_w, z0);
    // 3) mamba
    gemm(z0, in_proj_w, nullptr, xz, ROWS, 2*DI, CC, CC, CC, 2*DI, 0,0,0, 1, 0);
    k_conv1d<<<ROWS/TT, DI>>>(xz, conv1d_w, conv1d_b, xc);
    gemm(xc, x_proj_w, nullptr, xdbl, ROWS, 40, DI, DI, DI, 40, 0,0,0, 1, 0);
    gemm(xdbl, dt_proj_w, dt_proj_b, dtb, ROWS, DI, DTR, 40, DTR, DI, 0,0,0, 1, 1);
    k_scan<<<ROWS/TT, DI>>>(xc, xdbl, dtb, A_log, Dp, xz, yg);
    gemm(yg, out_proj_w, nullptr, zm, ROWS, CC, DI, DI, DI, CC, 0,0,0, 1, 0);
    // 4) attention
    k_zs<<<(ROWS*CC+255)/256, 256>>>(zm, zsb);
    gemm(zsb, attn_in_w, attn_in_b, qkv, ROWS, 3*CC, CC, CC, CC, 3*CC, 0,0,0, 1, 0);
    k_qkvrp<<<(NBATCH*KK*DH+255)/256, 256>>>(qkv, qb, kb, vt);
    gemm(qb, kb, nullptr, Sb, KK, KK, DH, DH, DH, KK,
         (long)KK*DH, (long)KK*DH, (long)KK*KK, NBATCH, 0);
    k_softmax<<<NBATCH*KK/8, 256>>>(Sb);
    gemm(Sb, vt, nullptr, oat, KK, DH, KK, KK, KK, DH,
         (long)KK*KK, (long)DH*KK, (long)KK*DH, NBATCH, 0);
    k_orp<<<(ROWS*CC+255)/256, 256>>>(oat, orp);
    gemm(orp, attn_out_w, attn_out_b, tmo, ROWS, CC, CC, CC, CC, CC, 0,0,0, 1, 0);
    k_ln<<<ROWS, CC>>>(zsb, tmo, ln_w, ln_b, zo);
    // 5) scatter + residual
    k_scatter<<<(ROWS*CC+255)/256, 256>>>(zo, idx, out);
}

// round 3
// speedup vs baseline: 1.4647x; 1.4647x over previous
#include <cuda_runtime.h>
#include <cuda_bf16.h>
#include <cstdint>

// ---------------- problem constants ----------------
#define BB 8
#define TT 8
#define CC 128
#define NSP 1024          // H*W
#define KK 512            // kept tokens (epoch 20 -> ratio 0.5)
#define DI 256            // d_inner
#define DS 16             // d_state
#define DTR 8             // dt_rank
#define NH 4
#define DH 32
#define ROWS 32768        // B*K*T
#define NBATCH 256        // B*T*NH

// ---------------- device scratch (allocation-free) ----------------
__device__ float g_xm  [BB*CC*NSP];
__device__ float g_h1  [BB*32*NSP];
__device__ float g_sc  [BB*NSP];
__device__ int   g_idx [BB*KK];
__device__ float g_scl [BB*KK];
__device__ float g_z0  [(size_t)ROWS*CC];
__device__ float g_xz  [(size_t)ROWS*2*DI];
__device__ float g_xc  [(size_t)ROWS*DI];
__device__ float g_xdbl[(size_t)ROWS*40];
__device__ float g_dt  [(size_t)ROWS*DI];
__device__ float g_yg  [(size_t)ROWS*DI];
__device__ float g_zm  [(size_t)ROWS*CC];
__device__ float g_zs  [(size_t)ROWS*CC];
__device__ float g_qkv [(size_t)ROWS*3*CC];
__device__ float g_q   [(size_t)NBATCH*KK*DH];
__device__ float g_k   [(size_t)NBATCH*KK*DH];
__device__ float g_vt  [(size_t)NBATCH*DH*KK];
__device__ float g_S   [(size_t)NBATCH*KK*KK];   // 256 MB
__device__ float g_oat [(size_t)NBATCH*KK*DH];
__device__ float g_orp [(size_t)ROWS*CC];
__device__ float g_tmo [(size_t)ROWS*CC];
__device__ float g_zo  [(size_t)ROWS*CC];

// ---------------- helpers ----------------
__device__ __forceinline__ float sigm(float x){ return 1.f/(1.f+__expf(-x)); }
__device__ __forceinline__ float siluf(float x){ return x*sigm(x); }
__device__ __forceinline__ float softplusf(float x){ return (x>20.f)?x:log1pf(__expf(x)); }

__device__ __forceinline__ float blockReduce128(float v, float* red){
    #pragma unroll
    for (int o=16;o>0;o>>=1) v += __shfl_xor_sync(0xffffffffu, v, o);
    int w = threadIdx.x >> 5;
    if ((threadIdx.x & 31)==0) red[w]=v;
    __syncthreads();
    return red[0]+red[1]+red[2]+red[3];
}

// ---------------- high-throughput fp32 TN GEMM ----------------
// C = A * Bw^T (+bias)(+softplus). A: M x Kd (lda), Bw: N x Kd (ldb).
// Block tile 128 x BN, BK=16, 256 threads, thread tile 8 x (BN/16).
// Double-buffered smem with register-staged prefetch.
template<int BN, int ACT>
__global__ __launch_bounds__(256)
void gemm2(const float* __restrict__ A, const float* __restrict__ Bw,
           const float* __restrict__ bias, float* __restrict__ C,
           int M, int N, int Kd, int lda, int ldb, int ldc,
           long aS, long bS, long cS)
{
    constexpr int TN = BN/16;
    constexpr int BF = (BN*4 + 255)/256;  // B float4 slots per thread
    __shared__ float As[2][16][132];
    __shared__ float Bs[2][16][BN+4];

    const float* Ab = A + (long)blockIdx.z*aS;
    const float* Bb = Bw + (long)blockIdx.z*bS;
    float* Cb = C + (long)blockIdx.z*cS;
    int m0 = blockIdx.y*128, n0 = blockIdx.x*BN;
    int tid = threadIdx.x;
    int tx = tid & 15, ty = tid >> 4;

    float acc[8][TN] = {};
    float4 ra[2], rb[BF];
    int nk = (Kd + 15) >> 4;

    // ---- load tile 0 into regs ----
    #pragma unroll
    for (int u=0;u<2;u++){
        int f = tid + u*256; int row = f>>2, k4 = f&3;
        int gm = m0+row, gk = k4*4;
        float4 v = {0.f,0.f,0.f,0.f};
        if (gm < M){
            if (gk+3 < Kd) v = *(const float4*)(Ab + (long)gm*lda + gk);
            else {
                if (gk   < Kd) v.x = Ab[(long)gm*lda+gk];
                if (gk+1 < Kd) v.y = Ab[(long)gm*lda+gk+1];
                if (gk+2 < Kd) v.z = Ab[(long)gm*lda+gk+2];
            }
        }
        ra[u] = v;
    }
    #pragma unroll
    for (int u=0;u<BF;u++){
        int f = tid + u*256;
        float4 v = {0.f,0.f,0.f,0.f};
        if (f < BN*4){
            int row = f>>2, k4 = f&3;
            int gn = n0+row, gk = k4*4;
            if (gn < N){
                if (gk+3 < Kd) v = *(const float4*)(Bb + (long)gn*ldb + gk);
                else {
                    if (gk   < Kd) v.x = Bb[(long)gn*ldb+gk];
                    if (gk+1 < Kd) v.y = Bb[(long)gn*ldb+gk+1];
                    if (gk+2 < Kd) v.z = Bb[(long)gn*ldb+gk+2];
                }
            }
        }
        rb[u] = v;
    }
    // ---- store tile 0 ----
    #pragma unroll
    for (int u=0;u<2;u++){
        int f = tid + u*256; int row = f>>2, k4 = f&3;
        As[0][k4*4+0][row]=ra[u].x; As[0][k4*4+1][row]=ra[u].y;
        As[0][k4*4+2][row]=ra[u].z; As[0][k4*4+3][row]=ra[u].w;
    }
    #pragma unroll
    for (int u=0;u<BF;u++){
        int f = tid + u*256;
        if (f < BN*4){
            int row = f>>2, k4 = f&3;
            Bs[0][k4*4+0][row]=rb[u].x; Bs[0][k4*4+1][row]=rb[u].y;
            Bs[0][k4*4+2][row]=rb[u].z; Bs[0][k4*4+3][row]=rb[u].w;
        }
    }
    __syncthreads();

    int buf = 0;
    for (int kt = 0; kt < nk; kt++){
        // prefetch next tile into registers
        if (kt+1 < nk){
            int k0 = (kt+1)*16;
            #pragma unroll
            for (int u=0;u<2;u++){
                int f = tid + u*256; int row = f>>2, k4 = f&3;
                int gm = m0+row, gk = k0 + k4*4;
                float4 v = {0.f,0.f,0.f,0.f};
                if (gm < M){
                    if (gk+3 < Kd) v = *(const float4*)(Ab + (long)gm*lda + gk);
                    else {
                        if (gk   < Kd) v.x = Ab[(long)gm*lda+gk];
                        if (gk+1 < Kd) v.y = Ab[(long)gm*lda+gk+1];
                        if (gk+2 < Kd) v.z = Ab[(long)gm*lda+gk+2];
                    }
                }
                ra[u] = v;
            }
            #pragma unroll
            for (int u=0;u<BF;u++){
                int f = tid + u*256;
                float4 v = {0.f,0.f,0.f,0.f};
                if (f < BN*4){
                    int row = f>>2, k4 = f&3;
                    int gn = n0+row, gk = k0 + k4*4;
                    if (gn < N){
                        if (gk+3 < Kd) v = *(const float4*)(Bb + (long)gn*ldb + gk);
                        else {
                            if (gk   < Kd) v.x = Bb[(long)gn*ldb+gk];
                            if (gk+1 < Kd) v.y = Bb[(long)gn*ldb+gk+1];
                            if (gk+2 < Kd) v.z = Bb[(long)gn*ldb+gk+2];
                        }
                    }
                }
                rb[u] = v;
            }
        }
        // compute current tile
        #pragma unroll
        for (int kk=0;kk<16;kk++){
            float a[8], b[TN];
            #pragma unroll
            for (int i=0;i<8;i++)  a[i] = As[buf][kk][ty*8+i];
            #pragma unroll
            for (int j=0;j<TN;j++) b[j] = Bs[buf][kk][tx*TN+j];
            #pragma unroll
            for (int i=0;i<8;i++)
                #pragma unroll
                for (int j=0;j<TN;j++)
                    acc[i][j] += a[i]*b[j];
        }
        // commit prefetched tile
        if (kt+1 < nk){
            int nb = buf^1;
            #pragma unroll
            for (int u=0;u<2;u++){
                int f = tid + u*256; int row = f>>2, k4 = f&3;
                As[nb][k4*4+0][row]=ra[u].x; As[nb][k4*4+1][row]=ra[u].y;
                As[nb][k4*4+2][row]=ra[u].z; As[nb][k4*4+3][row]=ra[u].w;
            }
            #pragma unroll
            for (int u=0;u<BF;u++){
                int f = tid + u*256;
                if (f < BN*4){
                    int row = f>>2, k4 = f&3;
                    Bs[nb][k4*4+0][row]=rb[u].x; Bs[nb][k4*4+1][row]=rb[u].y;
                    Bs[nb][k4*4+2][row]=rb[u].z; Bs[nb][k4*4+3][row]=rb[u].w;
                }
            }
            __syncthreads();
            buf = nb;
        }
    }
    // ---- epilogue ----
    #pragma unroll
    for (int i=0;i<8;i++){
        int gm = m0 + ty*8 + i;
        if (gm >= M) continue;
        #pragma unroll
        for (int j=0;j<TN;j++){
            int gn = n0 + tx*TN + j;
            if (gn >= N) continue;
            float v = acc[i][j];
            if (bias) v += bias[gn];
            if (ACT==1) v = softplusf(v);
            Cb[(long)gm*ldc + gn] = v;
        }
    }
}

// ---------------- stage kernels (unchanged from R1) ----------------
__global__ void k_copy(const float4* __restrict__ in, float4* __restrict__ out, int n4){
    int i = blockIdx.x*blockDim.x + threadIdx.x;
    if (i < n4) out[i] = in[i];
}

__global__ void k_mean(const float* __restrict__ x, float* __restrict__ xm){
    int i = blockIdx.x*blockDim.x + threadIdx.x;
    if (i >= BB*CC*NSP) return;
    int b = i >> 17; int rem = i & 131071;
    float s = 0.f;
    #pragma unroll
    for (int t=0;t<TT;t++) s += x[((long)b*TT+t)*131072 + rem];
    xm[i] = s * 0.125f;
}

__global__ void k_conv3(const float* __restrict__ xm, const float* __restrict__ w,
                        const float* __restrict__ bias, float* __restrict__ h1){
    __shared__ float pl[34*34];
    int bo = blockIdx.x; int b = bo >> 5; int oc = bo & 31;
    int tid = threadIdx.x;
    int h = tid >> 5, wq = tid & 31;
    float acc = 0.f;
    for (int ic=0; ic<CC; ic++){
        for (int i=tid; i<34*34; i+=1024){
            int hh = i/34 - 1, ww = i%34 - 1;
            pl[i] = (hh>=0 && hh<32 && ww>=0 && ww<32) ?
                    xm[((long)b*CC+ic)*NSP + hh*32+ww] : 0.f;
        }
        __syncthreads();
        const float* wp = w + ((long)oc*CC+ic)*9;
        #pragma unroll
        for (int kh=0;kh<3;kh++)
            #pragma unroll
            for (int kw=0;kw<3;kw++)
                acc += pl[(h+kh)*34 + (wq+kw)] * wp[kh*3+kw];
        __syncthreads();
    }
    acc += bias[oc];
    h1[(long)bo*NSP + tid] = (acc >= 0.f) ? acc : 0.01f*acc;
}

__global__ void k_score(const float* __restrict__ h1, const float* __restrict__ w2,
                        const float* __restrict__ b2, float* __restrict__ sc){
    int i = blockIdx.x*blockDim.x + threadIdx.x;
    if (i >= BB*NSP) return;
    int b = i >> 10, n = i & 1023;
    float a = 0.f;
    #pragma unroll
    for (int oc=0;oc<32;oc++) a += h1[((long)b*32+oc)*NSP + n] * w2[oc];
    a += b2[0];
    sc[i] = sigm(a);
}

__global__ void k_topk(const float* __restrict__ sc, int* __restrict__ idx,
                       float* __restrict__ scl){
    __shared__ float s[1024];
    __shared__ unsigned char keep[1024];
    int b = blockIdx.x, n = threadIdx.x;
    s[n] = sc[b*NSP + n];
    __syncthreads();
    float v = s[n];
    int cnt = 0;
    for (int m=0;m<1024;m++){ float u = s[m]; cnt += (u>v) || (u==v && m<n); }
    keep[n] = (cnt < KK) ? 1 : 0;
    __syncthreads();
    if (keep[n]){
        int pos = 0;
        for (int m=0;m<n;m++) pos += keep[m];
        idx[b*KK + pos] = n;
        scl[b*KK + pos] = v / (v + 1e-6f);
    }
}

__global__ void k_gather(const float* __restrict__ x, const int* __restrict__ idx,
                         const float* __restrict__ scl, const float* __restrict__ nw,
                         float* __restrict__ z0){
    __shared__ float red[4];
    long tok = blockIdx.x;
    int t = tok & 7; long bk = tok >> 3;
    int b = (int)(bk >> 9); int k = (int)(bk & 511);
    int c = threadIdx.x;
    int n = idx[b*KK + k];
    float sf = scl[b*KK + k];
    float v = x[(((long)b*TT + t)*CC + c)*NSP + n] * sf;
    float ss = blockReduce128(v*v, red);
    float r = rsqrtf(ss * (1.f/128.f) + 1e-5f);
    z0[tok*CC + c] = v * r * nw[c];
}

__global__ void k_conv1d(const float* __restrict__ xz, const float* __restrict__ w,
                         const float* __restrict__ bias, float* __restrict__ xc){
    int s = blockIdx.x; int ch = threadIdx.x;
    float in[TT];
    #pragma unroll
    for (int t=0;t<TT;t++) in[t] = xz[(((long)s*TT + t)*(2*DI)) + ch];
    float w0=w[ch*4+0], w1=w[ch*4+1], w2=w[ch*4+2], w3=w[ch*4+3];
    float bb = bias[ch];
    #pragma unroll
    for (int t=0;t<TT;t++){
        float a = bb + in[t]*w3;
        if (t>=1) a += in[t-1]*w2;
        if (t>=2) a += in[t-2]*w1;
        if (t>=3) a += in[t-3]*w0;
        xc[((long)s*TT + t)*DI + ch] = siluf(a);
    }
}

__global__ void k_scan(const float* __restrict__ xc, const float* __restrict__ xdbl,
                       const float* __restrict__ dtb, const float* __restrict__ Alog,
                       const float* __restrict__ Dp, const float* __restrict__ xz,
                       float* __restrict__ yg){
    int s = blockIdx.x; int ch = threadIdx.x;
    float Arow[DS];
    #pragma unroll
    for (int d=0;d<DS;d++) Arow[d] = -__expf(Alog[ch*DS + d]);
    float Dv = Dp[ch];
    float h[DS];
    #pragma unroll
    for (int d=0;d<DS;d++) h[d] = 0.f;
    #pragma unroll
    for (int t=0;t<TT;t++){
        long row = (long)s*TT + t;
        float dt = dtb[row*DI + ch];
        float u  = xc[row*DI + ch];
        float du = dt*u;
        float y = 0.f;
        #pragma unroll
        for (int d=0;d<DS;d++){
            float Bv = xdbl[row*40 + DTR + d];
            float Cv = xdbl[row*40 + DTR + DS + d];
            h[d] = h[d]*__expf(dt*Arow[d]) + du*Bv;
            y += h[d]*Cv;
        }
        float zg = xz[row*(2*DI) + DI + ch];
        yg[row*DI + ch] = (y + u*Dv) * siluf(zg);
    }
}

__global__ void k_zs(const float* __restrict__ zm, float* __restrict__ zs){
    long i = (long)blockIdx.x*blockDim.x + threadIdx.x;
    if (i >= (long)ROWS*CC) return;
    int c = i & 127; long r = i >> 7;
    int k = (int)(r & 511); long r2 = r >> 9;
    int t = (int)(r2 & 7); int b = (int)(r2 >> 3);
    zs[i] = zm[((((long)b*KK + k)*TT + t) << 7) + c];
}

__global__ void k_qkvrp(const float* __restrict__ qkv, float* __restrict__ q,
                        float* __restrict__ kk_, float* __restrict__ vt){
    long i = (long)blockIdx.x*blockDim.x + threadIdx.x;
    if (i >= (long)NBATCH*KK*DH) return;
    int d = i & 31; long r = i >> 5;
    int qr = (int)(r & 511); long bh = r >> 9;
    int hh = (int)(bh & 3); long bt = bh >> 2;
    long src = ((bt*KK + qr)*(3*CC)) + hh*DH + d;
    q[i]   = qkv[src];
    kk_[i] = qkv[src + CC];
    vt[(bh*DH + d)*KK + qr] = qkv[src + 2*CC];
}

__global__ void k_softmax(float* __restrict__ S){
    int warp = blockIdx.x*8 + (threadIdx.x >> 5);
    int lane = threadIdx.x & 31;
    float* row = S + (long)warp*KK;
    float v[16]; float mx = -1e30f;
    #pragma unroll
    for (int i=0;i<16;i++){ v[i] = row[lane + i*32] * 0.17677669529663687f; mx = fmaxf(mx, v[i]); }
    #pragma unroll
    for (int o=16;o>0;o>>=1) mx = fmaxf(mx, __shfl_xor_sync(0xffffffffu, mx, o));
    float sum = 0.f;
    #pragma unroll
    for (int i=0;i<16;i++){ v[i] = __expf(v[i]-mx); sum += v[i]; }
    #pragma unroll
    for (int o=16;o>0;o>>=1) sum += __shfl_xor_sync(0xffffffffu, sum, o);
    float inv = 1.f/sum;
    #pragma unroll
    for (int i=0;i<16;i++) row[lane + i*32] = v[i]*inv;
}

__global__ void k_orp(const float* __restrict__ oat, float* __restrict__ orp){
    long i = (long)blockIdx.x*blockDim.x + threadIdx.x;
    if (i >= (long)ROWS*CC) return;
    int c = i & 127; long r = i >> 7;
    int qr = (int)(r & 511); long bt = r >> 9;
    int hh = c >> 5, d = c & 31;
    orp[i] = oat[(((bt*NH + hh)*KK + qr) << 5) + d];
}

__global__ void k_ln(const float* __restrict__ zs, const float* __restrict__ tmo,
                     const float* __restrict__ w, const float* __restrict__ b,
                     float* __restrict__ zo){
    __shared__ float r1[4], r2[4];
    long r = blockIdx.x; int c = threadIdx.x;
    float v = zs[r*CC + c] + tmo[r*CC + c];
    float s = blockReduce128(v, r1);
    float mu = s * (1.f/128.f);
    float d = v - mu;
    float q = blockReduce128(d*d, r2);
    float var = q * (1.f/128.f);
    zo[r*CC + c] = d * rsqrtf(var + 1e-5f) * w[c] + b[c];
}

__global__ void k_scatter(const float* __restrict__ zo, const int* __restrict__ idx,
                          float* __restrict__ out){
    long i = (long)blockIdx.x*blockDim.x + threadIdx.x;
    if (i >= (long)ROWS*CC) return;
    int c = i & 127; long r = i >> 7;
    int k = (int)(r & 511); long bt = r >> 9;
    int b = (int)(bt >> 3);
    int n = idx[b*KK + k];
    out[((bt*CC) + c)*NSP + n] += zo[i];
}

// ---------------- host launch ----------------
static float* symf(const void* s){ void* p = nullptr; cudaGetSymbolAddress(&p, s); return (float*)p; }

extern "C" void kernel_launch(void* const* d_in, const int* in_sizes, int n_in,
                              void* d_out, int out_size)
{
    const float* x_in      = (const float*)d_in[0];
    const float* norm1_w   = (const float*)d_in[1];
    const float* in_proj_w = (const float*)d_in[2];
    const float* conv1d_w  = (const float*)d_in[3];
    const float* conv1d_b  = (const float*)d_in[4];
    const float* x_proj_w  = (const float*)d_in[5];
    const float* dt_proj_w = (const float*)d_in[6];
    const float* dt_proj_b = (const float*)d_in[7];
    const float* A_log     = (const float*)d_in[8];
    const float* Dp        = (const float*)d_in[9];
    const float* out_proj_w= (const float*)d_in[10];
    const float* r1_w      = (const float*)d_in[11];
    const float* r1_b      = (const float*)d_in[12];
    const float* r2_w      = (const float*)d_in[13];
    const float* r2_b      = (const float*)d_in[14];
    const float* attn_in_w = (const float*)d_in[15];
    const float* attn_in_b = (const float*)d_in[16];
    const float* attn_out_w= (const float*)d_in[17];
    const float* attn_out_b= (const float*)d_in[18];
    const float* ln_w      = (const float*)d_in[19];
    const float* ln_b      = (const float*)d_in[20];
    float* out = (float*)d_out;

    float *xm = symf(g_xm), *h1 = symf(g_h1), *sc = symf(g_sc);
    float *scl = symf(g_scl), *z0 = symf(g_z0), *xz = symf(g_xz);
    float *xc = symf(g_xc), *xdbl = symf(g_xdbl), *dtb = symf(g_dt);
    float *yg = symf(g_yg), *zm = symf(g_zm), *zsb = symf(g_zs);
    float *qkv = symf(g_qkv), *qb = symf(g_q), *kb = symf(g_k), *vt = symf(g_vt);
    float *Sb = symf(g_S), *oat = symf(g_oat), *orp = symf(g_orp);
    float *tmo = symf(g_tmo), *zo = symf(g_zo);
    int* idx = (int*)symf(g_idx);

    // 0) out = x_in
    {
        int n4 = (BB*TT*CC*NSP)/4;
        k_copy<<<(n4+255)/256, 256>>>((const float4*)x_in, (float4*)out, n4);
    }
    // 1) router
    k_mean<<<(BB*CC*NSP+255)/256, 256>>>(x_in, xm);
    k_conv3<<<BB*32, 1024>>>(xm, r1_w, r1_b, h1);
    k_score<<<(BB*NSP+255)/256, 256>>>(h1, r2_w, r2_b, sc);
    k_topk<<<BB, 1024>>>(sc, idx, scl);
    // 2) gather + rmsnorm
    k_gather<<<ROWS, CC>>>(x_in, idx, scl, norm1_w, z0);
    // 3) mamba
    gemm2<128,0><<<dim3(4,256,1),256>>>(z0, in_proj_w, nullptr, xz,
        ROWS, 2*DI, CC, CC, CC, 2*DI, 0,0,0);
    k_conv1d<<<ROWS/TT, DI>>>(xz, conv1d_w, conv1d_b, xc);
    gemm2<64,0><<<dim3(1,256,1),256>>>(xc, x_proj_w, nullptr, xdbl,
        ROWS, 40, DI, DI, DI, 40, 0,0,0);
    gemm2<64,1><<<dim3(4,256,1),256>>>(xdbl, dt_proj_w, dt_proj_b, dtb,
        ROWS, DI, DTR, 40, DTR, DI, 0,0,0);
    k_scan<<<ROWS/TT, DI>>>(xc, xdbl, dtb, A_log, Dp, xz, yg);
    gemm2<64,0><<<dim3(2,256,1),256>>>(yg, out_proj_w, nullptr, zm,
        ROWS, CC, DI, DI, DI, CC, 0,0,0);
    // 4) attention
    k_zs<<<(ROWS*CC+255)/256, 256>>>(zm, zsb);
    gemm2<128,0><<<dim3(3,256,1),256>>>(zsb, attn_in_w, attn_in_b, qkv,
        ROWS, 3*CC, CC, CC, CC, 3*CC, 0,0,0);
    k_qkvrp<<<(NBATCH*KK*DH+255)/256, 256>>>(qkv, qb, kb, vt);
    gemm2<128,0><<<dim3(4,4,NBATCH),256>>>(qb, kb, nullptr, Sb,
        KK, KK, DH, DH, DH, KK, (long)KK*DH, (long)KK*DH, (long)KK*KK);
    k_softmax<<<NBATCH*KK/8, 256>>>(Sb);
    gemm2<32,0><<<dim3(1,4,NBATCH),256>>>(Sb, vt, nullptr, oat,
        KK, DH, KK, KK, KK, DH, (long)KK*KK, (long)DH*KK, (long)KK*DH);
    k_orp<<<(ROWS*CC+255)/256, 256>>>(oat, orp);
    gemm2<64,0><<<dim3(2,256,1),256>>>(orp, attn_out_w, attn_out_b, tmo,
        ROWS, CC, CC, CC, CC, CC, 0,0,0);
    k_ln<<<ROWS, CC>>>(zsb, tmo, ln_w, ln_b, zo);
    // 5) scatter + residual
    k_scatter<<<(ROWS*CC+255)/256, 256>>>(zo, idx, out);
}

// round 4
// speedup vs baseline: 1.6877x; 1.1523x over previous
#include <cuda_runtime.h>
#include <cuda_bf16.h>
#include <cstdint>

// ---------------- problem constants ----------------
#define BB 8
#define TT 8
#define CC 128
#define NSP 1024          // H*W
#define KK 512            // kept tokens
#define DI 256            // d_inner
#define DS 16             // d_state
#define DTR 8             // dt_rank
#define NH 4
#define DH 32
#define ROWS 32768        // B*K*T
#define NBATCH 256        // B*T*NH

// ---------------- device scratch (allocation-free) ----------------
__device__ float g_xm  [BB*CC*NSP];
__device__ float g_h1  [BB*32*NSP];
__device__ float g_sc  [BB*NSP];
__device__ int   g_idx [BB*KK];
__device__ float g_scl [BB*KK];
__device__ float g_z0  [(size_t)ROWS*CC];
__device__ float g_xz  [(size_t)ROWS*2*DI];
__device__ float g_xc  [(size_t)ROWS*DI];
__device__ float g_xdbl[(size_t)ROWS*40];
__device__ float g_yg  [(size_t)ROWS*DI];
__device__ float g_zs  [(size_t)ROWS*CC];
__device__ float g_qkv [(size_t)ROWS*3*CC];
__device__ float g_orp [(size_t)ROWS*CC];
__device__ float g_tmo [(size_t)ROWS*CC];
__device__ float g_zo  [(size_t)ROWS*CC];

// ---------------- helpers ----------------
__device__ __forceinline__ float sigm(float x){ return 1.f/(1.f+__expf(-x)); }
__device__ __forceinline__ float siluf(float x){ return x*sigm(x); }
__device__ __forceinline__ float softplusf(float x){ return (x>20.f)?x:log1pf(__expf(x)); }

__device__ __forceinline__ float blockReduce128(float v, float* red){
    #pragma unroll
    for (int o=16;o>0;o>>=1) v += __shfl_xor_sync(0xffffffffu, v, o);
    int w = threadIdx.x >> 5;
    if ((threadIdx.x & 31)==0) red[w]=v;
    __syncthreads();
    return red[0]+red[1]+red[2]+red[3];
}

// ---------------- high-throughput fp32 TN GEMM ----------------
// C = A * Bw^T (+bias). Block tile 128 x BN, BK=16, 256 threads.
// PERM=1: output row gm=(b,k,t) remapped to (b,t,k) before store.
template<int BN, int PERM>
__global__ __launch_bounds__(256)
void gemm2(const float* __restrict__ A, const float* __restrict__ Bw,
           const float* __restrict__ bias, float* __restrict__ C,
           int M, int N, int Kd, int lda, int ldb, int ldc,
           long aS, long bS, long cS)
{
    constexpr int TN = BN/16;
    constexpr int BF = (BN*4 + 255)/256;
    __shared__ float As[2][16][132];
    __shared__ float Bs[2][16][BN+4];

    const float* Ab = A + (long)blockIdx.z*aS;
    const float* Bb = Bw + (long)blockIdx.z*bS;
    float* Cb = C + (long)blockIdx.z*cS;
    int m0 = blockIdx.y*128, n0 = blockIdx.x*BN;
    int tid = threadIdx.x;
    int tx = tid & 15, ty = tid >> 4;

    float acc[8][TN] = {};
    float4 ra[2], rb[BF];
    int nk = (Kd + 15) >> 4;

    #pragma unroll
    for (int u=0;u<2;u++){
        int f = tid + u*256; int row = f>>2, k4 = f&3;
        int gm = m0+row, gk = k4*4;
        float4 v = {0.f,0.f,0.f,0.f};
        if (gm < M){
            if (gk+3 < Kd) v = *(const float4*)(Ab + (long)gm*lda + gk);
            else {
                if (gk   < Kd) v.x = Ab[(long)gm*lda+gk];
                if (gk+1 < Kd) v.y = Ab[(long)gm*lda+gk+1];
                if (gk+2 < Kd) v.z = Ab[(long)gm*lda+gk+2];
            }
        }
        ra[u] = v;
    }
    #pragma unroll
    for (int u=0;u<BF;u++){
        int f = tid + u*256;
        float4 v = {0.f,0.f,0.f,0.f};
        if (f < BN*4){
            int row = f>>2, k4 = f&3;
            int gn = n0+row, gk = k4*4;
            if (gn < N){
                if (gk+3 < Kd) v = *(const float4*)(Bb + (long)gn*ldb + gk);
                else {
                    if (gk   < Kd) v.x = Bb[(long)gn*ldb+gk];
                    if (gk+1 < Kd) v.y = Bb[(long)gn*ldb+gk+1];
                    if (gk+2 < Kd) v.z = Bb[(long)gn*ldb+gk+2];
                }
            }
        }
        rb[u] = v;
    }
    #pragma unroll
    for (int u=0;u<2;u++){
        int f = tid + u*256; int row = f>>2, k4 = f&3;
        As[0][k4*4+0][row]=ra[u].x; As[0][k4*4+1][row]=ra[u].y;
        As[0][k4*4+2][row]=ra[u].z; As[0][k4*4+3][row]=ra[u].w;
    }
    #pragma unroll
    for (int u=0;u<BF;u++){
        int f = tid + u*256;
        if (f < BN*4){
            int row = f>>2, k4 = f&3;
            Bs[0][k4*4+0][row]=rb[u].x; Bs[0][k4*4+1][row]=rb[u].y;
            Bs[0][k4*4+2][row]=rb[u].z; Bs[0][k4*4+3][row]=rb[u].w;
        }
    }
    __syncthreads();

    int buf = 0;
    for (int kt = 0; kt < nk; kt++){
        if (kt+1 < nk){
            int k0 = (kt+1)*16;
            #pragma unroll
            for (int u=0;u<2;u++){
                int f = tid + u*256; int row = f>>2, k4 = f&3;
                int gm = m0+row, gk = k0 + k4*4;
                float4 v = {0.f,0.f,0.f,0.f};
                if (gm < M){
                    if (gk+3 < Kd) v = *(const float4*)(Ab + (long)gm*lda + gk);
                    else {
                        if (gk   < Kd) v.x = Ab[(long)gm*lda+gk];
                        if (gk+1 < Kd) v.y = Ab[(long)gm*lda+gk+1];
                        if (gk+2 < Kd) v.z = Ab[(long)gm*lda+gk+2];
                    }
                }
                ra[u] = v;
            }
            #pragma unroll
            for (int u=0;u<BF;u++){
                int f = tid + u*256;
                float4 v = {0.f,0.f,0.f,0.f};
                if (f < BN*4){
                    int row = f>>2, k4 = f&3;
                    int gn = n0+row, gk = k0 + k4*4;
                    if (gn < N){
                        if (gk+3 < Kd) v = *(const float4*)(Bb + (long)gn*ldb + gk);
                        else {
                            if (gk   < Kd) v.x = Bb[(long)gn*ldb+gk];
                            if (gk+1 < Kd) v.y = Bb[(long)gn*ldb+gk+1];
                            if (gk+2 < Kd) v.z = Bb[(long)gn*ldb+gk+2];
                        }
                    }
                }
                rb[u] = v;
            }
        }
        #pragma unroll
        for (int kk=0;kk<16;kk++){
            float a[8], b[TN];
            #pragma unroll
            for (int i=0;i<8;i++)  a[i] = As[buf][kk][ty*8+i];
            #pragma unroll
            for (int j=0;j<TN;j++) b[j] = Bs[buf][kk][tx*TN+j];
            #pragma unroll
            for (int i=0;i<8;i++)
                #pragma unroll
                for (int j=0;j<TN;j++)
                    acc[i][j] += a[i]*b[j];
        }
        if (kt+1 < nk){
            int nb = buf^1;
            #pragma unroll
            for (int u=0;u<2;u++){
                int f = tid + u*256; int row = f>>2, k4 = f&3;
                As[nb][k4*4+0][row]=ra[u].x; As[nb][k4*4+1][row]=ra[u].y;
                As[nb][k4*4+2][row]=ra[u].z; As[nb][k4*4+3][row]=ra[u].w;
            }
            #pragma unroll
            for (int u=0;u<BF;u++){
                int f = tid + u*256;
                if (f < BN*4){
                    int row = f>>2, k4 = f&3;
                    Bs[nb][k4*4+0][row]=rb[u].x; Bs[nb][k4*4+1][row]=rb[u].y;
                    Bs[nb][k4*4+2][row]=rb[u].z; Bs[nb][k4*4+3][row]=rb[u].w;
                }
            }
            __syncthreads();
            buf = nb;
        }
    }
    #pragma unroll
    for (int i=0;i<8;i++){
        int gm = m0 + ty*8 + i;
        if (gm >= M) continue;
        long gr = gm;
        if (PERM==1){
            int b = gm >> 12; int k = (gm >> 3) & 511; int t = gm & 7;
            gr = ((long)(b*8 + t) << 9) + k;
        }
        #pragma unroll
        for (int j=0;j<TN;j++){
            int gn = n0 + tx*TN + j;
            if (gn >= N) continue;
            float v = acc[i][j];
            if (bias) v += bias[gn];
            Cb[gr*ldc + gn] = v;
        }
    }
}

// ---------------- fused flash attention ----------------
// grid: (8 q-tiles, 256 bt*head). 64 queries/CTA, keys streamed in 64-chunks.
// Reads g_qkv directly, writes output in (bt, q, h*32+d) layout (orp).
__global__ __launch_bounds__(256)
void k_flash(const float* __restrict__ qkv, float* __restrict__ o)
{
    __shared__ float Qs[32][72];    // [d][q]
    __shared__ float Ks[32][72];    // [d][k]
    __shared__ float Vt[32][72];    // [d][k]
    __shared__ float Ps[64][72];    // [q][k]

    int bh = blockIdx.y;
    int bt = bh >> 2, h = bh & 3;
    const float* base = qkv + (long)bt*KK*(3*CC) + h*DH;
    int q0 = blockIdx.x * 64;

    int tid = threadIdx.x;
    int tx = tid & 15, ty = tid >> 4;

    // load Q tile (64 q x 32 d), transposed into [d][q]
    for (int i = tid; i < 64*32; i += 256) {
        int d = i & 31, q = i >> 5;
        Qs[d][q] = base[(long)(q0 + q)*(3*CC) + d];
    }

    float m_i[4], l_i[4], acc[4][2];
    #pragma unroll
    for (int i=0;i<4;i++){ m_i[i] = -1e30f; l_i[i] = 0.f; acc[i][0]=0.f; acc[i][1]=0.f; }

    const float scl = 0.17677669529663687f;   // 1/sqrt(32)

    for (int kc = 0; kc < 8; kc++) {
        int k0 = kc * 64;
        __syncthreads();   // previous chunk fully consumed
        for (int i = tid; i < 64*32; i += 256) {
            int d = i & 31, k = i >> 5;
            long r = (long)(k0 + k)*(3*CC);
            Ks[d][k] = base[r + CC + d];
            Vt[d][k] = base[r + 2*CC + d];
        }
        __syncthreads();

        // S tile: queries ty*4+i, keys tx*4+j
        float s[4][4] = {};
        #pragma unroll
        for (int d=0; d<32; d++){
            float4 a4 = *(const float4*)&Qs[d][ty*4];
            float4 b4 = *(const float4*)&Ks[d][tx*4];
            float a[4] = {a4.x,a4.y,a4.z,a4.w};
            float b[4] = {b4.x,b4.y,b4.z,b4.w};
            #pragma unroll
            for (int i=0;i<4;i++)
                #pragma unroll
                for (int j=0;j<4;j++)
                    s[i][j] += a[i]*b[j];
        }
        // online softmax (reduce across 16 tx lanes within half-warp)
        #pragma unroll
        for (int i=0;i<4;i++){
            float mx = -1e30f;
            #pragma unroll
            for (int j=0;j<4;j++){ s[i][j] *= scl; mx = fmaxf(mx, s[i][j]); }
            #pragma unroll
            for (int ofs=8; ofs>=1; ofs>>=1)
                mx = fmaxf(mx, __shfl_xor_sync(0xffffffffu, mx, ofs));
            float mnew = fmaxf(m_i[i], mx);
            float r = __expf(m_i[i] - mnew);
            l_i[i] *= r; acc[i][0] *= r; acc[i][1] *= r;
            float ls = 0.f;
            #pragma unroll
            for (int j=0;j<4;j++){ s[i][j] = __expf(s[i][j] - mnew); ls += s[i][j]; }
            #pragma unroll
            for (int ofs=8; ofs>=1; ofs>>=1)
                ls += __shfl_xor_sync(0xffffffffu, ls, ofs);
            l_i[i] += ls;
            m_i[i] = mnew;
        }
        // write P tile
        #pragma unroll
        for (int i=0;i<4;i++)
            *(float4*)&Ps[ty*4+i][tx*4] = make_float4(s[i][0],s[i][1],s[i][2],s[i][3]);
        __syncthreads();
        // acc += P * V : dims n = tx and tx+16
        #pragma unroll
        for (int k4 = 0; k4 < 64; k4 += 4) {
            float4 b0 = *(const float4*)&Vt[tx][k4];
            float4 b1 = *(const float4*)&Vt[tx+16][k4];
            #pragma unroll
            for (int i=0;i<4;i++){
                float4 a = *(const float4*)&Ps[ty*4+i][k4];
                acc[i][0] += a.x*b0.x + a.y*b0.y + a.z*b0.z + a.w*b0.w;
                acc[i][1] += a.x*b1.x + a.y*b1.y + a.z*b1.z + a.w*b1.w;
            }
        }
    }
    // output
    #pragma unroll
    for (int i=0;i<4;i++){
        int q = q0 + ty*4 + i;
        float inv = 1.f / l_i[i];
        long row = ((long)bt*KK + q)*CC + h*DH;
        o[row + tx]      = acc[i][0]*inv;
        o[row + tx + 16] = acc[i][1]*inv;
    }
}

// ---------------- stage kernels ----------------
__global__ void k_copy(const float4* __restrict__ in, float4* __restrict__ out, int n4){
    int i = blockIdx.x*blockDim.x + threadIdx.x;
    if (i < n4) out[i] = in[i];
}

__global__ void k_mean(const float* __restrict__ x, float* __restrict__ xm){
    int i = blockIdx.x*blockDim.x + threadIdx.x;
    if (i >= BB*CC*NSP) return;
    int b = i >> 17; int rem = i & 131071;
    float s = 0.f;
    #pragma unroll
    for (int t=0;t<TT;t++) s += x[((long)b*TT+t)*131072 + rem];
    xm[i] = s * 0.125f;
}

__global__ void k_conv3(const float* __restrict__ xm, const float* __restrict__ w,
                        const float* __restrict__ bias, float* __restrict__ h1){
    __shared__ float pl[34*34];
    int bo = blockIdx.x; int b = bo >> 5; int oc = bo & 31;
    int tid = threadIdx.x;
    int h = tid >> 5, wq = tid & 31;
    float acc = 0.f;
    for (int ic=0; ic<CC; ic++){
        for (int i=tid; i<34*34; i+=1024){
            int hh = i/34 - 1, ww = i%34 - 1;
            pl[i] = (hh>=0 && hh<32 && ww>=0 && ww<32) ?
                    xm[((long)b*CC+ic)*NSP + hh*32+ww] : 0.f;
        }
        __syncthreads();
        const float* wp = w + ((long)oc*CC+ic)*9;
        #pragma unroll
        for (int kh=0;kh<3;kh++)
            #pragma unroll
            for (int kw=0;kw<3;kw++)
                acc += pl[(h+kh)*34 + (wq+kw)] * wp[kh*3+kw];
        __syncthreads();
    }
    acc += bias[oc];
    h1[(long)bo*NSP + tid] = (acc >= 0.f) ? acc : 0.01f*acc;
}

__global__ void k_score(const float* __restrict__ h1, const float* __restrict__ w2,
                        const float* __restrict__ b2, float* __restrict__ sc){
    int i = blockIdx.x*blockDim.x + threadIdx.x;
    if (i >= BB*NSP) return;
    int b = i >> 10, n = i & 1023;
    float a = 0.f;
    #pragma unroll
    for (int oc=0;oc<32;oc++) a += h1[((long)b*32+oc)*NSP + n] * w2[oc];
    a += b2[0];
    sc[i] = sigm(a);
}

__global__ void k_topk(const float* __restrict__ sc, int* __restrict__ idx,
                       float* __restrict__ scl){
    __shared__ float s[1024];
    __shared__ unsigned char keep[1024];
    int b = blockIdx.x, n = threadIdx.x;
    s[n] = sc[b*NSP + n];
    __syncthreads();
    float v = s[n];
    int cnt = 0;
    for (int m=0;m<1024;m++){ float u = s[m]; cnt += (u>v) || (u==v && m<n); }
    keep[n] = (cnt < KK) ? 1 : 0;
    __syncthreads();
    if (keep[n]){
        int pos = 0;
        for (int m=0;m<n;m++) pos += keep[m];
        idx[b*KK + pos] = n;
        scl[b*KK + pos] = v / (v + 1e-6f);
    }
}

__global__ void k_gather(const float* __restrict__ x, const int* __restrict__ idx,
                         const float* __restrict__ scl, const float* __restrict__ nw,
                         float* __restrict__ z0){
    __shared__ float red[4];
    long tok = blockIdx.x;
    int t = tok & 7; long bk = tok >> 3;
    int b = (int)(bk >> 9); int k = (int)(bk & 511);
    int c = threadIdx.x;
    int n = idx[b*KK + k];
    float sf = scl[b*KK + k];
    float v = x[(((long)b*TT + t)*CC + c)*NSP + n] * sf;
    float ss = blockReduce128(v*v, red);
    float r = rsqrtf(ss * (1.f/128.f) + 1e-5f);
    z0[tok*CC + c] = v * r * nw[c];
}

__global__ void k_conv1d(const float* __restrict__ xz, const float* __restrict__ w,
                         const float* __restrict__ bias, float* __restrict__ xc){
    int s = blockIdx.x; int ch = threadIdx.x;
    float in[TT];
    #pragma unroll
    for (int t=0;t<TT;t++) in[t] = xz[(((long)s*TT + t)*(2*DI)) + ch];
    float w0=w[ch*4+0], w1=w[ch*4+1], w2=w[ch*4+2], w3=w[ch*4+3];
    float bb = bias[ch];
    #pragma unroll
    for (int t=0;t<TT;t++){
        float a = bb + in[t]*w3;
        if (t>=1) a += in[t-1]*w2;
        if (t>=2) a += in[t-2]*w1;
        if (t>=3) a += in[t-3]*w0;
        xc[((long)s*TT + t)*DI + ch] = siluf(a);
    }
}

// fused dt_proj + softplus + selective scan + gate
__global__ void k_scan2(const float* __restrict__ xc, const float* __restrict__ xdbl,
                        const float* __restrict__ dtw, const float* __restrict__ dtbias,
                        const float* __restrict__ Alog, const float* __restrict__ Dp,
                        const float* __restrict__ xz, float* __restrict__ yg){
    __shared__ float xd[TT][40];
    int s = blockIdx.x; int ch = threadIdx.x;
    for (int i = ch; i < TT*40; i += 256)
        xd[i/40][i%40] = xdbl[(long)s*TT*40 + i];
    float w8[DTR];
    #pragma unroll
    for (int r=0;r<DTR;r++) w8[r] = dtw[ch*DTR + r];
    float db = dtbias[ch];
    float Arow[DS];
    #pragma unroll
    for (int d=0;d<DS;d++) Arow[d] = -__expf(Alog[ch*DS + d]);
    float Dv = Dp[ch];
    __syncthreads();
    float h[DS];
    #pragma unroll
    for (int d=0;d<DS;d++) h[d] = 0.f;
    #pragma unroll
    for (int t=0;t<TT;t++){
        long row = (long)s*TT + t;
        float dtr = db;
        #pragma unroll
        for (int r=0;r<DTR;r++) dtr += xd[t][r]*w8[r];
        float dt = softplusf(dtr);
        float u  = xc[row*DI + ch];
        float du = dt*u;
        float y = 0.f;
        #pragma unroll
        for (int d=0;d<DS;d++){
            float Bv = xd[t][DTR + d];
            float Cv = xd[t][DTR + DS + d];
            h[d] = h[d]*__expf(dt*Arow[d]) + du*Bv;
            y += h[d]*Cv;
        }
        float zg = xz[row*(2*DI) + DI + ch];
        yg[row*DI + ch] = (y + u*Dv) * siluf(zg);
    }
}

__global__ void k_ln(const float* __restrict__ zs, const float* __restrict__ tmo,
                     const float* __restrict__ w, const float* __restrict__ b,
                     float* __restrict__ zo){
    __shared__ float r1[4], r2[4];
    long r = blockIdx.x; int c = threadIdx.x;
    float v = zs[r*CC + c] + tmo[r*CC + c];
    float s = blockReduce128(v, r1);
    float mu = s * (1.f/128.f);
    float d = v - mu;
    float q = blockReduce128(d*d, r2);
    float var = q * (1.f/128.f);
    zo[r*CC + c] = d * rsqrtf(var + 1e-5f) * w[c] + b[c];
}

__global__ void k_scatter(const float* __restrict__ zo, const int* __restrict__ idx,
                          float* __restrict__ out){
    long i = (long)blockIdx.x*blockDim.x + threadIdx.x;
    if (i >= (long)ROWS*CC) return;
    int c = i & 127; long r = i >> 7;
    int k = (int)(r & 511); long bt = r >> 9;
    int b = (int)(bt >> 3);
    int n = idx[b*KK + k];
    out[((bt*CC) + c)*NSP + n] += zo[i];
}

// ---------------- host launch ----------------
static float* symf(const void* s){ void* p = nullptr; cudaGetSymbolAddress(&p, s); return (float*)p; }

extern "C" void kernel_launch(void* const* d_in, const int* in_sizes, int n_in,
                              void* d_out, int out_size)
{
    const float* x_in      = (const float*)d_in[0];
    const float* norm1_w   = (const float*)d_in[1];
    const float* in_proj_w = (const float*)d_in[2];
    const float* conv1d_w  = (const float*)d_in[3];
    const float* conv1d_b  = (const float*)d_in[4];
    const float* x_proj_w  = (const float*)d_in[5];
    const float* dt_proj_w = (const float*)d_in[6];
    const float* dt_proj_b = (const float*)d_in[7];
    const float* A_log     = (const float*)d_in[8];
    const float* Dp        = (const float*)d_in[9];
    const float* out_proj_w= (const float*)d_in[10];
    const float* r1_w      = (const float*)d_in[11];
    const float* r1_b      = (const float*)d_in[12];
    const float* r2_w      = (const float*)d_in[13];
    const float* r2_b      = (const float*)d_in[14];
    const float* attn_in_w = (const float*)d_in[15];
    const float* attn_in_b = (const float*)d_in[16];
    const float* attn_out_w= (const float*)d_in[17];
    const float* attn_out_b= (const float*)d_in[18];
    const float* ln_w      = (const float*)d_in[19];
    const float* ln_b      = (const float*)d_in[20];
    float* out = (float*)d_out;

    float *xm = symf(g_xm), *h1 = symf(g_h1), *sc = symf(g_sc);
    float *scl = symf(g_scl), *z0 = symf(g_z0), *xz = symf(g_xz);
    float *xc = symf(g_xc), *xdbl = symf(g_xdbl);
    float *yg = symf(g_yg), *zsb = symf(g_zs);
    float *qkv = symf(g_qkv), *orp = symf(g_orp);
    float *tmo = symf(g_tmo), *zo = symf(g_zo);
    int* idx = (int*)symf(g_idx);

    // 0) out = x_in
    {
        int n4 = (BB*TT*CC*NSP)/4;
        k_copy<<<(n4+255)/256, 256>>>((const float4*)x_in, (float4*)out, n4);
    }
    // 1) router
    k_mean<<<(BB*CC*NSP+255)/256, 256>>>(x_in, xm);
    k_conv3<<<BB*32, 1024>>>(xm, r1_w, r1_b, h1);
    k_score<<<(BB*NSP+255)/256, 256>>>(h1, r2_w, r2_b, sc);
    k_topk<<<BB, 1024>>>(sc, idx, scl);
    // 2) gather + rmsnorm
    k_gather<<<ROWS, CC>>>(x_in, idx, scl, norm1_w, z0);
    // 3) mamba
    gemm2<128,0><<<dim3(4,256,1),256>>>(z0, in_proj_w, nullptr, xz,
        ROWS, 2*DI, CC, CC, CC, 2*DI, 0,0,0);
    k_conv1d<<<ROWS/TT, DI>>>(xz, conv1d_w, conv1d_b, xc);
    gemm2<64,0><<<dim3(1,256,1),256>>>(xc, x_proj_w, nullptr, xdbl,
        ROWS, 40, DI, DI, DI, 40, 0,0,0);
    k_scan2<<<ROWS/TT, DI>>>(xc, xdbl, dt_proj_w, dt_proj_b, A_log, Dp, xz, yg);
    // out_proj with fused (b,k,t)->(b,t,k) permute, writes zs directly
    gemm2<64,1><<<dim3(2,256,1),256>>>(yg, out_proj_w, nullptr, zsb,
        ROWS, CC, DI, DI, DI, CC, 0,0,0);
    // 4) attention
    gemm2<128,0><<<dim3(3,256,1),256>>>(zsb, attn_in_w, attn_in_b, qkv,
        ROWS, 3*CC, CC, CC, CC, 3*CC, 0,0,0);
    k_flash<<<dim3(8, NBATCH), 256>>>(qkv, orp);
    gemm2<64,0><<<dim3(2,256,1),256>>>(orp, attn_out_w, attn_out_b, tmo,
        ROWS, CC, CC, CC, CC, CC, 0,0,0);
    k_ln<<<ROWS, CC>>>(zsb, tmo, ln_w, ln_b, zo);
    // 5) scatter + residual
    k_scatter<<<(ROWS*CC+255)/256, 256>>>(zo, idx, out);
}

// round 5
// speedup vs baseline: 2.0606x; 1.2210x over previous
#include <cuda_runtime.h>
#include <cuda_bf16.h>
#include <cstdint>

// ---------------- problem constants ----------------
#define BB 8
#define TT 8
#define CC 128
#define NSP 1024          // H*W
#define KK 512            // kept tokens
#define DI 256            // d_inner
#define DS 16             // d_state
#define DTR 8             // dt_rank
#define NH 4
#define DH 32
#define ROWS 32768        // B*K*T
#define NBATCH 256        // B*T*NH

// ---------------- device scratch (allocation-free) ----------------
__device__ float g_xm  [BB*CC*NSP];
__device__ float g_h1  [BB*32*NSP];
__device__ float g_sc  [BB*NSP];
__device__ int   g_idx [BB*KK];
__device__ float g_scl [BB*KK];
__device__ float g_z0  [(size_t)ROWS*CC];
__device__ float g_xz  [(size_t)ROWS*2*DI];
__device__ float g_xc  [(size_t)ROWS*DI];
__device__ float g_xdbl[(size_t)ROWS*40];
__device__ float g_yg  [(size_t)ROWS*DI];
__device__ float g_zs  [(size_t)ROWS*CC];
__device__ float g_qkv [(size_t)ROWS*3*CC];
__device__ float g_orp [(size_t)ROWS*CC];
__device__ float g_tmo [(size_t)ROWS*CC];
__device__ float g_zo  [(size_t)ROWS*CC];

// ---------------- helpers ----------------
__device__ __forceinline__ float sigm(float x){ return 1.f/(1.f+__expf(-x)); }
__device__ __forceinline__ float siluf(float x){ return x*sigm(x); }
__device__ __forceinline__ float softplusf(float x){ return (x>20.f)?x:log1pf(__expf(x)); }
__device__ __forceinline__ uint32_t f2tf(float x){
    uint32_t r; asm("cvt.rna.tf32.f32 %0, %1;" : "=r"(r) : "f"(x)); return r;
}

__device__ __forceinline__ float blockReduce128(float v, float* red){
    #pragma unroll
    for (int o=16;o>0;o>>=1) v += __shfl_xor_sync(0xffffffffu, v, o);
    int w = threadIdx.x >> 5;
    if ((threadIdx.x & 31)==0) red[w]=v;
    __syncthreads();
    return red[0]+red[1]+red[2]+red[3];
}

__device__ __forceinline__ void mma_tf32(float* c, const uint32_t* a, const uint32_t* b){
    asm volatile(
        "mma.sync.aligned.m16n8k8.row.col.f32.tf32.tf32.f32 "
        "{%0,%1,%2,%3}, {%4,%5,%6,%7}, {%8,%9}, {%0,%1,%2,%3};"
        : "+f"(c[0]), "+f"(c[1]), "+f"(c[2]), "+f"(c[3])
        : "r"(a[0]), "r"(a[1]), "r"(a[2]), "r"(a[3]), "r"(b[0]), "r"(b[1]));
}

// ---------------- tf32 tensor-core TN GEMM ----------------
// C = A * Bw^T (+bias). A: M x Kd (row-major), Bw: N x Kd (row-major).
// BM=128, BN=64, BK=32, 256 threads (8 warps: 4 m x 2 n), warp tile 32x32.
// Requires: M % 128 == 0, Kd % 32 == 0. N guarded.
// PERM=1: output row gm=(b,k,t) remapped to (b,t,k).
template<int PERM>
__global__ __launch_bounds__(256)
void gemm_tc(const float* __restrict__ A, const float* __restrict__ Bw,
             const float* __restrict__ bias, float* __restrict__ C,
             int M, int N, int Kd, int lda, int ldb, int ldc)
{
    __shared__ uint32_t As[2][128][36];
    __shared__ uint32_t Bs[2][64][36];

    int m0 = blockIdx.y*128, n0 = blockIdx.x*64;
    int tid = threadIdx.x;
    int wid = tid >> 5, lane = tid & 31;
    int warp_m = wid >> 1, warp_n = wid & 1;
    int g = lane >> 2, t = lane & 3;

    float acc[2][4][4] = {};
    float4 ra[4], rb[2];
    int nk = Kd >> 5;

    // ---- stage tile 0 ----
    #pragma unroll
    for (int u=0;u<4;u++){
        int f = tid + u*256; int k4 = f&7, m = f>>3;
        ra[u] = *(const float4*)(A + (long)(m0+m)*lda + k4*4);
    }
    #pragma unroll
    for (int u=0;u<2;u++){
        int f = tid + u*256; int k4 = f&7, n = f>>3;
        int gn = n0 + n;
        float4 v = {0.f,0.f,0.f,0.f};
        if (gn < N) v = *(const float4*)(Bw + (long)gn*ldb + k4*4);
        rb[u] = v;
    }
    #pragma unroll
    for (int u=0;u<4;u++){
        int f = tid + u*256; int k4 = f&7, m = f>>3;
        *(uint4*)&As[0][m][k4*4] = make_uint4(f2tf(ra[u].x),f2tf(ra[u].y),f2tf(ra[u].z),f2tf(ra[u].w));
    }
    #pragma unroll
    for (int u=0;u<2;u++){
        int f = tid + u*256; int k4 = f&7, n = f>>3;
        *(uint4*)&Bs[0][n][k4*4] = make_uint4(f2tf(rb[u].x),f2tf(rb[u].y),f2tf(rb[u].z),f2tf(rb[u].w));
    }
    __syncthreads();

    int buf = 0;
    for (int kt = 0; kt < nk; kt++){
        if (kt+1 < nk){
            int k0 = (kt+1)*32;
            #pragma unroll
            for (int u=0;u<4;u++){
                int f = tid + u*256; int k4 = f&7, m = f>>3;
                ra[u] = *(const float4*)(A + (long)(m0+m)*lda + k0 + k4*4);
            }
            #pragma unroll
            for (int u=0;u<2;u++){
                int f = tid + u*256; int k4 = f&7, n = f>>3;
                int gn = n0 + n;
                float4 v = {0.f,0.f,0.f,0.f};
                if (gn < N) v = *(const float4*)(Bw + (long)gn*ldb + k0 + k4*4);
                rb[u] = v;
            }
        }
        // compute on buf
        #pragma unroll
        for (int ks=0; ks<4; ks++){
            int kc = ks*8;
            uint32_t af[2][4], bfr[4][2];
            #pragma unroll
            for (int mf=0; mf<2; mf++){
                int r = warp_m*32 + mf*16 + g;
                af[mf][0] = As[buf][r][kc+t];
                af[mf][1] = As[buf][r+8][kc+t];
                af[mf][2] = As[buf][r][kc+t+4];
                af[mf][3] = As[buf][r+8][kc+t+4];
            }
            #pragma unroll
            for (int nf=0; nf<4; nf++){
                int cn = warp_n*32 + nf*8 + g;
                bfr[nf][0] = Bs[buf][cn][kc+t];
                bfr[nf][1] = Bs[buf][cn][kc+t+4];
            }
            #pragma unroll
            for (int mf=0; mf<2; mf++)
                #pragma unroll
                for (int nf=0; nf<4; nf++)
                    mma_tf32(acc[mf][nf], af[mf], bfr[nf]);
        }
        if (kt+1 < nk){
            int nb = buf^1;
            #pragma unroll
            for (int u=0;u<4;u++){
                int f = tid + u*256; int k4 = f&7, m = f>>3;
                *(uint4*)&As[nb][m][k4*4] = make_uint4(f2tf(ra[u].x),f2tf(ra[u].y),f2tf(ra[u].z),f2tf(ra[u].w));
            }
            #pragma unroll
            for (int u=0;u<2;u++){
                int f = tid + u*256; int k4 = f&7, n = f>>3;
                *(uint4*)&Bs[nb][n][k4*4] = make_uint4(f2tf(rb[u].x),f2tf(rb[u].y),f2tf(rb[u].z),f2tf(rb[u].w));
            }
            __syncthreads();
            buf = nb;
        }
    }
    // ---- epilogue ----
    #pragma unroll
    for (int mf=0; mf<2; mf++){
        int r0 = m0 + warp_m*32 + mf*16 + g;
        int r1 = r0 + 8;
        long gr0 = r0, gr1 = r1;
        if (PERM==1){
            int b = r0 >> 12; int k = (r0 >> 3) & 511; int tt = r0 & 7;
            gr0 = ((long)(b*8 + tt) << 9) + k;
            b = r1 >> 12; k = (r1 >> 3) & 511; tt = r1 & 7;
            gr1 = ((long)(b*8 + tt) << 9) + k;
        }
        #pragma unroll
        for (int nf=0; nf<4; nf++){
            int cn = n0 + warp_n*32 + nf*8 + 2*t;
            if (cn >= N) continue;
            float b0 = bias ? bias[cn]   : 0.f;
            float b1 = bias ? bias[cn+1] : 0.f;
            C[gr0*ldc + cn]   = acc[mf][nf][0] + b0;
            C[gr0*ldc + cn+1] = acc[mf][nf][1] + b1;
            C[gr1*ldc + cn]   = acc[mf][nf][2] + b0;
            C[gr1*ldc + cn+1] = acc[mf][nf][3] + b1;
        }
    }
}

// ---------------- fused flash attention ----------------
__global__ __launch_bounds__(256)
void k_flash(const float* __restrict__ qkv, float* __restrict__ o)
{
    __shared__ float Qs[32][72];
    __shared__ float Ks[32][72];
    __shared__ float Vt[32][72];
    __shared__ float Ps[64][72];

    int bh = blockIdx.y;
    int bt = bh >> 2, h = bh & 3;
    const float* base = qkv + (long)bt*KK*(3*CC) + h*DH;
    int q0 = blockIdx.x * 64;

    int tid = threadIdx.x;
    int tx = tid & 15, ty = tid >> 4;

    for (int i = tid; i < 64*32; i += 256) {
        int d = i & 31, q = i >> 5;
        Qs[d][q] = base[(long)(q0 + q)*(3*CC) + d];
    }

    float m_i[4], l_i[4], acc[4][2];
    #pragma unroll
    for (int i=0;i<4;i++){ m_i[i] = -1e30f; l_i[i] = 0.f; acc[i][0]=0.f; acc[i][1]=0.f; }

    const float scl = 0.17677669529663687f;

    for (int kc = 0; kc < 8; kc++) {
        int k0 = kc * 64;
        __syncthreads();
        for (int i = tid; i < 64*32; i += 256) {
            int d = i & 31, k = i >> 5;
            long r = (long)(k0 + k)*(3*CC);
            Ks[d][k] = base[r + CC + d];
            Vt[d][k] = base[r + 2*CC + d];
        }
        __syncthreads();

        float s[4][4] = {};
        #pragma unroll
        for (int d=0; d<32; d++){
            float4 a4 = *(const float4*)&Qs[d][ty*4];
            float4 b4 = *(const float4*)&Ks[d][tx*4];
            float a[4] = {a4.x,a4.y,a4.z,a4.w};
            float b[4] = {b4.x,b4.y,b4.z,b4.w};
            #pragma unroll
            for (int i=0;i<4;i++)
                #pragma unroll
                for (int j=0;j<4;j++)
                    s[i][j] += a[i]*b[j];
        }
        #pragma unroll
        for (int i=0;i<4;i++){
            float mx = -1e30f;
            #pragma unroll
            for (int j=0;j<4;j++){ s[i][j] *= scl; mx = fmaxf(mx, s[i][j]); }
            #pragma unroll
            for (int ofs=8; ofs>=1; ofs>>=1)
                mx = fmaxf(mx, __shfl_xor_sync(0xffffffffu, mx, ofs));
            float mnew = fmaxf(m_i[i], mx);
            float r = __expf(m_i[i] - mnew);
            l_i[i] *= r; acc[i][0] *= r; acc[i][1] *= r;
            float ls = 0.f;
            #pragma unroll
            for (int j=0;j<4;j++){ s[i][j] = __expf(s[i][j] - mnew); ls += s[i][j]; }
            #pragma unroll
            for (int ofs=8; ofs>=1; ofs>>=1)
                ls += __shfl_xor_sync(0xffffffffu, ls, ofs);
            l_i[i] += ls;
            m_i[i] = mnew;
        }
        #pragma unroll
        for (int i=0;i<4;i++)
            *(float4*)&Ps[ty*4+i][tx*4] = make_float4(s[i][0],s[i][1],s[i][2],s[i][3]);
        __syncthreads();
        #pragma unroll
        for (int k4 = 0; k4 < 64; k4 += 4) {
            float4 b0 = *(const float4*)&Vt[tx][k4];
            float4 b1 = *(const float4*)&Vt[tx+16][k4];
            #pragma unroll
            for (int i=0;i<4;i++){
                float4 a = *(const float4*)&Ps[ty*4+i][k4];
                acc[i][0] += a.x*b0.x + a.y*b0.y + a.z*b0.z + a.w*b0.w;
                acc[i][1] += a.x*b1.x + a.y*b1.y + a.z*b1.z + a.w*b1.w;
            }
        }
    }
    #pragma unroll
    for (int i=0;i<4;i++){
        int q = q0 + ty*4 + i;
        float inv = 1.f / l_i[i];
        long row = ((long)bt*KK + q)*CC + h*DH;
        o[row + tx]      = acc[i][0]*inv;
        o[row + tx + 16] = acc[i][1]*inv;
    }
}

// ---------------- stage kernels ----------------
__global__ void k_copy(const float4* __restrict__ in, float4* __restrict__ out, int n4){
    int i = blockIdx.x*blockDim.x + threadIdx.x;
    if (i < n4) out[i] = in[i];
}

__global__ void k_mean(const float* __restrict__ x, float* __restrict__ xm){
    int i = blockIdx.x*blockDim.x + threadIdx.x;
    if (i >= BB*CC*NSP) return;
    int b = i >> 17; int rem = i & 131071;
    float s = 0.f;
    #pragma unroll
    for (int t=0;t<TT;t++) s += x[((long)b*TT+t)*131072 + rem];
    xm[i] = s * 0.125f;
}

__global__ void k_conv3(const float* __restrict__ xm, const float* __restrict__ w,
                        const float* __restrict__ bias, float* __restrict__ h1){
    __shared__ float pl[34*34];
    int bo = blockIdx.x; int b = bo >> 5; int oc = bo & 31;
    int tid = threadIdx.x;
    int h = tid >> 5, wq = tid & 31;
    float acc = 0.f;
    for (int ic=0; ic<CC; ic++){
        for (int i=tid; i<34*34; i+=1024){
            int hh = i/34 - 1, ww = i%34 - 1;
            pl[i] = (hh>=0 && hh<32 && ww>=0 && ww<32) ?
                    xm[((long)b*CC+ic)*NSP + hh*32+ww] : 0.f;
        }
        __syncthreads();
        const float* wp = w + ((long)oc*CC+ic)*9;
        #pragma unroll
        for (int kh=0;kh<3;kh++)
            #pragma unroll
            for (int kw=0;kw<3;kw++)
                acc += pl[(h+kh)*34 + (wq+kw)] * wp[kh*3+kw];
        __syncthreads();
    }
    acc += bias[oc];
    h1[(long)bo*NSP + tid] = (acc >= 0.f) ? acc : 0.01f*acc;
}

__global__ void k_score(const float* __restrict__ h1, const float* __restrict__ w2,
                        const float* __restrict__ b2, float* __restrict__ sc){
    int i = blockIdx.x*blockDim.x + threadIdx.x;
    if (i >= BB*NSP) return;
    int b = i >> 10, n = i & 1023;
    float a = 0.f;
    #pragma unroll
    for (int oc=0;oc<32;oc++) a += h1[((long)b*32+oc)*NSP + n] * w2[oc];
    a += b2[0];
    sc[i] = sigm(a);
}

__global__ void k_topk(const float* __restrict__ sc, int* __restrict__ idx,
                       float* __restrict__ scl){
    __shared__ float s[1024];
    __shared__ unsigned char keep[1024];
    int b = blockIdx.x, n = threadIdx.x;
    s[n] = sc[b*NSP + n];
    __syncthreads();
    float v = s[n];
    int cnt = 0;
    for (int m=0;m<1024;m++){ float u = s[m]; cnt += (u>v) || (u==v && m<n); }
    keep[n] = (cnt < KK) ? 1 : 0;
    __syncthreads();
    if (keep[n]){
        int pos = 0;
        for (int m=0;m<n;m++) pos += keep[m];
        idx[b*KK + pos] = n;
        scl[b*KK + pos] = v / (v + 1e-6f);
    }
}

__global__ void k_gather(const float* __restrict__ x, const int* __restrict__ idx,
                         const float* __restrict__ scl, const float* __restrict__ nw,
                         float* __restrict__ z0){
    __shared__ float red[4];
    long tok = blockIdx.x;
    int t = tok & 7; long bk = tok >> 3;
    int b = (int)(bk >> 9); int k = (int)(bk & 511);
    int c = threadIdx.x;
    int n = idx[b*KK + k];
    float sf = scl[b*KK + k];
    float v = x[(((long)b*TT + t)*CC + c)*NSP + n] * sf;
    float ss = blockReduce128(v*v, red);
    float r = rsqrtf(ss * (1.f/128.f) + 1e-5f);
    z0[tok*CC + c] = v * r * nw[c];
}

__global__ void k_conv1d(const float* __restrict__ xz, const float* __restrict__ w,
                         const float* __restrict__ bias, float* __restrict__ xc){
    int s = blockIdx.x; int ch = threadIdx.x;
    float in[TT];
    #pragma unroll
    for (int t=0;t<TT;t++) in[t] = xz[(((long)s*TT + t)*(2*DI)) + ch];
    float w0=w[ch*4+0], w1=w[ch*4+1], w2=w[ch*4+2], w3=w[ch*4+3];
    float bb = bias[ch];
    #pragma unroll
    for (int t=0;t<TT;t++){
        float a = bb + in[t]*w3;
        if (t>=1) a += in[t-1]*w2;
        if (t>=2) a += in[t-2]*w1;
        if (t>=3) a += in[t-3]*w0;
        xc[((long)s*TT + t)*DI + ch] = siluf(a);
    }
}

__global__ void k_scan2(const float* __restrict__ xc, const float* __restrict__ xdbl,
                        const float* __restrict__ dtw, const float* __restrict__ dtbias,
                        const float* __restrict__ Alog, const float* __restrict__ Dp,
                        const float* __restrict__ xz, float* __restrict__ yg){
    __shared__ float xd[TT][40];
    int s = blockIdx.x; int ch = threadIdx.x;
    for (int i = ch; i < TT*40; i += 256)
        xd[i/40][i%40] = xdbl[(long)s*TT*40 + i];
    float w8[DTR];
    #pragma unroll
    for (int r=0;r<DTR;r++) w8[r] = dtw[ch*DTR + r];
    float db = dtbias[ch];
    float Arow[DS];
    #pragma unroll
    for (int d=0;d<DS;d++) Arow[d] = -__expf(Alog[ch*DS + d]);
    float Dv = Dp[ch];
    __syncthreads();
    float h[DS];
    #pragma unroll
    for (int d=0;d<DS;d++) h[d] = 0.f;
    #pragma unroll
    for (int t=0;t<TT;t++){
        long row = (long)s*TT + t;
        float dtr = db;
        #pragma unroll
        for (int r=0;r<DTR;r++) dtr += xd[t][r]*w8[r];
        float dt = softplusf(dtr);
        float u  = xc[row*DI + ch];
        float du = dt*u;
        float y = 0.f;
        #pragma unroll
        for (int d=0;d<DS;d++){
            float Bv = xd[t][DTR + d];
            float Cv = xd[t][DTR + DS + d];
            h[d] = h[d]*__expf(dt*Arow[d]) + du*Bv;
            y += h[d]*Cv;
        }
        float zg = xz[row*(2*DI) + DI + ch];
        yg[row*DI + ch] = (y + u*Dv) * siluf(zg);
    }
}

__global__ void k_ln(const float* __restrict__ zs, const float* __restrict__ tmo,
                     const float* __restrict__ w, const float* __restrict__ b,
                     float* __restrict__ zo){
    __shared__ float r1[4], r2[4];
    long r = blockIdx.x; int c = threadIdx.x;
    float v = zs[r*CC + c] + tmo[r*CC + c];
    float s = blockReduce128(v, r1);
    float mu = s * (1.f/128.f);
    float d = v - mu;
    float q = blockReduce128(d*d, r2);
    float var = q * (1.f/128.f);
    zo[r*CC + c] = d * rsqrtf(var + 1e-5f) * w[c] + b[c];
}

__global__ void k_scatter(const float* __restrict__ zo, const int* __restrict__ idx,
                          float* __restrict__ out){
    long i = (long)blockIdx.x*blockDim.x + threadIdx.x;
    if (i >= (long)ROWS*CC) return;
    int c = i & 127; long r = i >> 7;
    int k = (int)(r & 511); long bt = r >> 9;
    int b = (int)(bt >> 3);
    int n = idx[b*KK + k];
    out[((bt*CC) + c)*NSP + n] += zo[i];
}

// ---------------- host launch ----------------
static float* symf(const void* s){ void* p = nullptr; cudaGetSymbolAddress(&p, s); return (float*)p; }

extern "C" void kernel_launch(void* const* d_in, const int* in_sizes, int n_in,
                              void* d_out, int out_size)
{
    const float* x_in      = (const float*)d_in[0];
    const float* norm1_w   = (const float*)d_in[1];
    const float* in_proj_w = (const float*)d_in[2];
    const float* conv1d_w  = (const float*)d_in[3];
    const float* conv1d_b  = (const float*)d_in[4];
    const float* x_proj_w  = (const float*)d_in[5];
    const float* dt_proj_w = (const float*)d_in[6];
    const float* dt_proj_b = (const float*)d_in[7];
    const float* A_log     = (const float*)d_in[8];
    const float* Dp        = (const float*)d_in[9];
    const float* out_proj_w= (const float*)d_in[10];
    const float* r1_w      = (const float*)d_in[11];
    const float* r1_b      = (const float*)d_in[12];
    const float* r2_w      = (const float*)d_in[13];
    const float* r2_b      = (const float*)d_in[14];
    const float* attn_in_w = (const float*)d_in[15];
    const float* attn_in_b = (const float*)d_in[16];
    const float* attn_out_w= (const float*)d_in[17];
    const float* attn_out_b= (const float*)d_in[18];
    const float* ln_w      = (const float*)d_in[19];
    const float* ln_b      = (const float*)d_in[20];
    float* out = (float*)d_out;

    float *xm = symf(g_xm), *h1 = symf(g_h1), *sc = symf(g_sc);
    float *scl = symf(g_scl), *z0 = symf(g_z0), *xz = symf(g_xz);
    float *xc = symf(g_xc), *xdbl = symf(g_xdbl);
    float *yg = symf(g_yg), *zsb = symf(g_zs);
    float *qkv = symf(g_qkv), *orp = symf(g_orp);
    float *tmo = symf(g_tmo), *zo = symf(g_zo);
    int* idx = (int*)symf(g_idx);

    // 0) out = x_in
    {
        int n4 = (BB*TT*CC*NSP)/4;
        k_copy<<<(n4+255)/256, 256>>>((const float4*)x_in, (float4*)out, n4);
    }
    // 1) router
    k_mean<<<(BB*CC*NSP+255)/256, 256>>>(x_in, xm);
    k_conv3<<<BB*32, 1024>>>(xm, r1_w, r1_b, h1);
    k_score<<<(BB*NSP+255)/256, 256>>>(h1, r2_w, r2_b, sc);
    k_topk<<<BB, 1024>>>(sc, idx, scl);
    // 2) gather + rmsnorm
    k_gather<<<ROWS, CC>>>(x_in, idx, scl, norm1_w, z0);
    // 3) mamba
    gemm_tc<0><<<dim3(8,256),256>>>(z0, in_proj_w, nullptr, xz,
        ROWS, 2*DI, CC, CC, CC, 2*DI);
    k_conv1d<<<ROWS/TT, DI>>>(xz, conv1d_w, conv1d_b, xc);
    gemm_tc<0><<<dim3(1,256),256>>>(xc, x_proj_w, nullptr, xdbl,
        ROWS, 40, DI, DI, DI, 40);
    k_scan2<<<ROWS/TT, DI>>>(xc, xdbl, dt_proj_w, dt_proj_b, A_log, Dp, xz, yg);
    gemm_tc<1><<<dim3(2,256),256>>>(yg, out_proj_w, nullptr, zsb,
        ROWS, CC, DI, DI, DI, CC);
    // 4) attention
    gemm_tc<0><<<dim3(6,256),256>>>(zsb, attn_in_w, attn_in_b, qkv,
        ROWS, 3*CC, CC, CC, CC, 3*CC);
    k_flash<<<dim3(8, NBATCH), 256>>>(qkv, orp);
    gemm_tc<0><<<dim3(2,256),256>>>(orp, attn_out_w, attn_out_b, tmo,
        ROWS, CC, CC, CC, CC, CC);
    k_ln<<<ROWS, CC>>>(zsb, tmo, ln_w, ln_b, zo);
    // 5) scatter + residual
    k_scatter<<<(ROWS*CC+255)/256, 256>>>(zo, idx, out);
}

// round 6
// speedup vs baseline: 2.3796x; 1.1548x over previous
#include <cuda_runtime.h>
#include <cuda_bf16.h>
#include <cstdint>

// ---------------- problem constants ----------------
#define BB 8
#define TT 8
#define CC 128
#define NSP 1024
#define KK 512
#define DI 256
#define DS 16
#define DTR 8
#define NH 4
#define DH 32
#define ROWS 32768
#define NBATCH 256

// ---------------- device scratch ----------------
__device__ float g_xm  [BB*CC*NSP];
__device__ float g_h1  [BB*32*NSP];
__device__ float g_sc  [BB*NSP];
__device__ int   g_idx [BB*KK];
__device__ float g_scl [BB*KK];
__device__ float g_z0  [(size_t)ROWS*CC];
__device__ float g_xz  [(size_t)ROWS*2*DI];
__device__ float g_xc  [(size_t)ROWS*DI];
__device__ float g_xdbl[(size_t)ROWS*40];
__device__ float g_yg  [(size_t)ROWS*DI];
__device__ float g_zs  [(size_t)ROWS*CC];
__device__ float g_qkv [(size_t)ROWS*3*CC];
__device__ float g_orp [(size_t)ROWS*CC];
__device__ float g_tmo [(size_t)ROWS*CC];

// ---------------- helpers ----------------
__device__ __forceinline__ float sigm(float x){ return 1.f/(1.f+__expf(-x)); }
__device__ __forceinline__ float siluf(float x){ return x*sigm(x); }
__device__ __forceinline__ float softplusf(float x){ return (x>20.f)?x:log1pf(__expf(x)); }
__device__ __forceinline__ uint32_t f2tf(float x){
    uint32_t r; asm("cvt.rna.tf32.f32 %0, %1;" : "=r"(r) : "f"(x)); return r;
}

__device__ __forceinline__ float blockReduce128(float v, float* red){
    #pragma unroll
    for (int o=16;o>0;o>>=1) v += __shfl_xor_sync(0xffffffffu, v, o);
    int w = threadIdx.x >> 5;
    if ((threadIdx.x & 31)==0) red[w]=v;
    __syncthreads();
    return red[0]+red[1]+red[2]+red[3];
}

__device__ __forceinline__ void mma_tf32(float* c, const uint32_t* a, const uint32_t* b){
    asm volatile(
        "mma.sync.aligned.m16n8k8.row.col.f32.tf32.tf32.f32 "
        "{%0,%1,%2,%3}, {%4,%5,%6,%7}, {%8,%9}, {%0,%1,%2,%3};"
        : "+f"(c[0]), "+f"(c[1]), "+f"(c[2]), "+f"(c[3])
        : "r"(a[0]), "r"(a[1]), "r"(a[2]), "r"(a[3]), "r"(b[0]), "r"(b[1]));
}

// ---------------- tf32 tensor-core TN GEMM (unchanged from R4) ----------------
template<int PERM>
__global__ __launch_bounds__(256)
void gemm_tc(const float* __restrict__ A, const float* __restrict__ Bw,
             const float* __restrict__ bias, float* __restrict__ C,
             int M, int N, int Kd, int lda, int ldb, int ldc)
{
    __shared__ uint32_t As[2][128][36];
    __shared__ uint32_t Bs[2][64][36];

    int m0 = blockIdx.y*128, n0 = blockIdx.x*64;
    int tid = threadIdx.x;
    int wid = tid >> 5, lane = tid & 31;
    int warp_m = wid >> 1, warp_n = wid & 1;
    int g = lane >> 2, t = lane & 3;

    float acc[2][4][4] = {};
    float4 ra[4], rb[2];
    int nk = Kd >> 5;

    #pragma unroll
    for (int u=0;u<4;u++){
        int f = tid + u*256; int k4 = f&7, m = f>>3;
        ra[u] = *(const float4*)(A + (long)(m0+m)*lda + k4*4);
    }
    #pragma unroll
    for (int u=0;u<2;u++){
        int f = tid + u*256; int k4 = f&7, n = f>>3;
        int gn = n0 + n;
        float4 v = {0.f,0.f,0.f,0.f};
        if (gn < N) v = *(const float4*)(Bw + (long)gn*ldb + k4*4);
        rb[u] = v;
    }
    #pragma unroll
    for (int u=0;u<4;u++){
        int f = tid + u*256; int k4 = f&7, m = f>>3;
        *(uint4*)&As[0][m][k4*4] = make_uint4(f2tf(ra[u].x),f2tf(ra[u].y),f2tf(ra[u].z),f2tf(ra[u].w));
    }
    #pragma unroll
    for (int u=0;u<2;u++){
        int f = tid + u*256; int k4 = f&7, n = f>>3;
        *(uint4*)&Bs[0][n][k4*4] = make_uint4(f2tf(rb[u].x),f2tf(rb[u].y),f2tf(rb[u].z),f2tf(rb[u].w));
    }
    __syncthreads();

    int buf = 0;
    for (int kt = 0; kt < nk; kt++){
        if (kt+1 < nk){
            int k0 = (kt+1)*32;
            #pragma unroll
            for (int u=0;u<4;u++){
                int f = tid + u*256; int k4 = f&7, m = f>>3;
                ra[u] = *(const float4*)(A + (long)(m0+m)*lda + k0 + k4*4);
            }
            #pragma unroll
            for (int u=0;u<2;u++){
                int f = tid + u*256; int k4 = f&7, n = f>>3;
                int gn = n0 + n;
                float4 v = {0.f,0.f,0.f,0.f};
                if (gn < N) v = *(const float4*)(Bw + (long)gn*ldb + k0 + k4*4);
                rb[u] = v;
            }
        }
        #pragma unroll
        for (int ks=0; ks<4; ks++){
            int kc = ks*8;
            uint32_t af[2][4], bfr[4][2];
            #pragma unroll
            for (int mf=0; mf<2; mf++){
                int r = warp_m*32 + mf*16 + g;
                af[mf][0] = As[buf][r][kc+t];
                af[mf][1] = As[buf][r+8][kc+t];
                af[mf][2] = As[buf][r][kc+t+4];
                af[mf][3] = As[buf][r+8][kc+t+4];
            }
            #pragma unroll
            for (int nf=0; nf<4; nf++){
                int cn = warp_n*32 + nf*8 + g;
                bfr[nf][0] = Bs[buf][cn][kc+t];
                bfr[nf][1] = Bs[buf][cn][kc+t+4];
            }
            #pragma unroll
            for (int mf=0; mf<2; mf++)
                #pragma unroll
                for (int nf=0; nf<4; nf++)
                    mma_tf32(acc[mf][nf], af[mf], bfr[nf]);
        }
        if (kt+1 < nk){
            int nb = buf^1;
            #pragma unroll
            for (int u=0;u<4;u++){
                int f = tid + u*256; int k4 = f&7, m = f>>3;
                *(uint4*)&As[nb][m][k4*4] = make_uint4(f2tf(ra[u].x),f2tf(ra[u].y),f2tf(ra[u].z),f2tf(ra[u].w));
            }
            #pragma unroll
            for (int u=0;u<2;u++){
                int f = tid + u*256; int k4 = f&7, n = f>>3;
                *(uint4*)&Bs[nb][n][k4*4] = make_uint4(f2tf(rb[u].x),f2tf(rb[u].y),f2tf(rb[u].z),f2tf(rb[u].w));
            }
            __syncthreads();
            buf = nb;
        }
    }
    #pragma unroll
    for (int mf=0; mf<2; mf++){
        int r0 = m0 + warp_m*32 + mf*16 + g;
        int r1 = r0 + 8;
        long gr0 = r0, gr1 = r1;
        if (PERM==1){
            int b = r0 >> 12; int k = (r0 >> 3) & 511; int tt = r0 & 7;
            gr0 = ((long)(b*8 + tt) << 9) + k;
            b = r1 >> 12; k = (r1 >> 3) & 511; tt = r1 & 7;
            gr1 = ((long)(b*8 + tt) << 9) + k;
        }
        #pragma unroll
        for (int nf=0; nf<4; nf++){
            int cn = n0 + warp_n*32 + nf*8 + 2*t;
            if (cn >= N) continue;
            float b0 = bias ? bias[cn]   : 0.f;
            float b1 = bias ? bias[cn+1] : 0.f;
            C[gr0*ldc + cn]   = acc[mf][nf][0] + b0;
            C[gr0*ldc + cn+1] = acc[mf][nf][1] + b1;
            C[gr1*ldc + cn]   = acc[mf][nf][2] + b0;
            C[gr1*ldc + cn+1] = acc[mf][nf][3] + b1;
        }
    }
}

// ---------------- tensor-core flash attention ----------------
// grid (8 q-tiles, 256 bt*head), 256 thr. 64 q x 32 d, keys in 8 chunks of 64.
__global__ __launch_bounds__(256)
void k_flash_tc(const float* __restrict__ qkv, float* __restrict__ o)
{
    __shared__ uint32_t Qs[64][36];   // tf32 bits, scaled
    __shared__ uint32_t Ks[64][36];   // [key][d]
    __shared__ uint32_t Vt[32][65];   // [d][key]
    __shared__ uint32_t Ps[64][68];   // S (f32 bits) then P (tf32 bits)
    __shared__ float m_s[64], l_s[64], r_s[64];

    int bh = blockIdx.y;
    int bt = bh >> 2, h = bh & 3;
    const float* base = qkv + (long)bt*KK*(3*CC) + h*DH;
    int q0 = blockIdx.x * 64;

    int tid = threadIdx.x;
    int wid = tid >> 5, lane = tid & 31;
    int g = lane >> 2, t = lane & 3;
    const float scl = 0.17677669529663687f;  // 1/sqrt(32)

    // load Q (scaled, tf32)
    for (int i = tid; i < 64*32; i += 256){
        int d = i & 31, q = i >> 5;
        Qs[q][d] = f2tf(base[(long)(q0+q)*(3*CC) + d] * scl);
    }
    if (tid < 64){ m_s[tid] = -1e30f; l_s[tid] = 0.f; }

    // QK warp roles: wm in {0,1} (m 32), wn in {0..3} (n 16)
    int wm = wid & 1, wn = wid >> 1;
    // PV warp roles: pm in {0..3} (m 16), pn in {0,1} (n 16)
    int pm = wid & 3, pn = wid >> 2;

    float oacc[2][4] = {};
    int qrow = tid >> 2, tr = tid & 3;   // softmax mapping

    for (int kc = 0; kc < 8; kc++){
        int k0 = kc * 64;
        __syncthreads();   // Vt/Ks reusable, Q visible (first iter)
        for (int i = tid; i < 64*32; i += 256){
            int d = i & 31, k = i >> 5;
            long r = (long)(k0 + k)*(3*CC);
            Ks[k][d] = f2tf(base[r + CC + d]);
            Vt[d][k] = f2tf(base[r + 2*CC + d]);
        }
        __syncthreads();

        // ---- S = Q K^T (per-warp 32x16 tile) ----
        float sacc[2][2][4] = {};
        #pragma unroll
        for (int ks=0; ks<4; ks++){
            int kc8 = ks*8;
            uint32_t af[2][4], bf[2][2];
            #pragma unroll
            for (int mf=0; mf<2; mf++){
                int r = wm*32 + mf*16 + g;
                af[mf][0] = Qs[r][kc8+t];
                af[mf][1] = Qs[r+8][kc8+t];
                af[mf][2] = Qs[r][kc8+t+4];
                af[mf][3] = Qs[r+8][kc8+t+4];
            }
            #pragma unroll
            for (int nf=0; nf<2; nf++){
                int cn = wn*16 + nf*8 + g;
                bf[nf][0] = Ks[cn][kc8+t];
                bf[nf][1] = Ks[cn][kc8+t+4];
            }
            #pragma unroll
            for (int mf=0; mf<2; mf++)
                #pragma unroll
                for (int nf=0; nf<2; nf++)
                    mma_tf32(sacc[mf][nf], af[mf], bf[nf]);
        }
        // write S tile (f32 bits)
        #pragma unroll
        for (int mf=0; mf<2; mf++){
            int r0 = wm*32 + mf*16 + g;
            #pragma unroll
            for (int nf=0; nf<2; nf++){
                int cn = wn*16 + nf*8 + 2*t;
                Ps[r0][cn]   = __float_as_uint(sacc[mf][nf][0]);
                Ps[r0][cn+1] = __float_as_uint(sacc[mf][nf][1]);
                Ps[r0+8][cn]   = __float_as_uint(sacc[mf][nf][2]);
                Ps[r0+8][cn+1] = __float_as_uint(sacc[mf][nf][3]);
            }
        }
        __syncthreads();

        // ---- online softmax: 4 threads per row, 16 cols each ----
        {
            float v[16]; float mx = -1e30f;
            #pragma unroll
            for (int j=0;j<16;j++){
                v[j] = __uint_as_float(Ps[qrow][tr*16 + j]);
                mx = fmaxf(mx, v[j]);
            }
            mx = fmaxf(mx, __shfl_xor_sync(0xffffffffu, mx, 1));
            mx = fmaxf(mx, __shfl_xor_sync(0xffffffffu, mx, 2));
            float mold = m_s[qrow];
            float mnew = fmaxf(mold, mx);
            float sum = 0.f;
            #pragma unroll
            for (int j=0;j<16;j++){
                v[j] = __expf(v[j] - mnew);
                sum += v[j];
            }
            sum += __shfl_xor_sync(0xffffffffu, sum, 1);
            sum += __shfl_xor_sync(0xffffffffu, sum, 2);
            #pragma unroll
            for (int j=0;j<16;j++)
                Ps[qrow][tr*16 + j] = f2tf(v[j]);
            if (tr == 0){
                float r = __expf(mold - mnew);
                l_s[qrow] = l_s[qrow]*r + sum;
                m_s[qrow] = mnew;
                r_s[qrow] = r;
            }
        }
        __syncthreads();

        // ---- O = O*r + P V (per-warp 16x16 tile) ----
        {
            float rr0 = r_s[pm*16 + g];
            float rr1 = r_s[pm*16 + g + 8];
            #pragma unroll
            for (int nf=0; nf<2; nf++){
                oacc[nf][0] *= rr0; oacc[nf][1] *= rr0;
                oacc[nf][2] *= rr1; oacc[nf][3] *= rr1;
            }
            #pragma unroll
            for (int ks=0; ks<8; ks++){
                int kc8 = ks*8;
                uint32_t af[4], bf[2][2];
                int r = pm*16 + g;
                af[0] = Ps[r][kc8+t];
                af[1] = Ps[r+8][kc8+t];
                af[2] = Ps[r][kc8+t+4];
                af[3] = Ps[r+8][kc8+t+4];
                #pragma unroll
                for (int nf=0; nf<2; nf++){
                    int cn = pn*16 + nf*8 + g;
                    bf[nf][0] = Vt[cn][kc8+t];
                    bf[nf][1] = Vt[cn][kc8+t+4];
                }
                #pragma unroll
                for (int nf=0; nf<2; nf++)
                    mma_tf32(oacc[nf], af, bf[nf]);
            }
        }
    }
    __syncthreads();
    // ---- output ----
    {
        float inv0 = 1.f / l_s[pm*16 + g];
        float inv1 = 1.f / l_s[pm*16 + g + 8];
        int qA = q0 + pm*16 + g;
        int qB = qA + 8;
        #pragma unroll
        for (int nf=0; nf<2; nf++){
            int d = pn*16 + nf*8 + 2*t;
            long rowA = ((long)bt*KK + qA)*CC + h*DH + d;
            long rowB = ((long)bt*KK + qB)*CC + h*DH + d;
            o[rowA]   = oacc[nf][0]*inv0;
            o[rowA+1] = oacc[nf][1]*inv0;
            o[rowB]   = oacc[nf][2]*inv1;
            o[rowB+1] = oacc[nf][3]*inv1;
        }
    }
}

// ---------------- stage kernels ----------------
__global__ void k_copy(const float4* __restrict__ in, float4* __restrict__ out, int n4){
    int i = blockIdx.x*blockDim.x + threadIdx.x;
    if (i < n4) out[i] = in[i];
}

__global__ void k_mean(const float* __restrict__ x, float* __restrict__ xm){
    int i = blockIdx.x*blockDim.x + threadIdx.x;
    if (i >= BB*CC*NSP) return;
    int b = i >> 17; int rem = i & 131071;
    float s = 0.f;
    #pragma unroll
    for (int t=0;t<TT;t++) s += x[((long)b*TT+t)*131072 + rem];
    xm[i] = s * 0.125f;
}

__global__ void k_conv3(const float* __restrict__ xm, const float* __restrict__ w,
                        const float* __restrict__ bias, float* __restrict__ h1){
    __shared__ float pl[34*34];
    int bo = blockIdx.x; int b = bo >> 5; int oc = bo & 31;
    int tid = threadIdx.x;
    int h = tid >> 5, wq = tid & 31;
    float acc = 0.f;
    for (int ic=0; ic<CC; ic++){
        for (int i=tid; i<34*34; i+=1024){
            int hh = i/34 - 1, ww = i%34 - 1;
            pl[i] = (hh>=0 && hh<32 && ww>=0 && ww<32) ?
                    xm[((long)b*CC+ic)*NSP + hh*32+ww] : 0.f;
        }
        __syncthreads();
        const float* wp = w + ((long)oc*CC+ic)*9;
        #pragma unroll
        for (int kh=0;kh<3;kh++)
            #pragma unroll
            for (int kw=0;kw<3;kw++)
                acc += pl[(h+kh)*34 + (wq+kw)] * wp[kh*3+kw];
        __syncthreads();
    }
    acc += bias[oc];
    h1[(long)bo*NSP + tid] = (acc >= 0.f) ? acc : 0.01f*acc;
}

__global__ void k_score(const float* __restrict__ h1, const float* __restrict__ w2,
                        const float* __restrict__ b2, float* __restrict__ sc){
    int i = blockIdx.x*blockDim.x + threadIdx.x;
    if (i >= BB*NSP) return;
    int b = i >> 10, n = i & 1023;
    float a = 0.f;
    #pragma unroll
    for (int oc=0;oc<32;oc++) a += h1[((long)b*32+oc)*NSP + n] * w2[oc];
    a += b2[0];
    sc[i] = sigm(a);
}

__global__ void k_topk(const float* __restrict__ sc, int* __restrict__ idx,
                       float* __restrict__ scl){
    __shared__ float s[1024];
    __shared__ unsigned char keep[1024];
    int b = blockIdx.x, n = threadIdx.x;
    s[n] = sc[b*NSP + n];
    __syncthreads();
    float v = s[n];
    int cnt = 0;
    for (int m=0;m<1024;m++){ float u = s[m]; cnt += (u>v) || (u==v && m<n); }
    keep[n] = (cnt < KK) ? 1 : 0;
    __syncthreads();
    if (keep[n]){
        int pos = 0;
        for (int m=0;m<n;m++) pos += keep[m];
        idx[b*KK + pos] = n;
        scl[b*KK + pos] = v / (v + 1e-6f);
    }
}

__global__ void k_gather(const float* __restrict__ x, const int* __restrict__ idx,
                         const float* __restrict__ scl, const float* __restrict__ nw,
                         float* __restrict__ z0){
    __shared__ float red[4];
    long tok = blockIdx.x;
    int t = tok & 7; long bk = tok >> 3;
    int b = (int)(bk >> 9); int k = (int)(bk & 511);
    int c = threadIdx.x;
    int n = idx[b*KK + k];
    float sf = scl[b*KK + k];
    float v = x[(((long)b*TT + t)*CC + c)*NSP + n] * sf;
    float ss = blockReduce128(v*v, red);
    float r = rsqrtf(ss * (1.f/128.f) + 1e-5f);
    z0[tok*CC + c] = v * r * nw[c];
}

__global__ void k_conv1d(const float* __restrict__ xz, const float* __restrict__ w,
                         const float* __restrict__ bias, float* __restrict__ xc){
    int s = blockIdx.x; int ch = threadIdx.x;
    float in[TT];
    #pragma unroll
    for (int t=0;t<TT;t++) in[t] = xz[(((long)s*TT + t)*(2*DI)) + ch];
    float w0=w[ch*4+0], w1=w[ch*4+1], w2=w[ch*4+2], w3=w[ch*4+3];
    float bb = bias[ch];
    #pragma unroll
    for (int t=0;t<TT;t++){
        float a = bb + in[t]*w3;
        if (t>=1) a += in[t-1]*w2;
        if (t>=2) a += in[t-2]*w1;
        if (t>=3) a += in[t-3]*w0;
        xc[((long)s*TT + t)*DI + ch] = siluf(a);
    }
}

__global__ void k_scan2(const float* __restrict__ xc, const float* __restrict__ xdbl,
                        const float* __restrict__ dtw, const float* __restrict__ dtbias,
                        const float* __restrict__ Alog, const float* __restrict__ Dp,
                        const float* __restrict__ xz, float* __restrict__ yg){
    __shared__ float xd[TT][40];
    int s = blockIdx.x; int ch = threadIdx.x;
    for (int i = ch; i < TT*40; i += 256)
        xd[i/40][i%40] = xdbl[(long)s*TT*40 + i];
    float w8[DTR];
    #pragma unroll
    for (int r=0;r<DTR;r++) w8[r] = dtw[ch*DTR + r];
    float db = dtbias[ch];
    float Arow[DS];
    #pragma unroll
    for (int d=0;d<DS;d++) Arow[d] = -__expf(Alog[ch*DS + d]);
    float Dv = Dp[ch];
    __syncthreads();
    float h[DS];
    #pragma unroll
    for (int d=0;d<DS;d++) h[d] = 0.f;
    #pragma unroll
    for (int t=0;t<TT;t++){
        long row = (long)s*TT + t;
        float dtr = db;
        #pragma unroll
        for (int r=0;r<DTR;r++) dtr += xd[t][r]*w8[r];
        float dt = softplusf(dtr);
        float u  = xc[row*DI + ch];
        float du = dt*u;
        float y = 0.f;
        #pragma unroll
        for (int d=0;d<DS;d++){
            float Bv = xd[t][DTR + d];
            float Cv = xd[t][DTR + DS + d];
            h[d] = h[d]*__expf(dt*Arow[d]) + du*Bv;
            y += h[d]*Cv;
        }
        float zg = xz[row*(2*DI) + DI + ch];
        yg[row*DI + ch] = (y + u*Dv) * siluf(zg);
    }
}

// fused layernorm + scatter-add into output
__global__ void k_lnsc(const float* __restrict__ zs, const float* __restrict__ tmo,
                       const float* __restrict__ w, const float* __restrict__ b,
                       const int* __restrict__ idx, float* __restrict__ out){
    __shared__ float r1[4], r2[4];
    long r = blockIdx.x;                 // (bt, k)
    int k = (int)(r & 511); long bt = r >> 9;
    int bb2 = (int)(bt >> 3);
    int c = threadIdx.x;
    int n = idx[bb2*KK + k];
    float v = zs[r*CC + c] + tmo[r*CC + c];
    float s = blockReduce128(v, r1);
    float mu = s * (1.f/128.f);
    float d = v - mu;
    float q = blockReduce128(d*d, r2);
    float var = q * (1.f/128.f);
    float val = d * rsqrtf(var + 1e-5f) * w[c] + b[c];
    out[((bt*CC) + c)*NSP + n] += val;
}

// ---------------- host launch ----------------
static float* symf(const void* s){ void* p = nullptr; cudaGetSymbolAddress(&p, s); return (float*)p; }

extern "C" void kernel_launch(void* const* d_in, const int* in_sizes, int n_in,
                              void* d_out, int out_size)
{
    const float* x_in      = (const float*)d_in[0];
    const float* norm1_w   = (const float*)d_in[1];
    const float* in_proj_w = (const float*)d_in[2];
    const float* conv1d_w  = (const float*)d_in[3];
    const float* conv1d_b  = (const float*)d_in[4];
    const float* x_proj_w  = (const float*)d_in[5];
    const float* dt_proj_w = (const float*)d_in[6];
    const float* dt_proj_b = (const float*)d_in[7];
    const float* A_log     = (const float*)d_in[8];
    const float* Dp        = (const float*)d_in[9];
    const float* out_proj_w= (const float*)d_in[10];
    const float* r1_w      = (const float*)d_in[11];
    const float* r1_b      = (const float*)d_in[12];
    const float* r2_w      = (const float*)d_in[13];
    const float* r2_b      = (const float*)d_in[14];
    const float* attn_in_w = (const float*)d_in[15];
    const float* attn_in_b = (const float*)d_in[16];
    const float* attn_out_w= (const float*)d_in[17];
    const float* attn_out_b= (const float*)d_in[18];
    const float* ln_w      = (const float*)d_in[19];
    const float* ln_b      = (const float*)d_in[20];
    float* out = (float*)d_out;

    float *xm = symf(g_xm), *h1 = symf(g_h1), *sc = symf(g_sc);
    float *scl = symf(g_scl), *z0 = symf(g_z0), *xz = symf(g_xz);
    float *xc = symf(g_xc), *xdbl = symf(g_xdbl);
    float *yg = symf(g_yg), *zsb = symf(g_zs);
    float *qkv = symf(g_qkv), *orp = symf(g_orp);
    float *tmo = symf(g_tmo);
    int* idx = (int*)symf(g_idx);

    // 0) out = x_in
    {
        int n4 = (BB*TT*CC*NSP)/4;
        k_copy<<<(n4+255)/256, 256>>>((const float4*)x_in, (float4*)out, n4);
    }
    // 1) router
    k_mean<<<(BB*CC*NSP+255)/256, 256>>>(x_in, xm);
    k_conv3<<<BB*32, 1024>>>(xm, r1_w, r1_b, h1);
    k_score<<<(BB*NSP+255)/256, 256>>>(h1, r2_w, r2_b, sc);
    k_topk<<<BB, 1024>>>(sc, idx, scl);
    // 2) gather + rmsnorm
    k_gather<<<ROWS, CC>>>(x_in, idx, scl, norm1_w, z0);
    // 3) mamba
    gemm_tc<0><<<dim3(8,256),256>>>(z0, in_proj_w, nullptr, xz,
        ROWS, 2*DI, CC, CC, CC, 2*DI);
    k_conv1d<<<ROWS/TT, DI>>>(xz, conv1d_w, conv1d_b, xc);
    gemm_tc<0><<<dim3(1,256),256>>>(xc, x_proj_w, nullptr, xdbl,
        ROWS, 40, DI, DI, DI, 40);
    k_scan2<<<ROWS/TT, DI>>>(xc, xdbl, dt_proj_w, dt_proj_b, A_log, Dp, xz, yg);
    gemm_tc<1><<<dim3(2,256),256>>>(yg, out_proj_w, nullptr, zsb,
        ROWS, CC, DI, DI, DI, CC);
    // 4) attention
    gemm_tc<0><<<dim3(6,256),256>>>(zsb, attn_in_w, attn_in_b, qkv,
        ROWS, 3*CC, CC, CC, CC, 3*CC);
    k_flash_tc<<<dim3(8, NBATCH), 256>>>(qkv, orp);
    gemm_tc<0><<<dim3(2,256),256>>>(orp, attn_out_w, attn_out_b, tmo,
        ROWS, CC, CC, CC, CC, CC);
    // 5) layernorm + scatter + residual (fused)
    k_lnsc<<<ROWS, CC>>>(zsb, tmo, ln_w, ln_b, idx, out);
}

// round 8
// speedup vs baseline: 2.5175x; 1.0580x over previous
#include <cuda_runtime.h>
#include <cuda_bf16.h>
#include <cstdint>

// ---------------- problem constants ----------------
#define BB 8
#define TT 8
#define CC 128
#define NSP 1024
#define KK 512
#define DI 256
#define DS 16
#define DTR 8
#define NH 4
#define DH 32
#define ROWS 32768
#define NBATCH 256

// ---------------- device scratch ----------------
__device__ float g_xm  [BB*CC*NSP];
__device__ float g_h1  [BB*32*NSP];
__device__ float g_sc  [BB*NSP];
__device__ int   g_idx [BB*KK];
__device__ float g_scl [BB*KK];
__device__ float g_z0  [(size_t)ROWS*CC];
__device__ float g_xz  [(size_t)ROWS*2*DI];
__device__ float g_xc  [(size_t)ROWS*DI];
__device__ float g_xdbl[(size_t)ROWS*40];
__device__ float g_yg  [(size_t)ROWS*DI];
__device__ float g_zs  [(size_t)ROWS*CC];
__device__ float g_qkv [(size_t)ROWS*3*CC];
__device__ float g_orp [(size_t)ROWS*CC];
__device__ float g_tmo [(size_t)ROWS*CC];

// ---------------- helpers ----------------
__device__ __forceinline__ float sigm(float x){ return 1.f/(1.f+__expf(-x)); }
__device__ __forceinline__ float siluf(float x){ return x*sigm(x); }
__device__ __forceinline__ float softplusf(float x){ return (x>20.f)?x:log1pf(__expf(x)); }

__device__ __forceinline__ uint32_t pk(float lo, float hi){
    __nv_bfloat162 v = __floats2bfloat162_rn(lo, hi);   // x=lo (low half), y=hi
    return *reinterpret_cast<uint32_t*>(&v);
}

__device__ __forceinline__ float blockReduce128(float v, float* red){
    #pragma unroll
    for (int o=16;o>0;o>>=1) v += __shfl_xor_sync(0xffffffffu, v, o);
    int w = threadIdx.x >> 5;
    if ((threadIdx.x & 31)==0) red[w]=v;
    __syncthreads();
    return red[0]+red[1]+red[2]+red[3];
}

__device__ __forceinline__ void mma_bf16(float* c, const uint32_t* a, const uint32_t* b){
    asm volatile(
        "mma.sync.aligned.m16n8k16.row.col.f32.bf16.bf16.f32 "
        "{%0,%1,%2,%3}, {%4,%5,%6,%7}, {%8,%9}, {%0,%1,%2,%3};"
        : "+f"(c[0]), "+f"(c[1]), "+f"(c[2]), "+f"(c[3])
        : "r"(a[0]), "r"(a[1]), "r"(a[2]), "r"(a[3]), "r"(b[0]), "r"(b[1]));
}

// ---------------- bf16 tensor-core TN GEMM ----------------
// C = A * Bw^T (+bias). A: M x Kd fp32 row-major, Bw: N x Kd fp32 row-major.
// BM=128, BN=64, BK=32 (fp32 elems -> 16 packed bf16x2 words), 256 threads,
// 8 warps (4 m x 2 n), warp tile 32x32. Requires M%128==0, Kd%32==0.
// PERM=1: output row gm=(b,k,t) remapped to (b,t,k).
template<int PERM>
__global__ __launch_bounds__(256)
void gemm_bf(const float* __restrict__ A, const float* __restrict__ Bw,
             const float* __restrict__ bias, float* __restrict__ C,
             int M, int N, int Kd, int lda, int ldb, int ldc)
{
    __shared__ uint32_t As[2][128][20];   // 16 bf16x2 + pad
    __shared__ uint32_t Bs[2][64][20];

    int m0 = blockIdx.y*128, n0 = blockIdx.x*64;
    int tid = threadIdx.x;
    int wid = tid >> 5, lane = tid & 31;
    int warp_m = wid >> 1, warp_n = wid & 1;
    int g = lane >> 2, t = lane & 3;

    float acc[2][4][4] = {};
    float4 ra[4], rb[2];
    int nk = Kd >> 5;

    #pragma unroll
    for (int u=0;u<4;u++){
        int f = tid + u*256; int k4 = f&7, m = f>>3;
        ra[u] = *(const float4*)(A + (long)(m0+m)*lda + k4*4);
    }
    #pragma unroll
    for (int u=0;u<2;u++){
        int f = tid + u*256; int k4 = f&7, n = f>>3;
        int gn = n0 + n;
        float4 v = {0.f,0.f,0.f,0.f};
        if (gn < N) v = *(const float4*)(Bw + (long)gn*ldb + k4*4);
        rb[u] = v;
    }
    #pragma unroll
    for (int u=0;u<4;u++){
        int f = tid + u*256; int k4 = f&7, m = f>>3;
        As[0][m][k4*2]   = pk(ra[u].x, ra[u].y);
        As[0][m][k4*2+1] = pk(ra[u].z, ra[u].w);
    }
    #pragma unroll
    for (int u=0;u<2;u++){
        int f = tid + u*256; int k4 = f&7, n = f>>3;
        Bs[0][n][k4*2]   = pk(rb[u].x, rb[u].y);
        Bs[0][n][k4*2+1] = pk(rb[u].z, rb[u].w);
    }
    __syncthreads();

    int buf = 0;
    for (int kt = 0; kt < nk; kt++){
        if (kt+1 < nk){
            int k0 = (kt+1)*32;
            #pragma unroll
            for (int u=0;u<4;u++){
                int f = tid + u*256; int k4 = f&7, m = f>>3;
                ra[u] = *(const float4*)(A + (long)(m0+m)*lda + k0 + k4*4);
            }
            #pragma unroll
            for (int u=0;u<2;u++){
                int f = tid + u*256; int k4 = f&7, n = f>>3;
                int gn = n0 + n;
                float4 v = {0.f,0.f,0.f,0.f};
                if (gn < N) v = *(const float4*)(Bw + (long)gn*ldb + k0 + k4*4);
                rb[u] = v;
            }
        }
        #pragma unroll
        for (int ks=0; ks<2; ks++){
            int kc2 = ks*8;
            uint32_t af[2][4], bfr[4][2];
            #pragma unroll
            for (int mf=0; mf<2; mf++){
                int r = warp_m*32 + mf*16 + g;
                af[mf][0] = As[buf][r][kc2+t];
                af[mf][1] = As[buf][r+8][kc2+t];
                af[mf][2] = As[buf][r][kc2+t+4];
                af[mf][3] = As[buf][r+8][kc2+t+4];
            }
            #pragma unroll
            for (int nf=0; nf<4; nf++){
                int cn = warp_n*32 + nf*8 + g;
                bfr[nf][0] = Bs[buf][cn][kc2+t];
                bfr[nf][1] = Bs[buf][cn][kc2+t+4];
            }
            #pragma unroll
            for (int mf=0; mf<2; mf++)
                #pragma unroll
                for (int nf=0; nf<4; nf++)
                    mma_bf16(acc[mf][nf], af[mf], bfr[nf]);
        }
        if (kt+1 < nk){
            int nb = buf^1;
            #pragma unroll
            for (int u=0;u<4;u++){
                int f = tid + u*256; int k4 = f&7, m = f>>3;
                As[nb][m][k4*2]   = pk(ra[u].x, ra[u].y);
                As[nb][m][k4*2+1] = pk(ra[u].z, ra[u].w);
            }
            #pragma unroll
            for (int u=0;u<2;u++){
                int f = tid + u*256; int k4 = f&7, n = f>>3;
                Bs[nb][n][k4*2]   = pk(rb[u].x, rb[u].y);
                Bs[nb][n][k4*2+1] = pk(rb[u].z, rb[u].w);
            }
            __syncthreads();
            buf = nb;
        }
    }
    #pragma unroll
    for (int mf=0; mf<2; mf++){
        int r0 = m0 + warp_m*32 + mf*16 + g;
        int r1 = r0 + 8;
        long gr0 = r0, gr1 = r1;
        if (PERM==1){
            int b = r0 >> 12; int k = (r0 >> 3) & 511; int tt = r0 & 7;
            gr0 = ((long)(b*8 + tt) << 9) + k;
            b = r1 >> 12; k = (r1 >> 3) & 511; tt = r1 & 7;
            gr1 = ((long)(b*8 + tt) << 9) + k;
        }
        #pragma unroll
        for (int nf=0; nf<4; nf++){
            int cn = n0 + warp_n*32 + nf*8 + 2*t;
            if (cn >= N) continue;
            float b0 = bias ? bias[cn]   : 0.f;
            float b1 = bias ? bias[cn+1] : 0.f;
            C[gr0*ldc + cn]   = acc[mf][nf][0] + b0;
            C[gr0*ldc + cn+1] = acc[mf][nf][1] + b1;
            C[gr1*ldc + cn]   = acc[mf][nf][2] + b0;
            C[gr1*ldc + cn+1] = acc[mf][nf][3] + b1;
        }
    }
}

// ---------------- bf16 tensor-core flash attention ----------------
// grid (8 q-tiles, 256 bt*head), 256 thr. 64 q x 32 d, keys in 8 chunks of 64.
__global__ __launch_bounds__(256)
void k_flash_bf(const float* __restrict__ qkv, float* __restrict__ o)
{
    __shared__ uint32_t Qs[64][20];   // bf16x2 along d (scaled)
    __shared__ uint32_t Ks[64][20];   // [key][d2]
    __shared__ uint32_t Vt[32][36];   // [d][key2]
    __shared__ uint32_t Ps[64][68];   // S fp32 bits
    __shared__ uint32_t Pb[64][36];   // P bf16x2 along key
    __shared__ float m_s[64], l_s[64], r_s[64];

    int bh = blockIdx.y;
    int bt = bh >> 2, h = bh & 3;
    const float* base = qkv + (long)bt*KK*(3*CC) + h*DH;
    int q0 = blockIdx.x * 64;

    int tid = threadIdx.x;
    int wid = tid >> 5, lane = tid & 31;
    int g = lane >> 2, t = lane & 3;
    const float scl = 0.17677669529663687f;  // 1/sqrt(32)

    // load Q (scaled, bf16 pairs along d)
    for (int i = tid; i < 64*16; i += 256){
        int k2 = i & 15, q = i >> 4;
        float2 v = *(const float2*)(base + (long)(q0+q)*(3*CC) + 2*k2);
        Qs[q][k2] = pk(v.x*scl, v.y*scl);
    }
    if (tid < 64){ m_s[tid] = -1e30f; l_s[tid] = 0.f; }

    int wm = wid & 1, wn = wid >> 1;     // QK roles
    int pm = wid & 3, pn = wid >> 2;     // PV roles

    float oacc[2][4] = {};
    int qrow = tid >> 2, tr = tid & 3;   // softmax mapping

    for (int kc = 0; kc < 8; kc++){
        int k0 = kc * 64;
        __syncthreads();
        for (int i = tid; i < 64*16; i += 256){
            int k2 = i & 15, k = i >> 4;
            float2 v = *(const float2*)(base + (long)(k0+k)*(3*CC) + CC + 2*k2);
            Ks[k][k2] = pk(v.x, v.y);
        }
        for (int i = tid; i < 32*32; i += 256){
            int d = i & 31, j = i >> 5;
            float v0 = base[(long)(k0+2*j)  *(3*CC) + 2*CC + d];
            float v1 = base[(long)(k0+2*j+1)*(3*CC) + 2*CC + d];
            Vt[d][j] = pk(v0, v1);
        }
        __syncthreads();

        // ---- S = Q K^T ----
        float sacc[2][2][4] = {};
        #pragma unroll
        for (int ks=0; ks<2; ks++){
            int kc2 = ks*8;
            uint32_t af[2][4], bf[2][2];
            #pragma unroll
            for (int mf=0; mf<2; mf++){
                int r = wm*32 + mf*16 + g;
                af[mf][0] = Qs[r][kc2+t];
                af[mf][1] = Qs[r+8][kc2+t];
                af[mf][2] = Qs[r][kc2+t+4];
                af[mf][3] = Qs[r+8][kc2+t+4];
            }
            #pragma unroll
            for (int nf=0; nf<2; nf++){
                int cn = wn*16 + nf*8 + g;
                bf[nf][0] = Ks[cn][kc2+t];
                bf[nf][1] = Ks[cn][kc2+t+4];
            }
            #pragma unroll
            for (int mf=0; mf<2; mf++)
                #pragma unroll
                for (int nf=0; nf<2; nf++)
                    mma_bf16(sacc[mf][nf], af[mf], bf[nf]);
        }
        #pragma unroll
        for (int mf=0; mf<2; mf++){
            int r0 = wm*32 + mf*16 + g;
            #pragma unroll
            for (int nf=0; nf<2; nf++){
                int cn = wn*16 + nf*8 + 2*t;
                Ps[r0][cn]     = __float_as_uint(sacc[mf][nf][0]);
                Ps[r0][cn+1]   = __float_as_uint(sacc[mf][nf][1]);
                Ps[r0+8][cn]   = __float_as_uint(sacc[mf][nf][2]);
                Ps[r0+8][cn+1] = __float_as_uint(sacc[mf][nf][3]);
            }
        }
        __syncthreads();

        // ---- online softmax: 4 threads/row, 16 cols each; pack P to bf16 ----
        {
            float v[16]; float mx = -1e30f;
            #pragma unroll
            for (int j=0;j<16;j++){
                v[j] = __uint_as_float(Ps[qrow][tr*16 + j]);
                mx = fmaxf(mx, v[j]);
            }
            mx = fmaxf(mx, __shfl_xor_sync(0xffffffffu, mx, 1));
            mx = fmaxf(mx, __shfl_xor_sync(0xffffffffu, mx, 2));
            float mold = m_s[qrow];
            float mnew = fmaxf(mold, mx);
            float sum = 0.f;
            #pragma unroll
            for (int j=0;j<16;j++){
                v[j] = __expf(v[j] - mnew);
                sum += v[j];
            }
            sum += __shfl_xor_sync(0xffffffffu, sum, 1);
            sum += __shfl_xor_sync(0xffffffffu, sum, 2);
            #pragma unroll
            for (int j=0;j<8;j++)
                Pb[qrow][tr*8 + j] = pk(v[2*j], v[2*j+1]);
            if (tr == 0){
                float r = __expf(mold - mnew);
                l_s[qrow] = l_s[qrow]*r + sum;
                m_s[qrow] = mnew;
                r_s[qrow] = r;
            }
        }
        __syncthreads();

        // ---- O = O*r + P V ----
        {
            float rr0 = r_s[pm*16 + g];
            float rr1 = r_s[pm*16 + g + 8];
            #pragma unroll
            for (int nf=0; nf<2; nf++){
                oacc[nf][0] *= rr0; oacc[nf][1] *= rr0;
                oacc[nf][2] *= rr1; oacc[nf][3] *= rr1;
            }
            #pragma unroll
            for (int ks=0; ks<4; ks++){
                int kc2 = ks*8;
                uint32_t af[4], bf[2][2];
                int r = pm*16 + g;
                af[0] = Pb[r][kc2+t];
                af[1] = Pb[r+8][kc2+t];
                af[2] = Pb[r][kc2+t+4];
                af[3] = Pb[r+8][kc2+t+4];
                #pragma unroll
                for (int nf=0; nf<2; nf++){
                    int cn = pn*16 + nf*8 + g;
                    bf[nf][0] = Vt[cn][kc2+t];
                    bf[nf][1] = Vt[cn][kc2+t+4];
                }
                #pragma unroll
                for (int nf=0; nf<2; nf++)
                    mma_bf16(oacc[nf], af, bf[nf]);
            }
        }
    }
    __syncthreads();
    {
        float inv0 = 1.f / l_s[pm*16 + g];
        float inv1 = 1.f / l_s[pm*16 + g + 8];
        int qA = q0 + pm*16 + g;
        int qB = qA + 8;
        #pragma unroll
        for (int nf=0; nf<2; nf++){
            int d = pn*16 + nf*8 + 2*t;
            long rowA = ((long)bt*KK + qA)*CC + h*DH + d;
            long rowB = ((long)bt*KK + qB)*CC + h*DH + d;
            o[rowA]   = oacc[nf][0]*inv0;
            o[rowA+1] = oacc[nf][1]*inv0;
            o[rowB]   = oacc[nf][2]*inv1;
            o[rowB+1] = oacc[nf][3]*inv1;
        }
    }
}

// ---------------- stage kernels ----------------
__global__ void k_copy(const float4* __restrict__ in, float4* __restrict__ out, int n4){
    int i = blockIdx.x*blockDim.x + threadIdx.x;
    if (i < n4) out[i] = in[i];
}

__global__ void k_mean(const float* __restrict__ x, float* __restrict__ xm){
    int i = blockIdx.x*blockDim.x + threadIdx.x;
    if (i >= BB*CC*NSP) return;
    int b = i >> 17; int rem = i & 131071;
    float s = 0.f;
    #pragma unroll
    for (int t=0;t<TT;t++) s += x[((long)b*TT+t)*131072 + rem];
    xm[i] = s * 0.125f;
}

__global__ void k_conv3(const float* __restrict__ xm, const float* __restrict__ w,
                        const float* __restrict__ bias, float* __restrict__ h1){
    __shared__ float pl[34*34];
    int bo = blockIdx.x; int b = bo >> 5; int oc = bo & 31;
    int tid = threadIdx.x;
    int h = tid >> 5, wq = tid & 31;
    float acc = 0.f;
    for (int ic=0; ic<CC; ic++){
        for (int i=tid; i<34*34; i+=1024){
            int hh = i/34 - 1, ww = i%34 - 1;
            pl[i] = (hh>=0 && hh<32 && ww>=0 && ww<32) ?
                    xm[((long)b*CC+ic)*NSP + hh*32+ww] : 0.f;
        }
        __syncthreads();
        const float* wp = w + ((long)oc*CC+ic)*9;
        #pragma unroll
        for (int kh=0;kh<3;kh++)
            #pragma unroll
            for (int kw=0;kw<3;kw++)
                acc += pl[(h+kh)*34 + (wq+kw)] * wp[kh*3+kw];
        __syncthreads();
    }
    acc += bias[oc];
    h1[(long)bo*NSP + tid] = (acc >= 0.f) ? acc : 0.01f*acc;
}

__global__ void k_score(const float* __restrict__ h1, const float* __restrict__ w2,
                        const float* __restrict__ b2, float* __restrict__ sc){
    int i = blockIdx.x*blockDim.x + threadIdx.x;
    if (i >= BB*NSP) return;
    int b = i >> 10, n = i & 1023;
    float a = 0.f;
    #pragma unroll
    for (int oc=0;oc<32;oc++) a += h1[((long)b*32+oc)*NSP + n] * w2[oc];
    a += b2[0];
    sc[i] = sigm(a);
}

__global__ void k_topk(const float* __restrict__ sc, int* __restrict__ idx,
                       float* __restrict__ scl){
    __shared__ float s[1024];
    __shared__ unsigned char keep[1024];
    int b = blockIdx.x, n = threadIdx.x;
    s[n] = sc[b*NSP + n];
    __syncthreads();
    float v = s[n];
    int cnt = 0;
    for (int m=0;m<1024;m++){ float u = s[m]; cnt += (u>v) || (u==v && m<n); }
    keep[n] = (cnt < KK) ? 1 : 0;
    __syncthreads();
    if (keep[n]){
        int pos = 0;
        for (int m=0;m<n;m++) pos += keep[m];
        idx[b*KK + pos] = n;
        scl[b*KK + pos] = v / (v + 1e-6f);
    }
}

__global__ void k_gather(const float* __restrict__ x, const int* __restrict__ idx,
                         const float* __restrict__ scl, const float* __restrict__ nw,
                         float* __restrict__ z0){
    __shared__ float red[4];
    long tok = blockIdx.x;
    int t = tok & 7; long bk = tok >> 3;
    int b = (int)(bk >> 9); int k = (int)(bk & 511);
    int c = threadIdx.x;
    int n = idx[b*KK + k];
    float sf = scl[b*KK + k];
    float v = x[(((long)b*TT + t)*CC + c)*NSP + n] * sf;
    float ss = blockReduce128(v*v, red);
    float r = rsqrtf(ss * (1.f/128.f) + 1e-5f);
    z0[tok*CC + c] = v * r * nw[c];
}

__global__ void k_conv1d(const float* __restrict__ xz, const float* __restrict__ w,
                         const float* __restrict__ bias, float* __restrict__ xc){
    int s = blockIdx.x; int ch = threadIdx.x;
    float in[TT];
    #pragma unroll
    for (int t=0;t<TT;t++) in[t] = xz[(((long)s*TT + t)*(2*DI)) + ch];
    float w0=w[ch*4+0], w1=w[ch*4+1], w2=w[ch*4+2], w3=w[ch*4+3];
    float bb = bias[ch];
    #pragma unroll
    for (int t=0;t<TT;t++){
        float a = bb + in[t]*w3;
        if (t>=1) a += in[t-1]*w2;
        if (t>=2) a += in[t-2]*w1;
        if (t>=3) a += in[t-3]*w0;
        xc[((long)s*TT + t)*DI + ch] = siluf(a);
    }
}

__global__ void k_scan2(const float* __restrict__ xc, const float* __restrict__ xdbl,
                        const float* __restrict__ dtw, const float* __restrict__ dtbias,
                        const float* __restrict__ Alog, const float* __restrict__ Dp,
                        const float* __restrict__ xz, float* __restrict__ yg){
    __shared__ float xd[TT][40];
    int s = blockIdx.x; int ch = threadIdx.x;
    for (int i = ch; i < TT*40; i += 256)
        xd[i/40][i%40] = xdbl[(long)s*TT*40 + i];
    float w8[DTR];
    #pragma unroll
    for (int r=0;r<DTR;r++) w8[r] = dtw[ch*DTR + r];
    float db = dtbias[ch];
    float Arow[DS];
    #pragma unroll
    for (int d=0;d<DS;d++) Arow[d] = -__expf(Alog[ch*DS + d]);
    float A0 = Arow[0];
    bool geom = true;
    #pragma unroll
    for (int d=1;d<DS;d++)
        geom = geom && (fabsf(Arow[d] - A0*(float)(d+1)) <= 1e-5f*fabsf(A0*(float)(d+1)) + 1e-12f);
    float Dv = Dp[ch];
    __syncthreads();
    float h[DS];
    #pragma unroll
    for (int d=0;d<DS;d++) h[d] = 0.f;
    #pragma unroll
    for (int t=0;t<TT;t++){
        long row = (long)s*TT + t;
        float dtr = db;
        #pragma unroll
        for (int r=0;r<DTR;r++) dtr += xd[t][r]*w8[r];
        float dt = softplusf(dtr);
        float u  = xc[row*DI + ch];
        float du = dt*u;
        float y = 0.f;
        if (geom){
            float e1 = __expf(dt*A0);
            float ed = 1.f;
            #pragma unroll
            for (int d=0;d<DS;d++){
                ed *= e1;
                float Bv = xd[t][DTR + d];
                float Cv = xd[t][DTR + DS + d];
                h[d] = h[d]*ed + du*Bv;
                y += h[d]*Cv;
            }
        } else {
            #pragma unroll
            for (int d=0;d<DS;d++){
                float Bv = xd[t][DTR + d];
                float Cv = xd[t][DTR + DS + d];
                h[d] = h[d]*__expf(dt*Arow[d]) + du*Bv;
                y += h[d]*Cv;
            }
        }
        float zg = xz[row*(2*DI) + DI + ch];
        yg[row*DI + ch] = (y + u*Dv) * siluf(zg);
    }
}

// fused layernorm + scatter-add into output
__global__ void k_lnsc(const float* __restrict__ zs, const float* __restrict__ tmo,
                       const float* __restrict__ w, const float* __restrict__ b,
                       const int* __restrict__ idx, float* __restrict__ out){
    __shared__ float r1[4], r2[4];
    long r = blockIdx.x;
    int k = (int)(r & 511); long bt = r >> 9;
    int bb2 = (int)(bt >> 3);
    int c = threadIdx.x;
    int n = idx[bb2*KK + k];
    float v = zs[r*CC + c] + tmo[r*CC + c];
    float s = blockReduce128(v, r1);
    float mu = s * (1.f/128.f);
    float d = v - mu;
    float q = blockReduce128(d*d, r2);
    float var = q * (1.f/128.f);
    float val = d * rsqrtf(var + 1e-5f) * w[c] + b[c];
    out[((bt*CC) + c)*NSP + n] += val;
}

// ---------------- host launch ----------------
static float* symf(const void* s){ void* p = nullptr; cudaGetSymbolAddress(&p, s); return (float*)p; }

extern "C" void kernel_launch(void* const* d_in, const int* in_sizes, int n_in,
                              void* d_out, int out_size)
{
    const float* x_in      = (const float*)d_in[0];
    const float* norm1_w   = (const float*)d_in[1];
    const float* in_proj_w = (const float*)d_in[2];
    const float* conv1d_w  = (const float*)d_in[3];
    const float* conv1d_b  = (const float*)d_in[4];
    const float* x_proj_w  = (const float*)d_in[5];
    const float* dt_proj_w = (const float*)d_in[6];
    const float* dt_proj_b = (const float*)d_in[7];
    const float* A_log     = (const float*)d_in[8];
    const float* Dp        = (const float*)d_in[9];
    const float* out_proj_w= (const float*)d_in[10];
    const float* r1_w      = (const float*)d_in[11];
    const float* r1_b      = (const float*)d_in[12];
    const float* r2_w      = (const float*)d_in[13];
    const float* r2_b      = (const float*)d_in[14];
    const float* attn_in_w = (const float*)d_in[15];
    const float* attn_in_b = (const float*)d_in[16];
    const float* attn_out_w= (const float*)d_in[17];
    const float* attn_out_b= (const float*)d_in[18];
    const float* ln_w      = (const float*)d_in[19];
    const float* ln_b      = (const float*)d_in[20];
    float* out = (float*)d_out;

    float *xm = symf(g_xm), *h1 = symf(g_h1), *sc = symf(g_sc);
    float *scl = symf(g_scl), *z0 = symf(g_z0), *xz = symf(g_xz);
    float *xc = symf(g_xc), *xdbl = symf(g_xdbl);
    float *yg = symf(g_yg), *zsb = symf(g_zs);
    float *qkv = symf(g_qkv), *orp = symf(g_orp);
    float *tmo = symf(g_tmo);
    int* idx = (int*)symf(g_idx);

    // 0) out = x_in
    {
        int n4 = (BB*TT*CC*NSP)/4;
        k_copy<<<(n4+255)/256, 256>>>((const float4*)x_in, (float4*)out, n4);
    }
    // 1) router
    k_mean<<<(BB*CC*NSP+255)/256, 256>>>(x_in, xm);
    k_conv3<<<BB*32, 1024>>>(xm, r1_w, r1_b, h1);
    k_score<<<(BB*NSP+255)/256, 256>>>(h1, r2_w, r2_b, sc);
    k_topk<<<BB, 1024>>>(sc, idx, scl);
    // 2) gather + rmsnorm
    k_gather<<<ROWS, CC>>>(x_in, idx, scl, norm1_w, z0);
    // 3) mamba
    gemm_bf<0><<<dim3(8,256),256>>>(z0, in_proj_w, nullptr, xz,
        ROWS, 2*DI, CC, CC, CC, 2*DI);
    k_conv1d<<<ROWS/TT, DI>>>(xz, conv1d_w, conv1d_b, xc);
    gemm_bf<0><<<dim3(1,256),256>>>(xc, x_proj_w, nullptr, xdbl,
        ROWS, 40, DI, DI, DI, 40);
    k_scan2<<<ROWS/TT, DI>>>(xc, xdbl, dt_proj_w, dt_proj_b, A_log, Dp, xz, yg);
    gemm_bf<1><<<dim3(2,256),256>>>(yg, out_proj_w, nullptr, zsb,
        ROWS, CC, DI, DI, DI, CC);
    // 4) attention
    gemm_bf<0><<<dim3(6,256),256>>>(zsb, attn_in_w, attn_in_b, qkv,
        ROWS, 3*CC, CC, CC, CC, 3*CC);
    k_flash_bf<<<dim3(8, NBATCH), 256>>>(qkv, orp);
    gemm_bf<0><<<dim3(2,256),256>>>(orp, attn_out_w, attn_out_b, tmo,
        ROWS, CC, CC, CC, CC, CC);
    // 5) layernorm + scatter + residual (fused)
    k_lnsc<<<ROWS, CC>>>(zsb, tmo, ln_w, ln_b, idx, out);
}

// round 9
// speedup vs baseline: 2.8206x; 1.1204x over previous
#include <cuda_runtime.h>
#include <cuda_bf16.h>
#include <cstdint>

// ---------------- problem constants ----------------
#define BB 8
#define TT 8
#define CC 128
#define NSP 1024
#define KK 512
#define DI 256
#define DS 16
#define DTR 8
#define NH 4
#define DH 32
#define ROWS 32768
#define NBATCH 256

// ---------------- device scratch ----------------
__device__ float g_xm  [BB*CC*NSP];
__device__ float g_h1  [BB*32*NSP];
__device__ int   g_idx [BB*KK];
__device__ float g_scl [BB*KK];
__device__ float g_z0  [(size_t)ROWS*CC];
__device__ float g_xz  [(size_t)ROWS*2*DI];
__device__ float g_xc  [(size_t)ROWS*DI];
__device__ float g_xdbl[(size_t)ROWS*40];
__device__ float g_yg  [(size_t)ROWS*DI];
__device__ float g_zs  [(size_t)ROWS*CC];
__device__ float g_qkv [(size_t)ROWS*3*CC];
__device__ float g_orp [(size_t)ROWS*CC];

// ---------------- helpers ----------------
__device__ __forceinline__ float sigm(float x){ return 1.f/(1.f+__expf(-x)); }
__device__ __forceinline__ float siluf(float x){ return x*sigm(x); }
__device__ __forceinline__ float softplusf(float x){ return (x>20.f)?x:log1pf(__expf(x)); }

__device__ __forceinline__ uint32_t pk(float lo, float hi){
    __nv_bfloat162 v = __floats2bfloat162_rn(lo, hi);
    return *reinterpret_cast<uint32_t*>(&v);
}

__device__ __forceinline__ float blockReduce128(float v, float* red){
    #pragma unroll
    for (int o=16;o>0;o>>=1) v += __shfl_xor_sync(0xffffffffu, v, o);
    int w = threadIdx.x >> 5;
    if ((threadIdx.x & 31)==0) red[w]=v;
    __syncthreads();
    return red[0]+red[1]+red[2]+red[3];
}

__device__ __forceinline__ void mma_bf16(float* c, const uint32_t* a, const uint32_t* b){
    asm volatile(
        "mma.sync.aligned.m16n8k16.row.col.f32.bf16.bf16.f32 "
        "{%0,%1,%2,%3}, {%4,%5,%6,%7}, {%8,%9}, {%0,%1,%2,%3};"
        : "+f"(c[0]), "+f"(c[1]), "+f"(c[2]), "+f"(c[3])
        : "r"(a[0]), "r"(a[1]), "r"(a[2]), "r"(a[3]), "r"(b[0]), "r"(b[1]));
}

// ---------------- bf16 tensor-core TN GEMM ----------------
// C = A * Bw^T (+bias). BM=128, BN in {64,128}, BK=32 fp32 elems.
// 8 warps (4 m x 2 n), warp tile 32 x BN/2.
// MODE 0: plain. MODE 1: (b,k,t)->(b,t,k) row permute on store.
// MODE 2: (BN=128,N=128 only) bias + residual(zres) + LayerNorm + scatter-add
//         into C at column n=idxp[b][k] (C is the (B,T,C,H,W) output tensor).
template<int BN, int MODE>
__global__ __launch_bounds__(256)
void gemm_bf(const float* __restrict__ A, const float* __restrict__ Bw,
             const float* __restrict__ bias, float* __restrict__ C,
             int M, int N, int Kd, int lda, int ldb, int ldc,
             const float* __restrict__ zres, const float* __restrict__ lnw,
             const float* __restrict__ lnb, const int* __restrict__ idxp)
{
    constexpr int NF = BN/16;     // n-frags per warp
    constexpr int BU = BN/32;     // B float4 loads per thread per tile
    __shared__ union SU {
        struct { uint32_t As[2][128][20]; uint32_t Bs[2][BN][20]; } g;
        float red[128][17];
    } S;

    int m0 = blockIdx.y*128, n0 = blockIdx.x*BN;
    int tid = threadIdx.x;
    int wid = tid >> 5, lane = tid & 31;
    int warp_m = wid >> 1, warp_n = wid & 1;
    int g = lane >> 2, t = lane & 3;

    float acc[2][NF][4] = {};
    float4 ra[4], rb[BU];
    int nk = Kd >> 5;

    // ---- stage tile 0 ----
    #pragma unroll
    for (int u=0;u<4;u++){
        int f = tid + u*256; int k4 = f&7, m = f>>3;
        ra[u] = *(const float4*)(A + (long)(m0+m)*lda + k4*4);
    }
    #pragma unroll
    for (int u=0;u<BU;u++){
        int f = tid + u*256; int k4 = f&7, n = f>>3;
        int gn = n0 + n;
        float4 v = {0.f,0.f,0.f,0.f};
        if (gn < N) v = *(const float4*)(Bw + (long)gn*ldb + k4*4);
        rb[u] = v;
    }
    #pragma unroll
    for (int u=0;u<4;u++){
        int f = tid + u*256; int k4 = f&7, m = f>>3;
        S.g.As[0][m][k4*2]   = pk(ra[u].x, ra[u].y);
        S.g.As[0][m][k4*2+1] = pk(ra[u].z, ra[u].w);
    }
    #pragma unroll
    for (int u=0;u<BU;u++){
        int f = tid + u*256; int k4 = f&7, n = f>>3;
        S.g.Bs[0][n][k4*2]   = pk(rb[u].x, rb[u].y);
        S.g.Bs[0][n][k4*2+1] = pk(rb[u].z, rb[u].w);
    }
    __syncthreads();

    int buf = 0;
    for (int kt = 0; kt < nk; kt++){
        if (kt+1 < nk){
            int k0 = (kt+1)*32;
            #pragma unroll
            for (int u=0;u<4;u++){
                int f = tid + u*256; int k4 = f&7, m = f>>3;
                ra[u] = *(const float4*)(A + (long)(m0+m)*lda + k0 + k4*4);
            }
            #pragma unroll
            for (int u=0;u<BU;u++){
                int f = tid + u*256; int k4 = f&7, n = f>>3;
                int gn = n0 + n;
                float4 v = {0.f,0.f,0.f,0.f};
                if (gn < N) v = *(const float4*)(Bw + (long)gn*ldb + k0 + k4*4);
                rb[u] = v;
            }
        }
        #pragma unroll
        for (int ks=0; ks<2; ks++){
            int kc2 = ks*8;
            uint32_t af[2][4], bfr[NF][2];
            #pragma unroll
            for (int mf=0; mf<2; mf++){
                int r = warp_m*32 + mf*16 + g;
                af[mf][0] = S.g.As[buf][r][kc2+t];
                af[mf][1] = S.g.As[buf][r+8][kc2+t];
                af[mf][2] = S.g.As[buf][r][kc2+t+4];
                af[mf][3] = S.g.As[buf][r+8][kc2+t+4];
            }
            #pragma unroll
            for (int nf=0; nf<NF; nf++){
                int cn = warp_n*(BN/2) + nf*8 + g;
                bfr[nf][0] = S.g.Bs[buf][cn][kc2+t];
                bfr[nf][1] = S.g.Bs[buf][cn][kc2+t+4];
            }
            #pragma unroll
            for (int mf=0; mf<2; mf++)
                #pragma unroll
                for (int nf=0; nf<NF; nf++)
                    mma_bf16(acc[mf][nf], af[mf], bfr[nf]);
        }
        if (kt+1 < nk){
            int nb = buf^1;
            #pragma unroll
            for (int u=0;u<4;u++){
                int f = tid + u*256; int k4 = f&7, m = f>>3;
                S.g.As[nb][m][k4*2]   = pk(ra[u].x, ra[u].y);
                S.g.As[nb][m][k4*2+1] = pk(ra[u].z, ra[u].w);
            }
            #pragma unroll
            for (int u=0;u<BU;u++){
                int f = tid + u*256; int k4 = f&7, n = f>>3;
                S.g.Bs[nb][n][k4*2]   = pk(rb[u].x, rb[u].y);
                S.g.Bs[nb][n][k4*2+1] = pk(rb[u].z, rb[u].w);
            }
            __syncthreads();
            buf = nb;
        }
    }

    if (MODE == 2){
        // bias + residual + LayerNorm + scatter-add (BN=128, N=128)
        __syncthreads();   // done with As/Bs; reuse as red[]
        float sum[2][2] = {}, sq[2][2] = {};
        #pragma unroll
        for (int mf=0;mf<2;mf++){
            int rl0 = warp_m*32 + mf*16 + g;
            long gr0 = m0 + rl0, gr1 = gr0 + 8;
            #pragma unroll
            for (int nf=0;nf<NF;nf++){
                int cn = warp_n*(BN/2) + nf*8 + 2*t;
                float b0 = bias[cn], b1 = bias[cn+1];
                float v0 = acc[mf][nf][0] + b0 + zres[gr0*CC + cn];
                float v1 = acc[mf][nf][1] + b1 + zres[gr0*CC + cn+1];
                float v2 = acc[mf][nf][2] + b0 + zres[gr1*CC + cn];
                float v3 = acc[mf][nf][3] + b1 + zres[gr1*CC + cn+1];
                acc[mf][nf][0]=v0; acc[mf][nf][1]=v1; acc[mf][nf][2]=v2; acc[mf][nf][3]=v3;
                sum[mf][0] += v0+v1;   sum[mf][1] += v2+v3;
                sq[mf][0]  += v0*v0+v1*v1; sq[mf][1] += v2*v2+v3*v3;
            }
        }
        int cid = warp_n*4 + t;
        #pragma unroll
        for (int mf=0;mf<2;mf++){
            int rl0 = warp_m*32 + mf*16 + g;
            S.red[rl0][cid]     = sum[mf][0];  S.red[rl0][8+cid]   = sq[mf][0];
            S.red[rl0+8][cid]   = sum[mf][1];  S.red[rl0+8][8+cid] = sq[mf][1];
        }
        __syncthreads();
        #pragma unroll
        for (int mf=0;mf<2;mf++){
            #pragma unroll
            for (int half=0; half<2; half++){
                int rl = warp_m*32 + mf*16 + g + half*8;
                float s8 = 0.f, q8 = 0.f;
                #pragma unroll
                for (int j=0;j<8;j++){ s8 += S.red[rl][j]; q8 += S.red[rl][8+j]; }
                float mu = s8 * (1.f/128.f);
                float var = q8 * (1.f/128.f) - mu*mu;
                float rsig = rsqrtf(var + 1e-5f);
                long gm = m0 + rl;
                int k = (int)(gm & 511); long bt = gm >> 9;
                int bidx = (int)(bt >> 3);
                int n = idxp[bidx*KK + k];
                float* ob = C + (bt*CC)*NSP + n;
                #pragma unroll
                for (int nf=0;nf<NF;nf++){
                    int cn = warp_n*(BN/2) + nf*8 + 2*t;
                    float vA = acc[mf][nf][half*2];
                    float vB = acc[mf][nf][half*2+1];
                    ob[(long)cn*NSP]     += (vA-mu)*rsig*lnw[cn]   + lnb[cn];
                    ob[(long)(cn+1)*NSP] += (vB-mu)*rsig*lnw[cn+1] + lnb[cn+1];
                }
            }
        }
        return;
    }

    #pragma unroll
    for (int mf=0; mf<2; mf++){
        int r0 = m0 + warp_m*32 + mf*16 + g;
        int r1 = r0 + 8;
        long gr0 = r0, gr1 = r1;
        if (MODE==1){
            int b = r0 >> 12; int k = (r0 >> 3) & 511; int tt = r0 & 7;
            gr0 = ((long)(b*8 + tt) << 9) + k;
            b = r1 >> 12; k = (r1 >> 3) & 511; tt = r1 & 7;
            gr1 = ((long)(b*8 + tt) << 9) + k;
        }
        #pragma unroll
        for (int nf=0; nf<NF; nf++){
            int cn = n0 + warp_n*(BN/2) + nf*8 + 2*t;
            if (cn >= N) continue;
            float b0 = bias ? bias[cn]   : 0.f;
            float b1 = bias ? bias[cn+1] : 0.f;
            C[gr0*ldc + cn]   = acc[mf][nf][0] + b0;
            C[gr0*ldc + cn+1] = acc[mf][nf][1] + b1;
            C[gr1*ldc + cn]   = acc[mf][nf][2] + b0;
            C[gr1*ldc + cn+1] = acc[mf][nf][3] + b1;
        }
    }
}

// ---------------- bf16 tensor-core flash attention ----------------
__global__ __launch_bounds__(256)
void k_flash_bf(const float* __restrict__ qkv, float* __restrict__ o)
{
    __shared__ uint32_t Qs[64][20];
    __shared__ uint32_t Ks[64][20];
    __shared__ uint32_t Vt[32][36];
    __shared__ uint32_t Ps[64][68];
    __shared__ uint32_t Pb[64][36];
    __shared__ float m_s[64], l_s[64], r_s[64];

    int bh = blockIdx.y;
    int bt = bh >> 2, h = bh & 3;
    const float* base = qkv + (long)bt*KK*(3*CC) + h*DH;
    int q0 = blockIdx.x * 64;

    int tid = threadIdx.x;
    int wid = tid >> 5, lane = tid & 31;
    int g = lane >> 2, t = lane & 3;
    const float scl = 0.17677669529663687f;

    for (int i = tid; i < 64*16; i += 256){
        int k2 = i & 15, q = i >> 4;
        float2 v = *(const float2*)(base + (long)(q0+q)*(3*CC) + 2*k2);
        Qs[q][k2] = pk(v.x*scl, v.y*scl);
    }
    if (tid < 64){ m_s[tid] = -1e30f; l_s[tid] = 0.f; }

    int wm = wid & 1, wn = wid >> 1;
    int pm = wid & 3, pn = wid >> 2;

    float oacc[2][4] = {};
    int qrow = tid >> 2, tr = tid & 3;

    for (int kc = 0; kc < 8; kc++){
        int k0 = kc * 64;
        __syncthreads();
        for (int i = tid; i < 64*16; i += 256){
            int k2 = i & 15, k = i >> 4;
            float2 v = *(const float2*)(base + (long)(k0+k)*(3*CC) + CC + 2*k2);
            Ks[k][k2] = pk(v.x, v.y);
        }
        for (int i = tid; i < 32*32; i += 256){
            int d = i & 31, j = i >> 5;
            float v0 = base[(long)(k0+2*j)  *(3*CC) + 2*CC + d];
            float v1 = base[(long)(k0+2*j+1)*(3*CC) + 2*CC + d];
            Vt[d][j] = pk(v0, v1);
        }
        __syncthreads();

        float sacc[2][2][4] = {};
        #pragma unroll
        for (int ks=0; ks<2; ks++){
            int kc2 = ks*8;
            uint32_t af[2][4], bf[2][2];
            #pragma unroll
            for (int mf=0; mf<2; mf++){
                int r = wm*32 + mf*16 + g;
                af[mf][0] = Qs[r][kc2+t];
                af[mf][1] = Qs[r+8][kc2+t];
                af[mf][2] = Qs[r][kc2+t+4];
                af[mf][3] = Qs[r+8][kc2+t+4];
            }
            #pragma unroll
            for (int nf=0; nf<2; nf++){
                int cn = wn*16 + nf*8 + g;
                bf[nf][0] = Ks[cn][kc2+t];
                bf[nf][1] = Ks[cn][kc2+t+4];
            }
            #pragma unroll
            for (int mf=0; mf<2; mf++)
                #pragma unroll
                for (int nf=0; nf<2; nf++)
                    mma_bf16(sacc[mf][nf], af[mf], bf[nf]);
        }
        #pragma unroll
        for (int mf=0; mf<2; mf++){
            int r0 = wm*32 + mf*16 + g;
            #pragma unroll
            for (int nf=0; nf<2; nf++){
                int cn = wn*16 + nf*8 + 2*t;
                Ps[r0][cn]     = __float_as_uint(sacc[mf][nf][0]);
                Ps[r0][cn+1]   = __float_as_uint(sacc[mf][nf][1]);
                Ps[r0+8][cn]   = __float_as_uint(sacc[mf][nf][2]);
                Ps[r0+8][cn+1] = __float_as_uint(sacc[mf][nf][3]);
            }
        }
        __syncthreads();

        {
            float v[16]; float mx = -1e30f;
            #pragma unroll
            for (int j=0;j<16;j++){
                v[j] = __uint_as_float(Ps[qrow][tr*16 + j]);
                mx = fmaxf(mx, v[j]);
            }
            mx = fmaxf(mx, __shfl_xor_sync(0xffffffffu, mx, 1));
            mx = fmaxf(mx, __shfl_xor_sync(0xffffffffu, mx, 2));
            float mold = m_s[qrow];
            float mnew = fmaxf(mold, mx);
            float sum = 0.f;
            #pragma unroll
            for (int j=0;j<16;j++){
                v[j] = __expf(v[j] - mnew);
                sum += v[j];
            }
            sum += __shfl_xor_sync(0xffffffffu, sum, 1);
            sum += __shfl_xor_sync(0xffffffffu, sum, 2);
            #pragma unroll
            for (int j=0;j<8;j++)
                Pb[qrow][tr*8 + j] = pk(v[2*j], v[2*j+1]);
            if (tr == 0){
                float r = __expf(mold - mnew);
                l_s[qrow] = l_s[qrow]*r + sum;
                m_s[qrow] = mnew;
                r_s[qrow] = r;
            }
        }
        __syncthreads();

        {
            float rr0 = r_s[pm*16 + g];
            float rr1 = r_s[pm*16 + g + 8];
            #pragma unroll
            for (int nf=0; nf<2; nf++){
                oacc[nf][0] *= rr0; oacc[nf][1] *= rr0;
                oacc[nf][2] *= rr1; oacc[nf][3] *= rr1;
            }
            #pragma unroll
            for (int ks=0; ks<4; ks++){
                int kc2 = ks*8;
                uint32_t af[4], bf[2][2];
                int r = pm*16 + g;
                af[0] = Pb[r][kc2+t];
                af[1] = Pb[r+8][kc2+t];
                af[2] = Pb[r][kc2+t+4];
                af[3] = Pb[r+8][kc2+t+4];
                #pragma unroll
                for (int nf=0; nf<2; nf++){
                    int cn = pn*16 + nf*8 + g;
                    bf[nf][0] = Vt[cn][kc2+t];
                    bf[nf][1] = Vt[cn][kc2+t+4];
                }
                #pragma unroll
                for (int nf=0; nf<2; nf++)
                    mma_bf16(oacc[nf], af, bf[nf]);
            }
        }
    }
    __syncthreads();
    {
        float inv0 = 1.f / l_s[pm*16 + g];
        float inv1 = 1.f / l_s[pm*16 + g + 8];
        int qA = q0 + pm*16 + g;
        int qB = qA + 8;
        #pragma unroll
        for (int nf=0; nf<2; nf++){
            int d = pn*16 + nf*8 + 2*t;
            long rowA = ((long)bt*KK + qA)*CC + h*DH + d;
            long rowB = ((long)bt*KK + qB)*CC + h*DH + d;
            o[rowA]   = oacc[nf][0]*inv0;
            o[rowA+1] = oacc[nf][1]*inv0;
            o[rowB]   = oacc[nf][2]*inv1;
            o[rowB+1] = oacc[nf][3]*inv1;
        }
    }
}

// ---------------- stage kernels ----------------
__global__ void k_copy(const float4* __restrict__ in, float4* __restrict__ out, int n4){
    int i = blockIdx.x*blockDim.x + threadIdx.x;
    if (i < n4) out[i] = in[i];
}

__global__ void k_mean(const float* __restrict__ x, float* __restrict__ xm){
    int i = blockIdx.x*blockDim.x + threadIdx.x;
    if (i >= BB*CC*NSP) return;
    int b = i >> 17; int rem = i & 131071;
    float s = 0.f;
    #pragma unroll
    for (int t=0;t<TT;t++) s += x[((long)b*TT+t)*131072 + rem];
    xm[i] = s * 0.125f;
}

__global__ void k_conv3(const float* __restrict__ xm, const float* __restrict__ w,
                        const float* __restrict__ bias, float* __restrict__ h1){
    __shared__ float pl[34*34];
    int bo = blockIdx.x; int b = bo >> 5; int oc = bo & 31;
    int tid = threadIdx.x;
    int h = tid >> 5, wq = tid & 31;
    float acc = 0.f;
    for (int ic=0; ic<CC; ic++){
        for (int i=tid; i<34*34; i+=1024){
            int hh = i/34 - 1, ww = i%34 - 1;
            pl[i] = (hh>=0 && hh<32 && ww>=0 && ww<32) ?
                    xm[((long)b*CC+ic)*NSP + hh*32+ww] : 0.f;
        }
        __syncthreads();
        const float* wp = w + ((long)oc*CC+ic)*9;
        #pragma unroll
        for (int kh=0;kh<3;kh++)
            #pragma unroll
            for (int kw=0;kw<3;kw++)
                acc += pl[(h+kh)*34 + (wq+kw)] * wp[kh*3+kw];
        __syncthreads();
    }
    acc += bias[oc];
    h1[(long)bo*NSP + tid] = (acc >= 0.f) ? acc : 0.01f*acc;
}

// fused score (1x1 conv + sigmoid) + exact top-K with compaction
__global__ void k_scoretopk(const float* __restrict__ h1, const float* __restrict__ w2,
                            const float* __restrict__ b2, int* __restrict__ idx,
                            float* __restrict__ scl){
    __shared__ float s[1024];
    __shared__ unsigned char keep[1024];
    int b = blockIdx.x, n = threadIdx.x;
    float a = 0.f;
    #pragma unroll
    for (int oc=0;oc<32;oc++) a += h1[((long)b*32+oc)*NSP + n] * w2[oc];
    float v = sigm(a + b2[0]);
    s[n] = v;
    __syncthreads();
    int cnt = 0;
    for (int m=0;m<1024;m++){ float u = s[m]; cnt += (u>v) || (u==v && m<n); }
    keep[n] = (cnt < KK) ? 1 : 0;
    __syncthreads();
    if (keep[n]){
        int pos = 0;
        for (int m=0;m<n;m++) pos += keep[m];
        idx[b*KK + pos] = n;
        scl[b*KK + pos] = v / (v + 1e-6f);
    }
}

__global__ void k_gather(const float* __restrict__ x, const int* __restrict__ idx,
                         const float* __restrict__ scl, const float* __restrict__ nw,
                         float* __restrict__ z0){
    __shared__ float red[4];
    long tok = blockIdx.x;
    int t = tok & 7; long bk = tok >> 3;
    int b = (int)(bk >> 9); int k = (int)(bk & 511);
    int c = threadIdx.x;
    int n = idx[b*KK + k];
    float sf = scl[b*KK + k];
    float v = x[(((long)b*TT + t)*CC + c)*NSP + n] * sf;
    float ss = blockReduce128(v*v, red);
    float r = rsqrtf(ss * (1.f/128.f) + 1e-5f);
    z0[tok*CC + c] = v * r * nw[c];
}

__global__ void k_conv1d(const float* __restrict__ xz, const float* __restrict__ w,
                         const float* __restrict__ bias, float* __restrict__ xc){
    int s = blockIdx.x; int ch = threadIdx.x;
    float in[TT];
    #pragma unroll
    for (int t=0;t<TT;t++) in[t] = xz[(((long)s*TT + t)*(2*DI)) + ch];
    float w0=w[ch*4+0], w1=w[ch*4+1], w2=w[ch*4+2], w3=w[ch*4+3];
    float bb = bias[ch];
    #pragma unroll
    for (int t=0;t<TT;t++){
        float a = bb + in[t]*w3;
        if (t>=1) a += in[t-1]*w2;
        if (t>=2) a += in[t-2]*w1;
        if (t>=3) a += in[t-3]*w0;
        xc[((long)s*TT + t)*DI + ch] = siluf(a);
    }
}

__global__ void k_scan2(const float* __restrict__ xc, const float* __restrict__ xdbl,
                        const float* __restrict__ dtw, const float* __restrict__ dtbias,
                        const float* __restrict__ Alog, const float* __restrict__ Dp,
                        const float* __restrict__ xz, float* __restrict__ yg){
    __shared__ float xd[TT][40];
    int s = blockIdx.x; int ch = threadIdx.x;
    for (int i = ch; i < TT*40; i += 256)
        xd[i/40][i%40] = xdbl[(long)s*TT*40 + i];
    float w8[DTR];
    #pragma unroll
    for (int r=0;r<DTR;r++) w8[r] = dtw[ch*DTR + r];
    float db = dtbias[ch];
    float Arow[DS];
    #pragma unroll
    for (int d=0;d<DS;d++) Arow[d] = -__expf(Alog[ch*DS + d]);
    float A0 = Arow[0];
    bool geom = true;
    #pragma unroll
    for (int d=1;d<DS;d++)
        geom = geom && (fabsf(Arow[d] - A0*(float)(d+1)) <= 1e-5f*fabsf(A0*(float)(d+1)) + 1e-12f);
    float Dv = Dp[ch];
    __syncthreads();
    float h[DS];
    #pragma unroll
    for (int d=0;d<DS;d++) h[d] = 0.f;
    #pragma unroll
    for (int t=0;t<TT;t++){
        long row = (long)s*TT + t;
        float dtr = db;
        #pragma unroll
        for (int r=0;r<DTR;r++) dtr += xd[t][r]*w8[r];
        float dt = softplusf(dtr);
        float u  = xc[row*DI + ch];
        float du = dt*u;
        float y = 0.f;
        if (geom){
            float e1 = __expf(dt*A0);
            float ed = 1.f;
            #pragma unroll
            for (int d=0;d<DS;d++){
                ed *= e1;
                float Bv = xd[t][DTR + d];
                float Cv = xd[t][DTR + DS + d];
                h[d] = h[d]*ed + du*Bv;
                y += h[d]*Cv;
            }
        } else {
            #pragma unroll
            for (int d=0;d<DS;d++){
                float Bv = xd[t][DTR + d];
                float Cv = xd[t][DTR + DS + d];
                h[d] = h[d]*__expf(dt*Arow[d]) + du*Bv;
                y += h[d]*Cv;
            }
        }
        float zg = xz[row*(2*DI) + DI + ch];
        yg[row*DI + ch] = (y + u*Dv) * siluf(zg);
    }
}

// ---------------- host launch ----------------
static float* symf(const void* s){ void* p = nullptr; cudaGetSymbolAddress(&p, s); return (float*)p; }

extern "C" void kernel_launch(void* const* d_in, const int* in_sizes, int n_in,
                              void* d_out, int out_size)
{
    const float* x_in      = (const float*)d_in[0];
    const float* norm1_w   = (const float*)d_in[1];
    const float* in_proj_w = (const float*)d_in[2];
    const float* conv1d_w  = (const float*)d_in[3];
    const float* conv1d_b  = (const float*)d_in[4];
    const float* x_proj_w  = (const float*)d_in[5];
    const float* dt_proj_w = (const float*)d_in[6];
    const float* dt_proj_b = (const float*)d_in[7];
    const float* A_log     = (const float*)d_in[8];
    const float* Dp        = (const float*)d_in[9];
    const float* out_proj_w= (const float*)d_in[10];
    const float* r1_w      = (const float*)d_in[11];
    const float* r1_b      = (const float*)d_in[12];
    const float* r2_w      = (const float*)d_in[13];
    const float* r2_b      = (const float*)d_in[14];
    const float* attn_in_w = (const float*)d_in[15];
    const float* attn_in_b = (const float*)d_in[16];
    const float* attn_out_w= (const float*)d_in[17];
    const float* attn_out_b= (const float*)d_in[18];
    const float* ln_w      = (const float*)d_in[19];
    const float* ln_b      = (const float*)d_in[20];
    float* out = (float*)d_out;

    float *xm = symf(g_xm), *h1 = symf(g_h1);
    float *scl = symf(g_scl), *z0 = symf(g_z0), *xz = symf(g_xz);
    float *xc = symf(g_xc), *xdbl = symf(g_xdbl);
    float *yg = symf(g_yg), *zsb = symf(g_zs);
    float *qkv = symf(g_qkv), *orp = symf(g_orp);
    int* idx = (int*)symf(g_idx);

    // 1) router
    k_mean<<<(BB*CC*NSP+255)/256, 256>>>(x_in, xm);
    k_conv3<<<BB*32, 1024>>>(xm, r1_w, r1_b, h1);
    k_scoretopk<<<BB, 1024>>>(h1, r2_w, r2_b, idx, scl);
    // 2) gather + rmsnorm   (profiled launch slot)
    k_gather<<<ROWS, CC>>>(x_in, idx, scl, norm1_w, z0);
    // 3) mamba
    gemm_bf<128,0><<<dim3(4,256),256>>>(z0, in_proj_w, nullptr, xz,
        ROWS, 2*DI, CC, CC, CC, 2*DI, nullptr, nullptr, nullptr, nullptr);
    k_conv1d<<<ROWS/TT, DI>>>(xz, conv1d_w, conv1d_b, xc);
    gemm_bf<64,0><<<dim3(1,256),256>>>(xc, x_proj_w, nullptr, xdbl,
        ROWS, 40, DI, DI, DI, 40, nullptr, nullptr, nullptr, nullptr);
    k_scan2<<<ROWS/TT, DI>>>(xc, xdbl, dt_proj_w, dt_proj_b, A_log, Dp, xz, yg);
    gemm_bf<128,1><<<dim3(1,256),256>>>(yg, out_proj_w, nullptr, zsb,
        ROWS, CC, DI, DI, DI, CC, nullptr, nullptr, nullptr, nullptr);
    // 4) attention
    gemm_bf<128,0><<<dim3(3,256),256>>>(zsb, attn_in_w, attn_in_b, qkv,
        ROWS, 3*CC, CC, CC, CC, 3*CC, nullptr, nullptr, nullptr, nullptr);
    k_flash_bf<<<dim3(8, NBATCH), 256>>>(qkv, orp);
    // 5) out = x_in, then attn_out + LayerNorm + scatter-add fused epilogue
    {
        int n4 = (BB*TT*CC*NSP)/4;
        k_copy<<<(n4+255)/256, 256>>>((const float4*)x_in, (float4*)out, n4);
    }
    gemm_bf<128,2><<<dim3(1,256),256>>>(orp, attn_out_w, attn_out_b, out,
        ROWS, CC, CC, CC, CC, NSP, zsb, ln_w, ln_b, idx);
}

// round 11
// speedup vs baseline: 2.9822x; 1.0573x over previous
#include <cuda_runtime.h>
#include <cuda_bf16.h>
#include <cstdint>

// ---------------- problem constants ----------------
#define BB 8
#define TT 8
#define CC 128
#define NSP 1024
#define KK 512
#define DI 256
#define DS 16
#define DTR 8
#define NH 4
#define DH 32
#define ROWS 32768
#define NBATCH 256

// ---------------- device scratch ----------------
__device__ float g_xm  [BB*CC*NSP];
__device__ float g_h1  [BB*32*NSP];
__device__ int   g_idx [BB*KK];
__device__ float g_scl [BB*KK];
__device__ float g_z0  [(size_t)ROWS*CC];
__device__ float g_xz  [(size_t)ROWS*2*DI];
__device__ float g_xc  [(size_t)ROWS*DI];
__device__ float g_xdbl[(size_t)ROWS*40];
__device__ float g_yg  [(size_t)ROWS*DI];
__device__ float g_zs  [(size_t)ROWS*CC];
__device__ float g_qkv [(size_t)ROWS*3*CC];
__device__ float g_orp [(size_t)ROWS*CC];

// ---------------- helpers ----------------
__device__ __forceinline__ float sigm(float x){ return 1.f/(1.f+__expf(-x)); }
__device__ __forceinline__ float siluf(float x){ return x*sigm(x); }
__device__ __forceinline__ float softplusf(float x){ return (x>20.f)?x:log1pf(__expf(x)); }

__device__ __forceinline__ uint32_t pk(float lo, float hi){
    __nv_bfloat162 v = __floats2bfloat162_rn(lo, hi);
    return *reinterpret_cast<uint32_t*>(&v);
}

__device__ __forceinline__ void mma_bf16(float* c, const uint32_t* a, const uint32_t* b){
    asm volatile(
        "mma.sync.aligned.m16n8k16.row.col.f32.bf16.bf16.f32 "
        "{%0,%1,%2,%3}, {%4,%5,%6,%7}, {%8,%9}, {%0,%1,%2,%3};"
        : "+f"(c[0]), "+f"(c[1]), "+f"(c[2]), "+f"(c[3])
        : "r"(a[0]), "r"(a[1]), "r"(a[2]), "r"(a[3]), "r"(b[0]), "r"(b[1]));
}

// ---------------- bf16 tensor-core TN GEMM ----------------
// MODE 0: plain. MODE 1: (b,k,t)->(b,t,k) row permute on store.
// MODE 2: bias + residual + LayerNorm + scatter-add into output tensor.
template<int BN, int MODE>
__global__ __launch_bounds__(256)
void gemm_bf(const float* __restrict__ A, const float* __restrict__ Bw,
             const float* __restrict__ bias, float* __restrict__ C,
             int M, int N, int Kd, int lda, int ldb, int ldc,
             const float* __restrict__ zres, const float* __restrict__ lnw,
             const float* __restrict__ lnb, const int* __restrict__ idxp)
{
    constexpr int NF = BN/16;
    constexpr int BU = BN/32;
    __shared__ union SU {
        struct { uint32_t As[2][128][20]; uint32_t Bs[2][BN][20]; } g;
        float red[128][17];
    } S;

    int m0 = blockIdx.y*128, n0 = blockIdx.x*BN;
    int tid = threadIdx.x;
    int wid = tid >> 5, lane = tid & 31;
    int warp_m = wid >> 1, warp_n = wid & 1;
    int g = lane >> 2, t = lane & 3;

    float acc[2][NF][4] = {};
    float4 ra[4], rb[BU];
    int nk = Kd >> 5;

    #pragma unroll
    for (int u=0;u<4;u++){
        int f = tid + u*256; int k4 = f&7, m = f>>3;
        ra[u] = *(const float4*)(A + (long)(m0+m)*lda + k4*4);
    }
    #pragma unroll
    for (int u=0;u<BU;u++){
        int f = tid + u*256; int k4 = f&7, n = f>>3;
        int gn = n0 + n;
        float4 v = {0.f,0.f,0.f,0.f};
        if (gn < N) v = *(const float4*)(Bw + (long)gn*ldb + k4*4);
        rb[u] = v;
    }
    #pragma unroll
    for (int u=0;u<4;u++){
        int f = tid + u*256; int k4 = f&7, m = f>>3;
        S.g.As[0][m][k4*2]   = pk(ra[u].x, ra[u].y);
        S.g.As[0][m][k4*2+1] = pk(ra[u].z, ra[u].w);
    }
    #pragma unroll
    for (int u=0;u<BU;u++){
        int f = tid + u*256; int k4 = f&7, n = f>>3;
        S.g.Bs[0][n][k4*2]   = pk(rb[u].x, rb[u].y);
        S.g.Bs[0][n][k4*2+1] = pk(rb[u].z, rb[u].w);
    }
    __syncthreads();

    int buf = 0;
    for (int kt = 0; kt < nk; kt++){
        if (kt+1 < nk){
            int k0 = (kt+1)*32;
            #pragma unroll
            for (int u=0;u<4;u++){
                int f = tid + u*256; int k4 = f&7, m = f>>3;
                ra[u] = *(const float4*)(A + (long)(m0+m)*lda + k0 + k4*4);
            }
            #pragma unroll
            for (int u=0;u<BU;u++){
                int f = tid + u*256; int k4 = f&7, n = f>>3;
                int gn = n0 + n;
                float4 v = {0.f,0.f,0.f,0.f};
                if (gn < N) v = *(const float4*)(Bw + (long)gn*ldb + k0 + k4*4);
                rb[u] = v;
            }
        }
        #pragma unroll
        for (int ks=0; ks<2; ks++){
            int kc2 = ks*8;
            uint32_t af[2][4], bfr[NF][2];
            #pragma unroll
            for (int mf=0; mf<2; mf++){
                int r = warp_m*32 + mf*16 + g;
                af[mf][0] = S.g.As[buf][r][kc2+t];
                af[mf][1] = S.g.As[buf][r+8][kc2+t];
                af[mf][2] = S.g.As[buf][r][kc2+t+4];
                af[mf][3] = S.g.As[buf][r+8][kc2+t+4];
            }
            #pragma unroll
            for (int nf=0; nf<NF; nf++){
                int cn = warp_n*(BN/2) + nf*8 + g;
                bfr[nf][0] = S.g.Bs[buf][cn][kc2+t];
                bfr[nf][1] = S.g.Bs[buf][cn][kc2+t+4];
            }
            #pragma unroll
            for (int mf=0; mf<2; mf++)
                #pragma unroll
                for (int nf=0; nf<NF; nf++)
                    mma_bf16(acc[mf][nf], af[mf], bfr[nf]);
        }
        if (kt+1 < nk){
            int nb = buf^1;
            #pragma unroll
            for (int u=0;u<4;u++){
                int f = tid + u*256; int k4 = f&7, m = f>>3;
                S.g.As[nb][m][k4*2]   = pk(ra[u].x, ra[u].y);
                S.g.As[nb][m][k4*2+1] = pk(ra[u].z, ra[u].w);
            }
            #pragma unroll
            for (int u=0;u<BU;u++){
                int f = tid + u*256; int k4 = f&7, n = f>>3;
                S.g.Bs[nb][n][k4*2]   = pk(rb[u].x, rb[u].y);
                S.g.Bs[nb][n][k4*2+1] = pk(rb[u].z, rb[u].w);
            }
            __syncthreads();
            buf = nb;
        }
    }

    if (MODE == 2){
        __syncthreads();
        float sum[2][2] = {}, sq[2][2] = {};
        #pragma unroll
        for (int mf=0;mf<2;mf++){
            int rl0 = warp_m*32 + mf*16 + g;
            long gr0 = m0 + rl0, gr1 = gr0 + 8;
            #pragma unroll
            for (int nf=0;nf<NF;nf++){
                int cn = warp_n*(BN/2) + nf*8 + 2*t;
                float b0 = bias[cn], b1 = bias[cn+1];
                float v0 = acc[mf][nf][0] + b0 + zres[gr0*CC + cn];
                float v1 = acc[mf][nf][1] + b1 + zres[gr0*CC + cn+1];
                float v2 = acc[mf][nf][2] + b0 + zres[gr1*CC + cn];
                float v3 = acc[mf][nf][3] + b1 + zres[gr1*CC + cn+1];
                acc[mf][nf][0]=v0; acc[mf][nf][1]=v1; acc[mf][nf][2]=v2; acc[mf][nf][3]=v3;
                sum[mf][0] += v0+v1;   sum[mf][1] += v2+v3;
                sq[mf][0]  += v0*v0+v1*v1; sq[mf][1] += v2*v2+v3*v3;
            }
        }
        int cid = warp_n*4 + t;
        #pragma unroll
        for (int mf=0;mf<2;mf++){
            int rl0 = warp_m*32 + mf*16 + g;
            S.red[rl0][cid]     = sum[mf][0];  S.red[rl0][8+cid]   = sq[mf][0];
            S.red[rl0+8][cid]   = sum[mf][1];  S.red[rl0+8][8+cid] = sq[mf][1];
        }
        __syncthreads();
        #pragma unroll
        for (int mf=0;mf<2;mf++){
            #pragma unroll
            for (int half=0; half<2; half++){
                int rl = warp_m*32 + mf*16 + g + half*8;
                float s8 = 0.f, q8 = 0.f;
                #pragma unroll
                for (int j=0;j<8;j++){ s8 += S.red[rl][j]; q8 += S.red[rl][8+j]; }
                float mu = s8 * (1.f/128.f);
                float var = q8 * (1.f/128.f) - mu*mu;
                float rsig = rsqrtf(var + 1e-5f);
                long gm = m0 + rl;
                int k = (int)(gm & 511); long bt = gm >> 9;
                int bidx = (int)(bt >> 3);
                int n = idxp[bidx*KK + k];
                float* ob = C + (bt*CC)*NSP + n;
                #pragma unroll
                for (int nf=0;nf<NF;nf++){
                    int cn = warp_n*(BN/2) + nf*8 + 2*t;
                    float vA = acc[mf][nf][half*2];
                    float vB = acc[mf][nf][half*2+1];
                    ob[(long)cn*NSP]     += (vA-mu)*rsig*lnw[cn]   + lnb[cn];
                    ob[(long)(cn+1)*NSP] += (vB-mu)*rsig*lnw[cn+1] + lnb[cn+1];
                }
            }
        }
        return;
    }

    #pragma unroll
    for (int mf=0; mf<2; mf++){
        int r0 = m0 + warp_m*32 + mf*16 + g;
        int r1 = r0 + 8;
        long gr0 = r0, gr1 = r1;
        if (MODE==1){
            int b = r0 >> 12; int k = (r0 >> 3) & 511; int tt = r0 & 7;
            gr0 = ((long)(b*8 + tt) << 9) + k;
            b = r1 >> 12; k = (r1 >> 3) & 511; tt = r1 & 7;
            gr1 = ((long)(b*8 + tt) << 9) + k;
        }
        #pragma unroll
        for (int nf=0; nf<NF; nf++){
            int cn = n0 + warp_n*(BN/2) + nf*8 + 2*t;
            if (cn >= N) continue;
            float b0 = bias ? bias[cn]   : 0.f;
            float b1 = bias ? bias[cn+1] : 0.f;
            C[gr0*ldc + cn]   = acc[mf][nf][0] + b0;
            C[gr0*ldc + cn+1] = acc[mf][nf][1] + b1;
            C[gr1*ldc + cn]   = acc[mf][nf][2] + b0;
            C[gr1*ldc + cn+1] = acc[mf][nf][3] + b1;
        }
    }
}

// ---------------- bf16 flash attention, q-tile 128 ----------------
// grid (4, 256 bt*head), 256 thr, dynamic smem 56320 B.
__global__ __launch_bounds__(256)
void k_flash2(const float* __restrict__ qkv, float* __restrict__ o)
{
    extern __shared__ char smraw[];
    uint32_t (*Qs)[20] = (uint32_t(*)[20])(smraw);            // 128 x 20
    uint32_t (*Ks)[20] = (uint32_t(*)[20])(smraw + 10240);    // 64 x 20
    uint32_t (*Vt)[36] = (uint32_t(*)[36])(smraw + 15360);    // 32 x 36
    uint32_t (*Ps)[68] = (uint32_t(*)[68])(smraw + 19968);    // 128 x 68 (Pb alias words 0..31)
    float* m_s = (float*)(smraw + 54784);
    float* l_s = (float*)(smraw + 55296);
    float* r_s = (float*)(smraw + 55808);

    int bh = blockIdx.y;
    int bt = bh >> 2, h = bh & 3;
    const float* base = qkv + (long)bt*KK*(3*CC) + h*DH;
    int q0 = blockIdx.x * 128;

    int tid = threadIdx.x;
    int wid = tid >> 5, lane = tid & 31;
    int g = lane >> 2, t = lane & 3;
    const float scl = 0.17677669529663687f;

    // Q load (scaled)
    for (int i = tid; i < 128*16; i += 256){
        int k2 = i & 15, q = i >> 4;
        float2 v = *(const float2*)(base + (long)(q0+q)*(3*CC) + 2*k2);
        Qs[q][k2] = pk(v.x*scl, v.y*scl);
    }
    if (tid < 128){ m_s[tid] = -1e30f; l_s[tid] = 0.f; }

    int wm = wid & 3, wn = wid >> 2;   // QK: 4 m-bands x 2 key-halves
    int pm = wid;                      // PV: 8 m-bands of 16 rows

    float oacc[4][4] = {};             // 16 rows x 32 d per warp
    int qrow = tid >> 1, tr = tid & 1; // softmax: 2 thr/row, 32 cols each

    for (int kc = 0; kc < 8; kc++){
        int k0 = kc * 64;
        __syncthreads();
        for (int i = tid; i < 64*16; i += 256){
            int k2 = i & 15, k = i >> 4;
            float2 v = *(const float2*)(base + (long)(k0+k)*(3*CC) + CC + 2*k2);
            Ks[k][k2] = pk(v.x, v.y);
        }
        for (int i = tid; i < 32*32; i += 256){
            int d = i & 31, j = i >> 5;
            float v0 = base[(long)(k0+2*j)  *(3*CC) + 2*CC + d];
            float v1 = base[(long)(k0+2*j+1)*(3*CC) + 2*CC + d];
            Vt[d][j] = pk(v0, v1);
        }
        __syncthreads();

        // ---- S = Q K^T : warp tile 32 rows x 32 keys ----
        float sacc[2][4][4] = {};
        #pragma unroll
        for (int ks=0; ks<2; ks++){
            int kc2 = ks*8;
            uint32_t af[2][4], bf[4][2];
            #pragma unroll
            for (int mf=0; mf<2; mf++){
                int r = wm*32 + mf*16 + g;
                af[mf][0] = Qs[r][kc2+t];
                af[mf][1] = Qs[r+8][kc2+t];
                af[mf][2] = Qs[r][kc2+t+4];
                af[mf][3] = Qs[r+8][kc2+t+4];
            }
            #pragma unroll
            for (int nf=0; nf<4; nf++){
                int cn = wn*32 + nf*8 + g;
                bf[nf][0] = Ks[cn][kc2+t];
                bf[nf][1] = Ks[cn][kc2+t+4];
            }
            #pragma unroll
            for (int mf=0; mf<2; mf++)
                #pragma unroll
                for (int nf=0; nf<4; nf++)
                    mma_bf16(sacc[mf][nf], af[mf], bf[nf]);
        }
        #pragma unroll
        for (int mf=0; mf<2; mf++){
            int r0 = wm*32 + mf*16 + g;
            #pragma unroll
            for (int nf=0; nf<4; nf++){
                int cn = wn*32 + nf*8 + 2*t;
                Ps[r0][cn]     = __float_as_uint(sacc[mf][nf][0]);
                Ps[r0][cn+1]   = __float_as_uint(sacc[mf][nf][1]);
                Ps[r0+8][cn]   = __float_as_uint(sacc[mf][nf][2]);
                Ps[r0+8][cn+1] = __float_as_uint(sacc[mf][nf][3]);
            }
        }
        __syncthreads();

        // ---- online softmax: 2 thr/row, 32 cols; pack P into Ps words 0..31 ----
        {
            float v[32]; float mx = -1e30f;
            #pragma unroll
            for (int j=0;j<32;j++){
                v[j] = __uint_as_float(Ps[qrow][tr*32 + j]);
                mx = fmaxf(mx, v[j]);
            }
            mx = fmaxf(mx, __shfl_xor_sync(0xffffffffu, mx, 1));
            float mold = m_s[qrow];
            float mnew = fmaxf(mold, mx);
            float sum = 0.f;
            #pragma unroll
            for (int j=0;j<32;j++){
                v[j] = __expf(v[j] - mnew);
                sum += v[j];
            }
            sum += __shfl_xor_sync(0xffffffffu, sum, 1);
            __syncwarp();   // all reads of this row's S complete before alias write
            #pragma unroll
            for (int j=0;j<16;j++)
                Ps[qrow][tr*16 + j] = pk(v[2*j], v[2*j+1]);
            if (tr == 0){
                float r = __expf(mold - mnew);
                l_s[qrow] = l_s[qrow]*r + sum;
                m_s[qrow] = mnew;
                r_s[qrow] = r;
            }
        }
        __syncthreads();

        // ---- O = O*r + P V : warp tile 16 rows x 32 d ----
        {
            float rr0 = r_s[pm*16 + g];
            float rr1 = r_s[pm*16 + g + 8];
            #pragma unroll
            for (int nf=0; nf<4; nf++){
                oacc[nf][0] *= rr0; oacc[nf][1] *= rr0;
                oacc[nf][2] *= rr1; oacc[nf][3] *= rr1;
            }
            #pragma unroll
            for (int ks=0; ks<4; ks++){
                int kc2 = ks*8;
                uint32_t af[4], bf[4][2];
                int r = pm*16 + g;
                af[0] = Ps[r][kc2+t];
                af[1] = Ps[r+8][kc2+t];
                af[2] = Ps[r][kc2+t+4];
                af[3] = Ps[r+8][kc2+t+4];
                #pragma unroll
                for (int nf=0; nf<4; nf++){
                    int cn = nf*8 + g;
                    bf[nf][0] = Vt[cn][kc2+t];
                    bf[nf][1] = Vt[cn][kc2+t+4];
                }
                #pragma unroll
                for (int nf=0; nf<4; nf++)
                    mma_bf16(oacc[nf], af, bf[nf]);
            }
        }
    }
    __syncthreads();
    {
        float inv0 = 1.f / l_s[pm*16 + g];
        float inv1 = 1.f / l_s[pm*16 + g + 8];
        int qA = q0 + pm*16 + g;
        int qB = qA + 8;
        #pragma unroll
        for (int nf=0; nf<4; nf++){
            int d = nf*8 + 2*t;
            long rowA = ((long)bt*KK + qA)*CC + h*DH + d;
            long rowB = ((long)bt*KK + qB)*CC + h*DH + d;
            o[rowA]   = oacc[nf][0]*inv0;
            o[rowA+1] = oacc[nf][1]*inv0;
            o[rowB]   = oacc[nf][2]*inv1;
            o[rowB+1] = oacc[nf][3]*inv1;
        }
    }
}

// ---------------- stage kernels ----------------
__global__ void k_copy(const float4* __restrict__ in, float4* __restrict__ out, int n4){
    int i = blockIdx.x*blockDim.x + threadIdx.x;
    if (i < n4) out[i] = in[i];
}

__global__ void k_mean(const float* __restrict__ x, float* __restrict__ xm){
    int i = blockIdx.x*blockDim.x + threadIdx.x;
    if (i >= BB*CC*NSP) return;
    int b = i >> 17; int rem = i & 131071;
    float s = 0.f;
    #pragma unroll
    for (int t=0;t<TT;t++) s += x[((long)b*TT+t)*131072 + rem];
    xm[i] = s * 0.125f;
}

__global__ void k_conv3(const float* __restrict__ xm, const float* __restrict__ w,
                        const float* __restrict__ bias, float* __restrict__ h1){
    __shared__ float pl[34*34];
    int bo = blockIdx.x; int b = bo >> 5; int oc = bo & 31;
    int tid = threadIdx.x;
    int h = tid >> 5, wq = tid & 31;
    float acc = 0.f;
    for (int ic=0; ic<CC; ic++){
        for (int i=tid; i<34*34; i+=1024){
            int hh = i/34 - 1, ww = i%34 - 1;
            pl[i] = (hh>=0 && hh<32 && ww>=0 && ww<32) ?
                    xm[((long)b*CC+ic)*NSP + hh*32+ww] : 0.f;
        }
        __syncthreads();
        const float* wp = w + ((long)oc*CC+ic)*9;
        #pragma unroll
        for (int kh=0;kh<3;kh++)
            #pragma unroll
            for (int kw=0;kw<3;kw++)
                acc += pl[(h+kh)*34 + (wq+kw)] * wp[kh*3+kw];
        __syncthreads();
    }
    acc += bias[oc];
    h1[(long)bo*NSP + tid] = (acc >= 0.f) ? acc : 0.01f*acc;
}

__global__ void k_scoretopk(const float* __restrict__ h1, const float* __restrict__ w2,
                            const float* __restrict__ b2, int* __restrict__ idx,
                            float* __restrict__ scl){
    __shared__ float s[1024];
    __shared__ unsigned char keep[1024];
    int b = blockIdx.x, n = threadIdx.x;
    float a = 0.f;
    #pragma unroll
    for (int oc=0;oc<32;oc++) a += h1[((long)b*32+oc)*NSP + n] * w2[oc];
    float v = sigm(a + b2[0]);
    s[n] = v;
    __syncthreads();
    int cnt = 0;
    for (int m=0;m<1024;m++){ float u = s[m]; cnt += (u>v) || (u==v && m<n); }
    keep[n] = (cnt < KK) ? 1 : 0;
    __syncthreads();
    if (keep[n]){
        int pos = 0;
        for (int m=0;m<n;m++) pos += keep[m];
        idx[b*KK + pos] = n;
        scl[b*KK + pos] = v / (v + 1e-6f);
    }
}

// tile-based gather + STE scale + RMSNorm  (k on lane index -> ~2 lines/warp)
__global__ __launch_bounds__(256)
void k_gather2(const float* __restrict__ x, const int* __restrict__ idx,
               const float* __restrict__ scl, const float* __restrict__ nw,
               float* __restrict__ z0){
    __shared__ float tile[128][33];
    __shared__ float red[32][9];
    __shared__ int   nsh[32];
    __shared__ float ssh[32];
    __shared__ float rst[32];
    int bt = blockIdx.x;          // b*TT + t
    int b = bt >> 3, t = bt & 7;
    int kc = blockIdx.y;          // 16 chunks of 32 k
    int tid = threadIdx.x;
    if (tid < 32){
        nsh[tid] = idx[b*KK + kc*32 + tid];
        ssh[tid] = scl[b*KK + kc*32 + tid];
    }
    __syncthreads();
    const float* xb = x + ((long)bt*CC)*NSP;
    #pragma unroll
    for (int u=0; u<16; u++){
        int e = tid + u*256;
        int k = e & 31, c = e >> 5;
        tile[c][k] = xb[(long)c*NSP + nsh[k]] * ssh[k];
    }
    __syncthreads();
    {
        int k = tid & 31, part = tid >> 5;
        float s = 0.f;
        #pragma unroll
        for (int j=0;j<16;j++){ float v = tile[part*16+j][k]; s += v*v; }
        red[k][part] = s;
    }
    __syncthreads();
    if (tid < 32){
        float s = 0.f;
        #pragma unroll
        for (int p=0;p<8;p++) s += red[tid][p];
        rst[tid] = rsqrtf(s*(1.f/128.f) + 1e-5f);
    }
    __syncthreads();
    #pragma unroll
    for (int u=0; u<16; u++){
        int e = tid + u*256;
        int c = e & 127, k = e >> 7;
        long row = (((long)b*KK + kc*32 + k)*TT + t);
        z0[row*CC + c] = tile[c][k] * rst[k] * nw[c];
    }
}

__global__ void k_conv1d(const float* __restrict__ xz, const float* __restrict__ w,
                         const float* __restrict__ bias, float* __restrict__ xc){
    int s = blockIdx.x; int ch = threadIdx.x;
    float in[TT];
    #pragma unroll
    for (int t=0;t<TT;t++) in[t] = xz[(((long)s*TT + t)*(2*DI)) + ch];
    float w0=w[ch*4+0], w1=w[ch*4+1], w2=w[ch*4+2], w3=w[ch*4+3];
    float bb = bias[ch];
    #pragma unroll
    for (int t=0;t<TT;t++){
        float a = bb + in[t]*w3;
        if (t>=1) a += in[t-1]*w2;
        if (t>=2) a += in[t-2]*w1;
        if (t>=3) a += in[t-3]*w0;
        xc[((long)s*TT + t)*DI + ch] = siluf(a);
    }
}

__global__ void k_scan2(const float* __restrict__ xc, const float* __restrict__ xdbl,
                        const float* __restrict__ dtw, const float* __restrict__ dtbias,
                        const float* __restrict__ Alog, const float* __restrict__ Dp,
                        const float* __restrict__ xz, float* __restrict__ yg){
    __shared__ float xd[TT][40];
    int s = blockIdx.x; int ch = threadIdx.x;
    for (int i = ch; i < TT*40; i += 256)
        xd[i/40][i%40] = xdbl[(long)s*TT*40 + i];
    float w8[DTR];
    #pragma unroll
    for (int r=0;r<DTR;r++) w8[r] = dtw[ch*DTR + r];
    float db = dtbias[ch];
    float Arow[DS];
    #pragma unroll
    for (int d=0;d<DS;d++) Arow[d] = -__expf(Alog[ch*DS + d]);
    float A0 = Arow[0];
    bool geom = true;
    #pragma unroll
    for (int d=1;d<DS;d++)
        geom = geom && (fabsf(Arow[d] - A0*(float)(d+1)) <= 1e-5f*fabsf(A0*(float)(d+1)) + 1e-12f);
    float Dv = Dp[ch];
    __syncthreads();
    float h[DS];
    #pragma unroll
    for (int d=0;d<DS;d++) h[d] = 0.f;
    #pragma unroll
    for (int t=0;t<TT;t++){
        long row = (long)s*TT + t;
        float dtr = db;
        #pragma unroll
        for (int r=0;r<DTR;r++) dtr += xd[t][r]*w8[r];
        float dt = softplusf(dtr);
        float u  = xc[row*DI + ch];
        float du = dt*u;
        float y = 0.f;
        if (geom){
            float e1 = __expf(dt*A0);
            float ed = 1.f;
            #pragma unroll
            for (int d=0;d<DS;d++){
                ed *= e1;
                float Bv = xd[t][DTR + d];
                float Cv = xd[t][DTR + DS + d];
                h[d] = h[d]*ed + du*Bv;
                y += h[d]*Cv;
            }
        } else {
            #pragma unroll
            for (int d=0;d<DS;d++){
                float Bv = xd[t][DTR + d];
                float Cv = xd[t][DTR + DS + d];
                h[d] = h[d]*__expf(dt*Arow[d]) + du*Bv;
                y += h[d]*Cv;
            }
        }
        float zg = xz[row*(2*DI) + DI + ch];
        yg[row*DI + ch] = (y + u*Dv) * siluf(zg);
    }
}

// ---------------- host launch ----------------
static float* symf(const void* s){ void* p = nullptr; cudaGetSymbolAddress(&p, s); return (float*)p; }

extern "C" void kernel_launch(void* const* d_in, const int* in_sizes, int n_in,
                              void* d_out, int out_size)
{
    const float* x_in      = (const float*)d_in[0];
    const float* norm1_w   = (const float*)d_in[1];
    const float* in_proj_w = (const float*)d_in[2];
    const float* conv1d_w  = (const float*)d_in[3];
    const float* conv1d_b  = (const float*)d_in[4];
    const float* x_proj_w  = (const float*)d_in[5];
    const float* dt_proj_w = (const float*)d_in[6];
    const float* dt_proj_b = (const float*)d_in[7];
    const float* A_log     = (const float*)d_in[8];
    const float* Dp        = (const float*)d_in[9];
    const float* out_proj_w= (const float*)d_in[10];
    const float* r1_w      = (const float*)d_in[11];
    const float* r1_b      = (const float*)d_in[12];
    const float* r2_w      = (const float*)d_in[13];
    const float* r2_b      = (const float*)d_in[14];
    const float* attn_in_w = (const float*)d_in[15];
    const float* attn_in_b = (const float*)d_in[16];
    const float* attn_out_w= (const float*)d_in[17];
    const float* attn_out_b= (const float*)d_in[18];
    const float* ln_w      = (const float*)d_in[19];
    const float* ln_b      = (const float*)d_in[20];
    float* out = (float*)d_out;

    float *xm = symf(g_xm), *h1 = symf(g_h1);
    float *scl = symf(g_scl), *z0 = symf(g_z0), *xz = symf(g_xz);
    float *xc = symf(g_xc), *xdbl = symf(g_xdbl);
    float *yg = symf(g_yg), *zsb = symf(g_zs);
    float *qkv = symf(g_qkv), *orp = symf(g_orp);
    int* idx = (int*)symf(g_idx);

    static int smem_set = 0;
    if (!smem_set){
        cudaFuncSetAttribute(k_flash2, cudaFuncAttributeMaxDynamicSharedMemorySize, 57344);
        smem_set = 1;
    }

    // 1) router
    k_mean<<<(BB*CC*NSP+255)/256, 256>>>(x_in, xm);
    k_conv3<<<BB*32, 1024>>>(xm, r1_w, r1_b, h1);
    k_scoretopk<<<BB, 1024>>>(h1, r2_w, r2_b, idx, scl);
    // 2) gather + rmsnorm   (profiled launch slot)
    k_gather2<<<dim3(BB*TT, 16), 256>>>(x_in, idx, scl, norm1_w, z0);
    // 3) mamba
    gemm_bf<128,0><<<dim3(4,256),256>>>(z0, in_proj_w, nullptr, xz,
        ROWS, 2*DI, CC, CC, CC, 2*DI, nullptr, nullptr, nullptr, nullptr);
    k_conv1d<<<ROWS/TT, DI>>>(xz, conv1d_w, conv1d_b, xc);
    gemm_bf<64,0><<<dim3(1,256),256>>>(xc, x_proj_w, nullptr, xdbl,
        ROWS, 40, DI, DI, DI, 40, nullptr, nullptr, nullptr, nullptr);
    k_scan2<<<ROWS/TT, DI>>>(xc, xdbl, dt_proj_w, dt_proj_b, A_log, Dp, xz, yg);
    gemm_bf<128,1><<<dim3(1,256),256>>>(yg, out_proj_w, nullptr, zsb,
        ROWS, CC, DI, DI, DI, CC, nullptr, nullptr, nullptr, nullptr);
    // 4) attention
    gemm_bf<128,0><<<dim3(3,256),256>>>(zsb, attn_in_w, attn_in_b, qkv,
        ROWS, 3*CC, CC, CC, CC, 3*CC, nullptr, nullptr, nullptr, nullptr);
    k_flash2<<<dim3(4, NBATCH), 256, 56320>>>(qkv, orp);
    // 5) out = x_in, then attn_out + LayerNorm + scatter-add fused epilogue
    {
        int n4 = (BB*TT*CC*NSP)/4;
        k_copy<<<(n4+255)/256, 256>>>((const float4*)x_in, (float4*)out, n4);
    }
    gemm_bf<128,2><<<dim3(1,256),256>>>(orp, attn_out_w, attn_out_b, out,
        ROWS, CC, CC, CC, CC, NSP, zsb, ln_w, ln_b, idx);
}

// round 13
// speedup vs baseline: 2.9994x; 1.0058x over previous
#include <cuda_runtime.h>
#include <cuda_bf16.h>
#include <cstdint>

// ---------------- problem constants ----------------
#define BB 8
#define TT 8
#define CC 128
#define NSP 1024
#define KK 512
#define DI 256
#define DS 16
#define DTR 8
#define NH 4
#define DH 32
#define ROWS 32768
#define NBATCH 256

// ---------------- device scratch ----------------
__device__ float g_xm  [BB*CC*NSP];
__device__ float g_h1  [BB*32*NSP];
__device__ int   g_idx [BB*KK];
__device__ float g_scl [BB*KK];
__device__ float g_z0  [(size_t)ROWS*CC];
__device__ float g_xz  [(size_t)ROWS*2*DI];
__device__ float g_xc  [(size_t)ROWS*DI];
__device__ float g_xdbl[(size_t)ROWS*40];
__device__ float g_yg  [(size_t)ROWS*DI];
__device__ float g_zs  [(size_t)ROWS*CC];
__device__ float g_qkv [(size_t)ROWS*3*CC];
__device__ float g_orp [(size_t)ROWS*CC];

// ---------------- helpers ----------------
__device__ __forceinline__ float sigm(float x){ return 1.f/(1.f+__expf(-x)); }
__device__ __forceinline__ float siluf(float x){ return x*sigm(x); }
__device__ __forceinline__ float softplusf(float x){ return (x>20.f)?x:log1pf(__expf(x)); }

__device__ __forceinline__ uint32_t pk(float lo, float hi){
    __nv_bfloat162 v = __floats2bfloat162_rn(lo, hi);
    return *reinterpret_cast<uint32_t*>(&v);
}

__device__ __forceinline__ void mma_bf16(float* c, const uint32_t* a, const uint32_t* b){
    asm volatile(
        "mma.sync.aligned.m16n8k16.row.col.f32.bf16.bf16.f32 "
        "{%0,%1,%2,%3}, {%4,%5,%6,%7}, {%8,%9}, {%0,%1,%2,%3};"
        : "+f"(c[0]), "+f"(c[1]), "+f"(c[2]), "+f"(c[3])
        : "r"(a[0]), "r"(a[1]), "r"(a[2]), "r"(a[3]), "r"(b[0]), "r"(b[1]));
}

// ---------------- bf16 tensor-core TN GEMM ----------------
// MODE 0: plain. MODE 1: (b,k,t)->(b,t,k) row permute on store.
// MODE 2: bias + residual + LayerNorm + k-coalesced scatter-add into output.
template<int BN, int MODE>
__global__ __launch_bounds__(256)
void gemm_bf(const float* __restrict__ A, const float* __restrict__ Bw,
             const float* __restrict__ bias, float* __restrict__ C,
             int M, int N, int Kd, int lda, int ldb, int ldc,
             const float* __restrict__ zres, const float* __restrict__ lnw,
             const float* __restrict__ lnb, const int* __restrict__ idxp)
{
    constexpr int NF = BN/16;
    constexpr int BU = BN/32;
    __shared__ union SU {
        struct { uint32_t As[2][128][20]; uint32_t Bs[2][BN][20]; } g;
        struct { float red[128][17]; float tile[128][33]; int nsh[32]; } e;
    } S;

    int m0 = blockIdx.y*128, n0 = blockIdx.x*BN;
    int tid = threadIdx.x;
    int wid = tid >> 5, lane = tid & 31;
    int warp_m = wid >> 1, warp_n = wid & 1;
    int g = lane >> 2, t = lane & 3;

    float acc[2][NF][4] = {};
    float4 ra[4], rb[BU];
    int nk = Kd >> 5;

    #pragma unroll
    for (int u=0;u<4;u++){
        int f = tid + u*256; int k4 = f&7, m = f>>3;
        ra[u] = *(const float4*)(A + (long)(m0+m)*lda + k4*4);
    }
    #pragma unroll
    for (int u=0;u<BU;u++){
        int f = tid + u*256; int k4 = f&7, n = f>>3;
        int gn = n0 + n;
        float4 v = {0.f,0.f,0.f,0.f};
        if (gn < N) v = *(const float4*)(Bw + (long)gn*ldb + k4*4);
        rb[u] = v;
    }
    #pragma unroll
    for (int u=0;u<4;u++){
        int f = tid + u*256; int k4 = f&7, m = f>>3;
        S.g.As[0][m][k4*2]   = pk(ra[u].x, ra[u].y);
        S.g.As[0][m][k4*2+1] = pk(ra[u].z, ra[u].w);
    }
    #pragma unroll
    for (int u=0;u<BU;u++){
        int f = tid + u*256; int k4 = f&7, n = f>>3;
        S.g.Bs[0][n][k4*2]   = pk(rb[u].x, rb[u].y);
        S.g.Bs[0][n][k4*2+1] = pk(rb[u].z, rb[u].w);
    }
    __syncthreads();

    int buf = 0;
    for (int kt = 0; kt < nk; kt++){
        if (kt+1 < nk){
            int k0 = (kt+1)*32;
            #pragma unroll
            for (int u=0;u<4;u++){
                int f = tid + u*256; int k4 = f&7, m = f>>3;
                ra[u] = *(const float4*)(A + (long)(m0+m)*lda + k0 + k4*4);
            }
            #pragma unroll
            for (int u=0;u<BU;u++){
                int f = tid + u*256; int k4 = f&7, n = f>>3;
                int gn = n0 + n;
                float4 v = {0.f,0.f,0.f,0.f};
                if (gn < N) v = *(const float4*)(Bw + (long)gn*ldb + k0 + k4*4);
                rb[u] = v;
            }
        }
        #pragma unroll
        for (int ks=0; ks<2; ks++){
            int kc2 = ks*8;
            uint32_t af[2][4], bfr[NF][2];
            #pragma unroll
            for (int mf=0; mf<2; mf++){
                int r = warp_m*32 + mf*16 + g;
                af[mf][0] = S.g.As[buf][r][kc2+t];
                af[mf][1] = S.g.As[buf][r+8][kc2+t];
                af[mf][2] = S.g.As[buf][r][kc2+t+4];
                af[mf][3] = S.g.As[buf][r+8][kc2+t+4];
            }
            #pragma unroll
            for (int nf=0; nf<NF; nf++){
                int cn = warp_n*(BN/2) + nf*8 + g;
                bfr[nf][0] = S.g.Bs[buf][cn][kc2+t];
                bfr[nf][1] = S.g.Bs[buf][cn][kc2+t+4];
            }
            #pragma unroll
            for (int mf=0; mf<2; mf++)
                #pragma unroll
                for (int nf=0; nf<NF; nf++)
                    mma_bf16(acc[mf][nf], af[mf], bfr[nf]);
        }
        if (kt+1 < nk){
            int nb = buf^1;
            #pragma unroll
            for (int u=0;u<4;u++){
                int f = tid + u*256; int k4 = f&7, m = f>>3;
                S.g.As[nb][m][k4*2]   = pk(ra[u].x, ra[u].y);
                S.g.As[nb][m][k4*2+1] = pk(ra[u].z, ra[u].w);
            }
            #pragma unroll
            for (int u=0;u<BU;u++){
                int f = tid + u*256; int k4 = f&7, n = f>>3;
                S.g.Bs[nb][n][k4*2]   = pk(rb[u].x, rb[u].y);
                S.g.Bs[nb][n][k4*2+1] = pk(rb[u].z, rb[u].w);
            }
            __syncthreads();
            buf = nb;
        }
    }

    if (MODE == 2){
        __syncthreads();   // As/Bs dead; reuse union for red/tile/nsh
        // bias + residual, accumulate row stats
        float sum[2][2] = {}, sq[2][2] = {};
        #pragma unroll
        for (int mf=0;mf<2;mf++){
            int rl0 = warp_m*32 + mf*16 + g;
            long gr0 = m0 + rl0, gr1 = gr0 + 8;
            #pragma unroll
            for (int nf=0;nf<NF;nf++){
                int cn = warp_n*(BN/2) + nf*8 + 2*t;
                float b0 = bias[cn], b1 = bias[cn+1];
                float v0 = acc[mf][nf][0] + b0 + zres[gr0*CC + cn];
                float v1 = acc[mf][nf][1] + b1 + zres[gr0*CC + cn+1];
                float v2 = acc[mf][nf][2] + b0 + zres[gr1*CC + cn];
                float v3 = acc[mf][nf][3] + b1 + zres[gr1*CC + cn+1];
                acc[mf][nf][0]=v0; acc[mf][nf][1]=v1; acc[mf][nf][2]=v2; acc[mf][nf][3]=v3;
                sum[mf][0] += v0+v1;   sum[mf][1] += v2+v3;
                sq[mf][0]  += v0*v0+v1*v1; sq[mf][1] += v2*v2+v3*v3;
            }
        }
        int cid = warp_n*4 + t;
        #pragma unroll
        for (int mf=0;mf<2;mf++){
            int rl0 = warp_m*32 + mf*16 + g;
            S.e.red[rl0][cid]     = sum[mf][0];  S.e.red[rl0][8+cid]   = sq[mf][0];
            S.e.red[rl0+8][cid]   = sum[mf][1];  S.e.red[rl0+8][8+cid] = sq[mf][1];
        }
        __syncthreads();
        // per-thread stats for its own rows
        float mu_[2][2], rs_[2][2];
        #pragma unroll
        for (int mf=0;mf<2;mf++)
            #pragma unroll
            for (int half=0; half<2; half++){
                int rl = warp_m*32 + mf*16 + g + half*8;
                float s8 = 0.f, q8 = 0.f;
                #pragma unroll
                for (int j=0;j<8;j++){ s8 += S.e.red[rl][j]; q8 += S.e.red[rl][8+j]; }
                float mu = s8 * (1.f/128.f);
                float var = q8 * (1.f/128.f) - mu*mu;
                mu_[mf][half] = mu;
                rs_[mf][half] = rsqrtf(var + 1e-5f);
            }
        long bt = m0 >> 9;
        int bidx = (int)(bt >> 3);
        int kbase = m0 & 511;
        float* Cb0 = C + (bt*CC)*NSP;
        // 4 chunks of 32 k; stage LN'd values, write with k on lane (coalesced)
        #pragma unroll
        for (int chunk=0; chunk<4; chunk++){
            __syncthreads();
            if (tid < 32) S.e.nsh[tid] = idxp[bidx*KK + kbase + chunk*32 + tid];
            if (warp_m == chunk){
                #pragma unroll
                for (int mf=0; mf<2; mf++)
                    #pragma unroll
                    for (int half=0; half<2; half++){
                        int kl = mf*16 + g + half*8;
                        float mu = mu_[mf][half], rs = rs_[mf][half];
                        #pragma unroll
                        for (int nf=0; nf<NF; nf++){
                            int cn = warp_n*(BN/2) + nf*8 + 2*t;
                            S.e.tile[cn][kl]   = (acc[mf][nf][half*2]   - mu)*rs*lnw[cn]   + lnb[cn];
                            S.e.tile[cn+1][kl] = (acc[mf][nf][half*2+1] - mu)*rs*lnw[cn+1] + lnb[cn+1];
                        }
                    }
            }
            __syncthreads();
            #pragma unroll
            for (int u=0; u<16; u++){
                int e = tid + u*256;
                int k = e & 31, c = e >> 5;
                Cb0[(long)c*NSP + S.e.nsh[k]] += S.e.tile[c][k];
            }
        }
        return;
    }

    #pragma unroll
    for (int mf=0; mf<2; mf++){
        int r0 = m0 + warp_m*32 + mf*16 + g;
        int r1 = r0 + 8;
        long gr0 = r0, gr1 = r1;
        if (MODE==1){
            int b = r0 >> 12; int k = (r0 >> 3) & 511; int tt = r0 & 7;
            gr0 = ((long)(b*8 + tt) << 9) + k;
            b = r1 >> 12; k = (r1 >> 3) & 511; tt = r1 & 7;
            gr1 = ((long)(b*8 + tt) << 9) + k;
        }
        #pragma unroll
        for (int nf=0; nf<NF; nf++){
            int cn = n0 + warp_n*(BN/2) + nf*8 + 2*t;
            if (cn >= N) continue;
            float b0 = bias ? bias[cn]   : 0.f;
            float b1 = bias ? bias[cn+1] : 0.f;
            C[gr0*ldc + cn]   = acc[mf][nf][0] + b0;
            C[gr0*ldc + cn+1] = acc[mf][nf][1] + b1;
            C[gr1*ldc + cn]   = acc[mf][nf][2] + b0;
            C[gr1*ldc + cn+1] = acc[mf][nf][3] + b1;
        }
    }
}

// ---------------- bf16 flash attention, q-tile 128 ----------------
__global__ __launch_bounds__(256)
void k_flash2(const float* __restrict__ qkv, float* __restrict__ o)
{
    extern __shared__ char smraw[];
    uint32_t (*Qs)[20] = (uint32_t(*)[20])(smraw);
    uint32_t (*Ks)[20] = (uint32_t(*)[20])(smraw + 10240);
    uint32_t (*Vt)[36] = (uint32_t(*)[36])(smraw + 15360);
    uint32_t (*Ps)[68] = (uint32_t(*)[68])(smraw + 19968);
    float* m_s = (float*)(smraw + 54784);
    float* l_s = (float*)(smraw + 55296);
    float* r_s = (float*)(smraw + 55808);

    int bh = blockIdx.y;
    int bt = bh >> 2, h = bh & 3;
    const float* base = qkv + (long)bt*KK*(3*CC) + h*DH;
    int q0 = blockIdx.x * 128;

    int tid = threadIdx.x;
    int wid = tid >> 5, lane = tid & 31;
    int g = lane >> 2, t = lane & 3;
    const float scl = 0.17677669529663687f;

    for (int i = tid; i < 128*16; i += 256){
        int k2 = i & 15, q = i >> 4;
        float2 v = *(const float2*)(base + (long)(q0+q)*(3*CC) + 2*k2);
        Qs[q][k2] = pk(v.x*scl, v.y*scl);
    }
    if (tid < 128){ m_s[tid] = -1e30f; l_s[tid] = 0.f; }

    int wm = wid & 3, wn = wid >> 2;
    int pm = wid;

    float oacc[4][4] = {};
    int qrow = tid >> 1, tr = tid & 1;

    for (int kc = 0; kc < 8; kc++){
        int k0 = kc * 64;
        __syncthreads();
        for (int i = tid; i < 64*16; i += 256){
            int k2 = i & 15, k = i >> 4;
            float2 v = *(const float2*)(base + (long)(k0+k)*(3*CC) + CC + 2*k2);
            Ks[k][k2] = pk(v.x, v.y);
        }
        for (int i = tid; i < 32*32; i += 256){
            int d = i & 31, j = i >> 5;
            float v0 = base[(long)(k0+2*j)  *(3*CC) + 2*CC + d];
            float v1 = base[(long)(k0+2*j+1)*(3*CC) + 2*CC + d];
            Vt[d][j] = pk(v0, v1);
        }
        __syncthreads();

        float sacc[2][4][4] = {};
        #pragma unroll
        for (int ks=0; ks<2; ks++){
            int kc2 = ks*8;
            uint32_t af[2][4], bf[4][2];
            #pragma unroll
            for (int mf=0; mf<2; mf++){
                int r = wm*32 + mf*16 + g;
                af[mf][0] = Qs[r][kc2+t];
                af[mf][1] = Qs[r+8][kc2+t];
                af[mf][2] = Qs[r][kc2+t+4];
                af[mf][3] = Qs[r+8][kc2+t+4];
            }
            #pragma unroll
            for (int nf=0; nf<4; nf++){
                int cn = wn*32 + nf*8 + g;
                bf[nf][0] = Ks[cn][kc2+t];
                bf[nf][1] = Ks[cn][kc2+t+4];
            }
            #pragma unroll
            for (int mf=0; mf<2; mf++)
                #pragma unroll
                for (int nf=0; nf<4; nf++)
                    mma_bf16(sacc[mf][nf], af[mf], bf[nf]);
        }
        #pragma unroll
        for (int mf=0; mf<2; mf++){
            int r0 = wm*32 + mf*16 + g;
            #pragma unroll
            for (int nf=0; nf<4; nf++){
                int cn = wn*32 + nf*8 + 2*t;
                Ps[r0][cn]     = __float_as_uint(sacc[mf][nf][0]);
                Ps[r0][cn+1]   = __float_as_uint(sacc[mf][nf][1]);
                Ps[r0+8][cn]   = __float_as_uint(sacc[mf][nf][2]);
                Ps[r0+8][cn+1] = __float_as_uint(sacc[mf][nf][3]);
            }
        }
        __syncthreads();

        {
            float v[32]; float mx = -1e30f;
            #pragma unroll
            for (int j=0;j<32;j++){
                v[j] = __uint_as_float(Ps[qrow][tr*32 + j]);
                mx = fmaxf(mx, v[j]);
            }
            mx = fmaxf(mx, __shfl_xor_sync(0xffffffffu, mx, 1));
            float mold = m_s[qrow];
            float mnew = fmaxf(mold, mx);
            float sum = 0.f;
            #pragma unroll
            for (int j=0;j<32;j++){
                v[j] = __expf(v[j] - mnew);
                sum += v[j];
            }
            sum += __shfl_xor_sync(0xffffffffu, sum, 1);
            __syncwarp();
            #pragma unroll
            for (int j=0;j<16;j++)
                Ps[qrow][tr*16 + j] = pk(v[2*j], v[2*j+1]);
            if (tr == 0){
                float r = __expf(mold - mnew);
                l_s[qrow] = l_s[qrow]*r + sum;
                m_s[qrow] = mnew;
                r_s[qrow] = r;
            }
        }
        __syncthreads();

        {
            float rr0 = r_s[pm*16 + g];
            float rr1 = r_s[pm*16 + g + 8];
            #pragma unroll
            for (int nf=0; nf<4; nf++){
                oacc[nf][0] *= rr0; oacc[nf][1] *= rr0;
                oacc[nf][2] *= rr1; oacc[nf][3] *= rr1;
            }
            #pragma unroll
            for (int ks=0; ks<4; ks++){
                int kc2 = ks*8;
                uint32_t af[4], bf[4][2];
                int r = pm*16 + g;
                af[0] = Ps[r][kc2+t];
                af[1] = Ps[r+8][kc2+t];
                af[2] = Ps[r][kc2+t+4];
                af[3] = Ps[r+8][kc2+t+4];
                #pragma unroll
                for (int nf=0; nf<4; nf++){
                    int cn = nf*8 + g;
                    bf[nf][0] = Vt[cn][kc2+t];
                    bf[nf][1] = Vt[cn][kc2+t+4];
                }
                #pragma unroll
                for (int nf=0; nf<4; nf++)
                    mma_bf16(oacc[nf], af, bf[nf]);
            }
        }
    }
    __syncthreads();
    {
        float inv0 = 1.f / l_s[pm*16 + g];
        float inv1 = 1.f / l_s[pm*16 + g + 8];
        int qA = q0 + pm*16 + g;
        int qB = qA + 8;
        #pragma unroll
        for (int nf=0; nf<4; nf++){
            int d = nf*8 + 2*t;
            long rowA = ((long)bt*KK + qA)*CC + h*DH + d;
            long rowB = ((long)bt*KK + qB)*CC + h*DH + d;
            o[rowA]   = oacc[nf][0]*inv0;
            o[rowA+1] = oacc[nf][1]*inv0;
            o[rowB]   = oacc[nf][2]*inv1;
            o[rowB+1] = oacc[nf][3]*inv1;
        }
    }
}

// ---------------- stage kernels ----------------
__global__ void k_copy(const float4* __restrict__ in, float4* __restrict__ out, int n4){
    int i = blockIdx.x*blockDim.x + threadIdx.x;
    if (i < n4) out[i] = in[i];
}

__global__ void k_mean(const float* __restrict__ x, float* __restrict__ xm){
    int i = blockIdx.x*blockDim.x + threadIdx.x;
    if (i >= BB*CC*NSP) return;
    int b = i >> 17; int rem = i & 131071;
    float s = 0.f;
    #pragma unroll
    for (int t=0;t<TT;t++) s += x[((long)b*TT+t)*131072 + rem];
    xm[i] = s * 0.125f;
}

__global__ void k_conv3(const float* __restrict__ xm, const float* __restrict__ w,
                        const float* __restrict__ bias, float* __restrict__ h1){
    __shared__ float pl[34*34];
    int bo = blockIdx.x; int b = bo >> 5; int oc = bo & 31;
    int tid = threadIdx.x;
    int h = tid >> 5, wq = tid & 31;
    float acc = 0.f;
    for (int ic=0; ic<CC; ic++){
        for (int i=tid; i<34*34; i+=1024){
            int hh = i/34 - 1, ww = i%34 - 1;
            pl[i] = (hh>=0 && hh<32 && ww>=0 && ww<32) ?
                    xm[((long)b*CC+ic)*NSP + hh*32+ww] : 0.f;
        }
        __syncthreads();
        const float* wp = w + ((long)oc*CC+ic)*9;
        #pragma unroll
        for (int kh=0;kh<3;kh++)
            #pragma unroll
            for (int kw=0;kw<3;kw++)
                acc += pl[(h+kh)*34 + (wq+kw)] * wp[kh*3+kw];
        __syncthreads();
    }
    acc += bias[oc];
    h1[(long)bo*NSP + tid] = (acc >= 0.f) ? acc : 0.01f*acc;
}

__global__ void k_scoretopk(const float* __restrict__ h1, const float* __restrict__ w2,
                            const float* __restrict__ b2, int* __restrict__ idx,
                            float* __restrict__ scl){
    __shared__ float s[1024];
    __shared__ unsigned char keep[1024];
    int b = blockIdx.x, n = threadIdx.x;
    float a = 0.f;
    #pragma unroll
    for (int oc=0;oc<32;oc++) a += h1[((long)b*32+oc)*NSP + n] * w2[oc];
    float v = sigm(a + b2[0]);
    s[n] = v;
    __syncthreads();
    int cnt = 0;
    for (int m=0;m<1024;m++){ float u = s[m]; cnt += (u>v) || (u==v && m<n); }
    keep[n] = (cnt < KK) ? 1 : 0;
    __syncthreads();
    if (keep[n]){
        int pos = 0;
        for (int m=0;m<n;m++) pos += keep[m];
        idx[b*KK + pos] = n;
        scl[b*KK + pos] = v / (v + 1e-6f);
    }
}

__global__ __launch_bounds__(256)
void k_gather2(const float* __restrict__ x, const int* __restrict__ idx,
               const float* __restrict__ scl, const float* __restrict__ nw,
               float* __restrict__ z0){
    __shared__ float tile[128][33];
    __shared__ float red[32][9];
    __shared__ int   nsh[32];
    __shared__ float ssh[32];
    __shared__ float rst[32];
    int bt = blockIdx.x;
    int b = bt >> 3, t = bt & 7;
    int kc = blockIdx.y;
    int tid = threadIdx.x;
    if (tid < 32){
        nsh[tid] = idx[b*KK + kc*32 + tid];
        ssh[tid] = scl[b*KK + kc*32 + tid];
    }
    __syncthreads();
    const float* xb = x + ((long)bt*CC)*NSP;
    #pragma unroll
    for (int u=0; u<16; u++){
        int e = tid + u*256;
        int k = e & 31, c = e >> 5;
        tile[c][k] = xb[(long)c*NSP + nsh[k]] * ssh[k];
    }
    __syncthreads();
    {
        int k = tid & 31, part = tid >> 5;
        float s = 0.f;
        #pragma unroll
        for (int j=0;j<16;j++){ float v = tile[part*16+j][k]; s += v*v; }
        red[k][part] = s;
    }
    __syncthreads();
    if (tid < 32){
        float s = 0.f;
        #pragma unroll
        for (int p=0;p<8;p++) s += red[tid][p];
        rst[tid] = rsqrtf(s*(1.f/128.f) + 1e-5f);
    }
    __syncthreads();
    #pragma unroll
    for (int u=0; u<16; u++){
        int e = tid + u*256;
        int c = e & 127, k = e >> 7;
        long row = (((long)b*KK + kc*32 + k)*TT + t);
        z0[row*CC + c] = tile[c][k] * rst[k] * nw[c];
    }
}

__global__ void k_conv1d(const float* __restrict__ xz, const float* __restrict__ w,
                         const float* __restrict__ bias, float* __restrict__ xc){
    int s = blockIdx.x; int ch = threadIdx.x;
    float in[TT];
    #pragma unroll
    for (int t=0;t<TT;t++) in[t] = xz[(((long)s*TT + t)*(2*DI)) + ch];
    float w0=w[ch*4+0], w1=w[ch*4+1], w2=w[ch*4+2], w3=w[ch*4+3];
    float bb = bias[ch];
    #pragma unroll
    for (int t=0;t<TT;t++){
        float a = bb + in[t]*w3;
        if (t>=1) a += in[t-1]*w2;
        if (t>=2) a += in[t-2]*w1;
        if (t>=3) a += in[t-3]*w0;
        xc[((long)s*TT + t)*DI + ch] = siluf(a);
    }
}

// scan: recompute conv1d+silu from xz (no xc read), fused dt_proj + scan + gate
__global__ void k_scan3(const float* __restrict__ xz, const float* __restrict__ xdbl,
                        const float* __restrict__ dtw, const float* __restrict__ dtbias,
                        const float* __restrict__ Alog, const float* __restrict__ Dp,
                        const float* __restrict__ cw, const float* __restrict__ cb,
                        float* __restrict__ yg){
    __shared__ float xd[TT][40];
    int s = blockIdx.x; int ch = threadIdx.x;
    for (int i = ch; i < TT*40; i += 256)
        xd[i/40][i%40] = xdbl[(long)s*TT*40 + i];
    float w8[DTR];
    #pragma unroll
    for (int r=0;r<DTR;r++) w8[r] = dtw[ch*DTR + r];
    float db = dtbias[ch];
    float cw0=cw[ch*4+0], cw1=cw[ch*4+1], cw2=cw[ch*4+2], cw3=cw[ch*4+3];
    float cbb = cb[ch];
    float in[TT];
    #pragma unroll
    for (int t=0;t<TT;t++) in[t] = xz[(((long)s*TT + t)*(2*DI)) + ch];
    float Arow[DS];
    #pragma unroll
    for (int d=0;d<DS;d++) Arow[d] = -__expf(Alog[ch*DS + d]);
    float A0 = Arow[0];
    bool geom = true;
    #pragma unroll
    for (int d=1;d<DS;d++)
        geom = geom && (fabsf(Arow[d] - A0*(float)(d+1)) <= 1e-5f*fabsf(A0*(float)(d+1)) + 1e-12f);
    float Dv = Dp[ch];
    __syncthreads();
    float h[DS];
    #pragma unroll
    for (int d=0;d<DS;d++) h[d] = 0.f;
    #pragma unroll
    for (int t=0;t<TT;t++){
        long row = (long)s*TT + t;
        float a = cbb + in[t]*cw3;
        if (t>=1) a += in[t-1]*cw2;
        if (t>=2) a += in[t-2]*cw1;
        if (t>=3) a += in[t-3]*cw0;
        float u = siluf(a);
        float dtr = db;
        #pragma unroll
        for (int r=0;r<DTR;r++) dtr += xd[t][r]*w8[r];
        float dt = softplusf(dtr);
        float du = dt*u;
        float y = 0.f;
        if (geom){
            float e1 = __expf(dt*A0);
            float ed = 1.f;
            #pragma unroll
            for (int d=0;d<DS;d++){
                ed *= e1;
                float Bv = xd[t][DTR + d];
                float Cv = xd[t][DTR + DS + d];
                h[d] = h[d]*ed + du*Bv;
                y += h[d]*Cv;
            }
        } else {
            #pragma unroll
            for (int d=0;d<DS;d++){
                float Bv = xd[t][DTR + d];
                float Cv = xd[t][DTR + DS + d];
                h[d] = h[d]*__expf(dt*Arow[d]) + du*Bv;
                y += h[d]*Cv;
            }
        }
        float zg = xz[row*(2*DI) + DI + ch];
        yg[row*DI + ch] = (y + u*Dv) * siluf(zg);
    }
}

// ---------------- host launch ----------------
static float* symf(const void* s){ void* p = nullptr; cudaGetSymbolAddress(&p, s); return (float*)p; }

extern "C" void kernel_launch(void* const* d_in, const int* in_sizes, int n_in,
                              void* d_out, int out_size)
{
    const float* x_in      = (const float*)d_in[0];
    const float* norm1_w   = (const float*)d_in[1];
    const float* in_proj_w = (const float*)d_in[2];
    const float* conv1d_w  = (const float*)d_in[3];
    const float* conv1d_b  = (const float*)d_in[4];
    const float* x_proj_w  = (const float*)d_in[5];
    const float* dt_proj_w = (const float*)d_in[6];
    const float* dt_proj_b = (const float*)d_in[7];
    const float* A_log     = (const float*)d_in[8];
    const float* Dp        = (const float*)d_in[9];
    const float* out_proj_w= (const float*)d_in[10];
    const float* r1_w      = (const float*)d_in[11];
    const float* r1_b      = (const float*)d_in[12];
    const float* r2_w      = (const float*)d_in[13];
    const float* r2_b      = (const float*)d_in[14];
    const float* attn_in_w = (const float*)d_in[15];
    const float* attn_in_b = (const float*)d_in[16];
    const float* attn_out_w= (const float*)d_in[17];
    const float* attn_out_b= (const float*)d_in[18];
    const float* ln_w      = (const float*)d_in[19];
    const float* ln_b      = (const float*)d_in[20];
    float* out = (float*)d_out;

    float *xm = symf(g_xm), *h1 = symf(g_h1);
    float *scl = symf(g_scl), *z0 = symf(g_z0), *xz = symf(g_xz);
    float *xc = symf(g_xc), *xdbl = symf(g_xdbl);
    float *yg = symf(g_yg), *zsb = symf(g_zs);
    float *qkv = symf(g_qkv), *orp = symf(g_orp);
    int* idx = (int*)symf(g_idx);

    static int smem_set = 0;
    if (!smem_set){
        cudaFuncSetAttribute(k_flash2, cudaFuncAttributeMaxDynamicSharedMemorySize, 57344);
        smem_set = 1;
    }

    // 1) router
    k_mean<<<(BB*CC*NSP+255)/256, 256>>>(x_in, xm);
    k_conv3<<<BB*32, 1024>>>(xm, r1_w, r1_b, h1);
    k_scoretopk<<<BB, 1024>>>(h1, r2_w, r2_b, idx, scl);
    // 2) gather + rmsnorm   (profiled launch slot)
    k_gather2<<<dim3(BB*TT, 16), 256>>>(x_in, idx, scl, norm1_w, z0);
    // 3) mamba
    gemm_bf<128,0><<<dim3(4,256),256>>>(z0, in_proj_w, nullptr, xz,
        ROWS, 2*DI, CC, CC, CC, 2*DI, nullptr, nullptr, nullptr, nullptr);
    k_conv1d<<<ROWS/TT, DI>>>(xz, conv1d_w, conv1d_b, xc);
    gemm_bf<64,0><<<dim3(1,256),256>>>(xc, x_proj_w, nullptr, xdbl,
        ROWS, 40, DI, DI, DI, 40, nullptr, nullptr, nullptr, nullptr);
    k_scan3<<<ROWS/TT, DI>>>(xz, xdbl, dt_proj_w, dt_proj_b, A_log, Dp,
        conv1d_w, conv1d_b, yg);
    gemm_bf<128,1><<<dim3(1,256),256>>>(yg, out_proj_w, nullptr, zsb,
        ROWS, CC, DI, DI, DI, CC, nullptr, nullptr, nullptr, nullptr);
    // 4) attention
    gemm_bf<128,0><<<dim3(3,256),256>>>(zsb, attn_in_w, attn_in_b, qkv,
        ROWS, 3*CC, CC, CC, CC, 3*CC, nullptr, nullptr, nullptr, nullptr);
    k_flash2<<<dim3(4, NBATCH), 256, 56320>>>(qkv, orp);
    // 5) out = x_in, then attn_out + LayerNorm + coalesced scatter-add
    {
        int n4 = (BB*TT*CC*NSP)/4;
        k_copy<<<(n4+255)/256, 256>>>((const float4*)x_in, (float4*)out, n4);
    }
    gemm_bf<128,2><<<dim3(1,256),256>>>(orp, attn_out_w, attn_out_b, out,
        ROWS, CC, CC, CC, CC, NSP, zsb, ln_w, ln_b, idx);
}

// round 14
// speedup vs baseline: 3.0315x; 1.0107x over previous
#include <cuda_runtime.h>
#include <cuda_bf16.h>
#include <cstdint>

// ---------------- problem constants ----------------
#define BB 8
#define TT 8
#define CC 128
#define NSP 1024
#define KK 512
#define DI 256
#define DS 16
#define DTR 8
#define NH 4
#define DH 32
#define ROWS 32768
#define NBATCH 256

// ---------------- device scratch ----------------
__device__ float    g_xm  [BB*CC*NSP];
__device__ float    g_h1  [BB*32*NSP];
__device__ int      g_idx [BB*KK];
__device__ float    g_scl [BB*KK];
__device__ uint32_t g_z0p [(size_t)ROWS*64];    // bf16x2 z0
__device__ float    g_xz  [(size_t)ROWS*2*DI];
__device__ uint32_t g_xcp [(size_t)ROWS*128];   // bf16x2 xc
__device__ float    g_xdbl[(size_t)ROWS*40];
__device__ uint32_t g_ygp [(size_t)ROWS*128];   // bf16x2 yg
__device__ float    g_zs  [(size_t)ROWS*CC];    // fp32 (residual path)
__device__ uint32_t g_qkvp[(size_t)ROWS*192];   // bf16x2 qkv (Q pre-scaled)
__device__ uint32_t g_orpp[(size_t)ROWS*64];    // bf16x2 attn out

// ---------------- helpers ----------------
__device__ __forceinline__ float sigm(float x){ return 1.f/(1.f+__expf(-x)); }
__device__ __forceinline__ float siluf(float x){ return x*sigm(x); }
__device__ __forceinline__ float softplusf(float x){ return (x>20.f)?x:log1pf(__expf(x)); }

__device__ __forceinline__ uint32_t pk(float lo, float hi){
    __nv_bfloat162 v = __floats2bfloat162_rn(lo, hi);
    return *reinterpret_cast<uint32_t*>(&v);
}

__device__ __forceinline__ void mma_bf16(float* c, const uint32_t* a, const uint32_t* b){
    asm volatile(
        "mma.sync.aligned.m16n8k16.row.col.f32.bf16.bf16.f32 "
        "{%0,%1,%2,%3}, {%4,%5,%6,%7}, {%8,%9}, {%0,%1,%2,%3};"
        : "+f"(c[0]), "+f"(c[1]), "+f"(c[2]), "+f"(c[3])
        : "r"(a[0]), "r"(a[1]), "r"(a[2]), "r"(a[3]), "r"(b[0]), "r"(b[1]));
}

// ---------------- bf16 tensor-core TN GEMM ----------------
// A: fp32 (ABF=false, lda in floats) or packed bf16x2 (ABF=true, lda in words).
// Bw: N x Kd fp32. MODE 0: fp32 out. MODE 1: fp32 out + (b,k,t)->(b,t,k) permute.
// MODE 2: bias + residual + LayerNorm + k-coalesced scatter-add into output.
// MODE 4: bf16x2 packed out (ldc = word stride), cols < CC scaled by 1/sqrt(dh).
template<int BN, int MODE, bool ABF>
__global__ __launch_bounds__(256)
void gemm_bf(const void* __restrict__ Av, const float* __restrict__ Bw,
             const float* __restrict__ bias, void* __restrict__ Cv,
             int M, int N, int Kd, int lda, int ldb, int ldc,
             const float* __restrict__ zres, const float* __restrict__ lnw,
             const float* __restrict__ lnb, const int* __restrict__ idxp)
{
    constexpr int NF = BN/16;
    constexpr int BU = BN/32;
    __shared__ union SU {
        struct { uint32_t As[2][128][20]; uint32_t Bs[2][BN][20]; } g;
        struct { float red[128][17]; float tile[128][33]; int nsh[32]; } e;
    } S;

    const float* A = (const float*)Av;
    const uint32_t* A32 = (const uint32_t*)Av;
    float* C = (float*)Cv;
    uint32_t* C32 = (uint32_t*)Cv;

    int m0 = blockIdx.y*128, n0 = blockIdx.x*BN;
    int tid = threadIdx.x;
    int wid = tid >> 5, lane = tid & 31;
    int warp_m = wid >> 1, warp_n = wid & 1;
    int g = lane >> 2, t = lane & 3;

    float acc[2][NF][4] = {};
    float4 ra[4]; uint4 ua[2];
    float4 rb[BU];
    int nk = Kd >> 5;
    const float qscl = 0.17677669529663687f;

    // ---- stage tile 0 ----
    if (ABF){
        #pragma unroll
        for (int u=0;u<2;u++){
            int f = tid + u*256; int w4 = f&3, m = f>>2;
            ua[u] = *(const uint4*)(A32 + (long)(m0+m)*lda + w4*4);
        }
    } else {
        #pragma unroll
        for (int u=0;u<4;u++){
            int f = tid + u*256; int k4 = f&7, m = f>>3;
            ra[u] = *(const float4*)(A + (long)(m0+m)*lda + k4*4);
        }
    }
    #pragma unroll
    for (int u=0;u<BU;u++){
        int f = tid + u*256; int k4 = f&7, n = f>>3;
        int gn = n0 + n;
        float4 v = {0.f,0.f,0.f,0.f};
        if (gn < N) v = *(const float4*)(Bw + (long)gn*ldb + k4*4);
        rb[u] = v;
    }
    if (ABF){
        #pragma unroll
        for (int u=0;u<2;u++){
            int f = tid + u*256; int w4 = f&3, m = f>>2;
            *(uint4*)&S.g.As[0][m][w4*4] = ua[u];
        }
    } else {
        #pragma unroll
        for (int u=0;u<4;u++){
            int f = tid + u*256; int k4 = f&7, m = f>>3;
            S.g.As[0][m][k4*2]   = pk(ra[u].x, ra[u].y);
            S.g.As[0][m][k4*2+1] = pk(ra[u].z, ra[u].w);
        }
    }
    #pragma unroll
    for (int u=0;u<BU;u++){
        int f = tid + u*256; int k4 = f&7, n = f>>3;
        S.g.Bs[0][n][k4*2]   = pk(rb[u].x, rb[u].y);
        S.g.Bs[0][n][k4*2+1] = pk(rb[u].z, rb[u].w);
    }
    __syncthreads();

    int buf = 0;
    for (int kt = 0; kt < nk; kt++){
        if (kt+1 < nk){
            if (ABF){
                int kw0 = (kt+1)*16;
                #pragma unroll
                for (int u=0;u<2;u++){
                    int f = tid + u*256; int w4 = f&3, m = f>>2;
                    ua[u] = *(const uint4*)(A32 + (long)(m0+m)*lda + kw0 + w4*4);
                }
            } else {
                int k0 = (kt+1)*32;
                #pragma unroll
                for (int u=0;u<4;u++){
                    int f = tid + u*256; int k4 = f&7, m = f>>3;
                    ra[u] = *(const float4*)(A + (long)(m0+m)*lda + k0 + k4*4);
                }
            }
            int k0 = (kt+1)*32;
            #pragma unroll
            for (int u=0;u<BU;u++){
                int f = tid + u*256; int k4 = f&7, n = f>>3;
                int gn = n0 + n;
                float4 v = {0.f,0.f,0.f,0.f};
                if (gn < N) v = *(const float4*)(Bw + (long)gn*ldb + k0 + k4*4);
                rb[u] = v;
            }
        }
        #pragma unroll
        for (int ks=0; ks<2; ks++){
            int kc2 = ks*8;
            uint32_t af[2][4], bfr[NF][2];
            #pragma unroll
            for (int mf=0; mf<2; mf++){
                int r = warp_m*32 + mf*16 + g;
                af[mf][0] = S.g.As[buf][r][kc2+t];
                af[mf][1] = S.g.As[buf][r+8][kc2+t];
                af[mf][2] = S.g.As[buf][r][kc2+t+4];
                af[mf][3] = S.g.As[buf][r+8][kc2+t+4];
            }
            #pragma unroll
            for (int nf=0; nf<NF; nf++){
                int cn = warp_n*(BN/2) + nf*8 + g;
                bfr[nf][0] = S.g.Bs[buf][cn][kc2+t];
                bfr[nf][1] = S.g.Bs[buf][cn][kc2+t+4];
            }
            #pragma unroll
            for (int mf=0; mf<2; mf++)
                #pragma unroll
                for (int nf=0; nf<NF; nf++)
                    mma_bf16(acc[mf][nf], af[mf], bfr[nf]);
        }
        if (kt+1 < nk){
            int nb = buf^1;
            if (ABF){
                #pragma unroll
                for (int u=0;u<2;u++){
                    int f = tid + u*256; int w4 = f&3, m = f>>2;
                    *(uint4*)&S.g.As[nb][m][w4*4] = ua[u];
                }
            } else {
                #pragma unroll
                for (int u=0;u<4;u++){
                    int f = tid + u*256; int k4 = f&7, m = f>>3;
                    S.g.As[nb][m][k4*2]   = pk(ra[u].x, ra[u].y);
                    S.g.As[nb][m][k4*2+1] = pk(ra[u].z, ra[u].w);
                }
            }
            #pragma unroll
            for (int u=0;u<BU;u++){
                int f = tid + u*256; int k4 = f&7, n = f>>3;
                S.g.Bs[nb][n][k4*2]   = pk(rb[u].x, rb[u].y);
                S.g.Bs[nb][n][k4*2+1] = pk(rb[u].z, rb[u].w);
            }
            __syncthreads();
            buf = nb;
        }
    }

    if (MODE == 2){
        __syncthreads();
        float sum[2][2] = {}, sq[2][2] = {};
        #pragma unroll
        for (int mf=0;mf<2;mf++){
            int rl0 = warp_m*32 + mf*16 + g;
            long gr0 = m0 + rl0, gr1 = gr0 + 8;
            #pragma unroll
            for (int nf=0;nf<NF;nf++){
                int cn = warp_n*(BN/2) + nf*8 + 2*t;
                float b0 = bias[cn], b1 = bias[cn+1];
                float v0 = acc[mf][nf][0] + b0 + zres[gr0*CC + cn];
                float v1 = acc[mf][nf][1] + b1 + zres[gr0*CC + cn+1];
                float v2 = acc[mf][nf][2] + b0 + zres[gr1*CC + cn];
                float v3 = acc[mf][nf][3] + b1 + zres[gr1*CC + cn+1];
                acc[mf][nf][0]=v0; acc[mf][nf][1]=v1; acc[mf][nf][2]=v2; acc[mf][nf][3]=v3;
                sum[mf][0] += v0+v1;   sum[mf][1] += v2+v3;
                sq[mf][0]  += v0*v0+v1*v1; sq[mf][1] += v2*v2+v3*v3;
            }
        }
        int cid = warp_n*4 + t;
        #pragma unroll
        for (int mf=0;mf<2;mf++){
            int rl0 = warp_m*32 + mf*16 + g;
            S.e.red[rl0][cid]     = sum[mf][0];  S.e.red[rl0][8+cid]   = sq[mf][0];
            S.e.red[rl0+8][cid]   = sum[mf][1];  S.e.red[rl0+8][8+cid] = sq[mf][1];
        }
        __syncthreads();
        float mu_[2][2], rs_[2][2];
        #pragma unroll
        for (int mf=0;mf<2;mf++)
            #pragma unroll
            for (int half=0; half<2; half++){
                int rl = warp_m*32 + mf*16 + g + half*8;
                float s8 = 0.f, q8 = 0.f;
                #pragma unroll
                for (int j=0;j<8;j++){ s8 += S.e.red[rl][j]; q8 += S.e.red[rl][8+j]; }
                float mu = s8 * (1.f/128.f);
                float var = q8 * (1.f/128.f) - mu*mu;
                mu_[mf][half] = mu;
                rs_[mf][half] = rsqrtf(var + 1e-5f);
            }
        long bt = m0 >> 9;
        int bidx = (int)(bt >> 3);
        int kbase = m0 & 511;
        float* Cb0 = C + (bt*CC)*NSP;
        #pragma unroll
        for (int chunk=0; chunk<4; chunk++){
            __syncthreads();
            if (tid < 32) S.e.nsh[tid] = idxp[bidx*KK + kbase + chunk*32 + tid];
            if (warp_m == chunk){
                #pragma unroll
                for (int mf=0; mf<2; mf++)
                    #pragma unroll
                    for (int half=0; half<2; half++){
                        int kl = mf*16 + g + half*8;
                        float mu = mu_[mf][half], rs = rs_[mf][half];
                        #pragma unroll
                        for (int nf=0; nf<NF; nf++){
                            int cn = warp_n*(BN/2) + nf*8 + 2*t;
                            S.e.tile[cn][kl]   = (acc[mf][nf][half*2]   - mu)*rs*lnw[cn]   + lnb[cn];
                            S.e.tile[cn+1][kl] = (acc[mf][nf][half*2+1] - mu)*rs*lnw[cn+1] + lnb[cn+1];
                        }
                    }
            }
            __syncthreads();
            #pragma unroll
            for (int u=0; u<16; u++){
                int e = tid + u*256;
                int k = e & 31, c = e >> 5;
                Cb0[(long)c*NSP + S.e.nsh[k]] += S.e.tile[c][k];
            }
        }
        return;
    }

    #pragma unroll
    for (int mf=0; mf<2; mf++){
        int r0 = m0 + warp_m*32 + mf*16 + g;
        int r1 = r0 + 8;
        long gr0 = r0, gr1 = r1;
        if (MODE==1){
            int b = r0 >> 12; int k = (r0 >> 3) & 511; int tt = r0 & 7;
            gr0 = ((long)(b*8 + tt) << 9) + k;
            b = r1 >> 12; k = (r1 >> 3) & 511; tt = r1 & 7;
            gr1 = ((long)(b*8 + tt) << 9) + k;
        }
        #pragma unroll
        for (int nf=0; nf<NF; nf++){
            int cn = n0 + warp_n*(BN/2) + nf*8 + 2*t;
            if (cn >= N) continue;
            float b0 = bias ? bias[cn]   : 0.f;
            float b1 = bias ? bias[cn+1] : 0.f;
            float v0 = acc[mf][nf][0] + b0;
            float v1 = acc[mf][nf][1] + b1;
            float v2 = acc[mf][nf][2] + b0;
            float v3 = acc[mf][nf][3] + b1;
            if (MODE==4){
                if (cn < CC){ v0*=qscl; v1*=qscl; v2*=qscl; v3*=qscl; }
                C32[gr0*ldc + (cn>>1)] = pk(v0, v1);
                C32[gr1*ldc + (cn>>1)] = pk(v2, v3);
            } else {
                C[gr0*ldc + cn]   = v0;
                C[gr0*ldc + cn+1] = v1;
                C[gr1*ldc + cn]   = v2;
                C[gr1*ldc + cn+1] = v3;
            }
        }
    }
}

// ---------------- bf16 flash attention, q-tile 128, packed qkv ----------------
__global__ __launch_bounds__(256)
void k_flash2(const uint32_t* __restrict__ qkvp, uint32_t* __restrict__ op)
{
    extern __shared__ char smraw[];
    uint32_t (*Qs)[20] = (uint32_t(*)[20])(smraw);
    uint32_t (*Ks)[20] = (uint32_t(*)[20])(smraw + 10240);
    uint32_t (*Vt)[36] = (uint32_t(*)[36])(smraw + 15360);
    uint32_t (*Ps)[68] = (uint32_t(*)[68])(smraw + 19968);
    float* m_s = (float*)(smraw + 54784);
    float* l_s = (float*)(smraw + 55296);
    float* r_s = (float*)(smraw + 55808);

    int bh = blockIdx.y;
    int bt = bh >> 2, h = bh & 3;
    const uint32_t* base = qkvp + (long)bt*KK*192 + h*16;   // h*32 bf16 = 16 words
    int q0 = blockIdx.x * 128;

    int tid = threadIdx.x;
    int wid = tid >> 5, lane = tid & 31;
    int g = lane >> 2, t = lane & 3;

    // Q load (already scaled, packed)
    for (int i = tid; i < 128*16; i += 256){
        int k2 = i & 15, q = i >> 4;
        Qs[q][k2] = base[(long)(q0+q)*192 + k2];
    }
    if (tid < 128){ m_s[tid] = -1e30f; l_s[tid] = 0.f; }

    int wm = wid & 3, wn = wid >> 2;
    int pm = wid;

    float oacc[4][4] = {};
    int qrow = tid >> 1, tr = tid & 1;

    for (int kc = 0; kc < 8; kc++){
        int k0 = kc * 64;
        __syncthreads();
        for (int i = tid; i < 64*16; i += 256){
            int k2 = i & 15, k = i >> 4;
            Ks[k][k2] = base[(long)(k0+k)*192 + 64 + k2];
        }
        for (int i = tid; i < 16*32; i += 256){
            int d2 = i & 15, j = i >> 4;
            uint32_t w0 = base[(long)(k0+2*j)  *192 + 128 + d2];
            uint32_t w1 = base[(long)(k0+2*j+1)*192 + 128 + d2];
            Vt[2*d2][j]   = __byte_perm(w0, w1, 0x5410);
            Vt[2*d2+1][j] = __byte_perm(w0, w1, 0x7632);
        }
        __syncthreads();

        float sacc[2][4][4] = {};
        #pragma unroll
        for (int ks=0; ks<2; ks++){
            int kc2 = ks*8;
            uint32_t af[2][4], bf[4][2];
            #pragma unroll
            for (int mf=0; mf<2; mf++){
                int r = wm*32 + mf*16 + g;
                af[mf][0] = Qs[r][kc2+t];
                af[mf][1] = Qs[r+8][kc2+t];
                af[mf][2] = Qs[r][kc2+t+4];
                af[mf][3] = Qs[r+8][kc2+t+4];
            }
            #pragma unroll
            for (int nf=0; nf<4; nf++){
                int cn = wn*32 + nf*8 + g;
                bf[nf][0] = Ks[cn][kc2+t];
                bf[nf][1] = Ks[cn][kc2+t+4];
            }
            #pragma unroll
            for (int mf=0; mf<2; mf++)
                #pragma unroll
                for (int nf=0; nf<4; nf++)
                    mma_bf16(sacc[mf][nf], af[mf], bf[nf]);
        }
        #pragma unroll
        for (int mf=0; mf<2; mf++){
            int r0 = wm*32 + mf*16 + g;
            #pragma unroll
            for (int nf=0; nf<4; nf++){
                int cn = wn*32 + nf*8 + 2*t;
                Ps[r0][cn]     = __float_as_uint(sacc[mf][nf][0]);
                Ps[r0][cn+1]   = __float_as_uint(sacc[mf][nf][1]);
                Ps[r0+8][cn]   = __float_as_uint(sacc[mf][nf][2]);
                Ps[r0+8][cn+1] = __float_as_uint(sacc[mf][nf][3]);
            }
        }
        __syncthreads();

        {
            float v[32]; float mx = -1e30f;
            #pragma unroll
            for (int j=0;j<32;j++){
                v[j] = __uint_as_float(Ps[qrow][tr*32 + j]);
                mx = fmaxf(mx, v[j]);
            }
            mx = fmaxf(mx, __shfl_xor_sync(0xffffffffu, mx, 1));
            float mold = m_s[qrow];
            float mnew = fmaxf(mold, mx);
            float sum = 0.f;
            #pragma unroll
            for (int j=0;j<32;j++){
                v[j] = __expf(v[j] - mnew);
                sum += v[j];
            }
            sum += __shfl_xor_sync(0xffffffffu, sum, 1);
            __syncwarp();
            #pragma unroll
            for (int j=0;j<16;j++)
                Ps[qrow][tr*16 + j] = pk(v[2*j], v[2*j+1]);
            if (tr == 0){
                float r = __expf(mold - mnew);
                l_s[qrow] = l_s[qrow]*r + sum;
                m_s[qrow] = mnew;
                r_s[qrow] = r;
            }
        }
        __syncthreads();

        {
            float rr0 = r_s[pm*16 + g];
            float rr1 = r_s[pm*16 + g + 8];
            #pragma unroll
            for (int nf=0; nf<4; nf++){
                oacc[nf][0] *= rr0; oacc[nf][1] *= rr0;
                oacc[nf][2] *= rr1; oacc[nf][3] *= rr1;
            }
            #pragma unroll
            for (int ks=0; ks<4; ks++){
                int kc2 = ks*8;
                uint32_t af[4], bf[4][2];
                int r = pm*16 + g;
                af[0] = Ps[r][kc2+t];
                af[1] = Ps[r+8][kc2+t];
                af[2] = Ps[r][kc2+t+4];
                af[3] = Ps[r+8][kc2+t+4];
                #pragma unroll
                for (int nf=0; nf<4; nf++){
                    int cn = nf*8 + g;
                    bf[nf][0] = Vt[cn][kc2+t];
                    bf[nf][1] = Vt[cn][kc2+t+4];
                }
                #pragma unroll
                for (int nf=0; nf<4; nf++)
                    mma_bf16(oacc[nf], af, bf[nf]);
            }
        }
    }
    __syncthreads();
    {
        float inv0 = 1.f / l_s[pm*16 + g];
        float inv1 = 1.f / l_s[pm*16 + g + 8];
        int qA = q0 + pm*16 + g;
        int qB = qA + 8;
        #pragma unroll
        for (int nf=0; nf<4; nf++){
            int d = nf*8 + 2*t;
            int w = (h*DH + d) >> 1;
            long rowA = ((long)bt*KK + qA)*64 + w;
            long rowB = ((long)bt*KK + qB)*64 + w;
            op[rowA] = pk(oacc[nf][0]*inv0, oacc[nf][1]*inv0);
            op[rowB] = pk(oacc[nf][2]*inv1, oacc[nf][3]*inv1);
        }
    }
}

// ---------------- stage kernels ----------------
__global__ void k_copy(const float4* __restrict__ in, float4* __restrict__ out, int n4){
    int i = blockIdx.x*blockDim.x + threadIdx.x;
    if (i < n4) out[i] = in[i];
}

__global__ void k_mean(const float* __restrict__ x, float* __restrict__ xm){
    int i = blockIdx.x*blockDim.x + threadIdx.x;
    if (i >= BB*CC*NSP) return;
    int b = i >> 17; int rem = i & 131071;
    float s = 0.f;
    #pragma unroll
    for (int t=0;t<TT;t++) s += x[((long)b*TT+t)*131072 + rem];
    xm[i] = s * 0.125f;
}

__global__ void k_conv3(const float* __restrict__ xm, const float* __restrict__ w,
                        const float* __restrict__ bias, float* __restrict__ h1){
    __shared__ float pl[34*34];
    int bo = blockIdx.x; int b = bo >> 5; int oc = bo & 31;
    int tid = threadIdx.x;
    int h = tid >> 5, wq = tid & 31;
    float acc = 0.f;
    for (int ic=0; ic<CC; ic++){
        for (int i=tid; i<34*34; i+=1024){
            int hh = i/34 - 1, ww = i%34 - 1;
            pl[i] = (hh>=0 && hh<32 && ww>=0 && ww<32) ?
                    xm[((long)b*CC+ic)*NSP + hh*32+ww] : 0.f;
        }
        __syncthreads();
        const float* wp = w + ((long)oc*CC+ic)*9;
        #pragma unroll
        for (int kh=0;kh<3;kh++)
            #pragma unroll
            for (int kw=0;kw<3;kw++)
                acc += pl[(h+kh)*34 + (wq+kw)] * wp[kh*3+kw];
        __syncthreads();
    }
    acc += bias[oc];
    h1[(long)bo*NSP + tid] = (acc >= 0.f) ? acc : 0.01f*acc;
}

__global__ void k_scoretopk(const float* __restrict__ h1, const float* __restrict__ w2,
                            const float* __restrict__ b2, int* __restrict__ idx,
                            float* __restrict__ scl){
    __shared__ float s[1024];
    __shared__ unsigned char keep[1024];
    int b = blockIdx.x, n = threadIdx.x;
    float a = 0.f;
    #pragma unroll
    for (int oc=0;oc<32;oc++) a += h1[((long)b*32+oc)*NSP + n] * w2[oc];
    float v = sigm(a + b2[0]);
    s[n] = v;
    __syncthreads();
    int cnt = 0;
    for (int m=0;m<1024;m++){ float u = s[m]; cnt += (u>v) || (u==v && m<n); }
    keep[n] = (cnt < KK) ? 1 : 0;
    __syncthreads();
    if (keep[n]){
        int pos = 0;
        for (int m=0;m<n;m++) pos += keep[m];
        idx[b*KK + pos] = n;
        scl[b*KK + pos] = v / (v + 1e-6f);
    }
}

// tile-based gather + STE scale + RMSNorm, packed bf16 out
__global__ __launch_bounds__(256)
void k_gather2(const float* __restrict__ x, const int* __restrict__ idx,
               const float* __restrict__ scl, const float* __restrict__ nw,
               uint32_t* __restrict__ z0p){
    __shared__ float tile[128][33];
    __shared__ float red[32][9];
    __shared__ int   nsh[32];
    __shared__ float ssh[32];
    __shared__ float rst[32];
    int bt = blockIdx.x;
    int b = bt >> 3, t = bt & 7;
    int kc = blockIdx.y;
    int tid = threadIdx.x;
    if (tid < 32){
        nsh[tid] = idx[b*KK + kc*32 + tid];
        ssh[tid] = scl[b*KK + kc*32 + tid];
    }
    __syncthreads();
    const float* xb = x + ((long)bt*CC)*NSP;
    #pragma unroll
    for (int u=0; u<16; u++){
        int e = tid + u*256;
        int k = e & 31, c = e >> 5;
        tile[c][k] = xb[(long)c*NSP + nsh[k]] * ssh[k];
    }
    __syncthreads();
    {
        int k = tid & 31, part = tid >> 5;
        float s = 0.f;
        #pragma unroll
        for (int j=0;j<16;j++){ float v = tile[part*16+j][k]; s += v*v; }
        red[k][part] = s;
    }
    __syncthreads();
    if (tid < 32){
        float s = 0.f;
        #pragma unroll
        for (int p=0;p<8;p++) s += red[tid][p];
        rst[tid] = rsqrtf(s*(1.f/128.f) + 1e-5f);
    }
    __syncthreads();
    #pragma unroll
    for (int u=0; u<8; u++){
        int e = tid + u*256;
        int c2 = e & 63, k = e >> 6;
        long row = (((long)b*KK + kc*32 + k)*TT + t);
        float r = rst[k];
        z0p[row*64 + c2] = pk(tile[2*c2][k]*r*nw[2*c2], tile[2*c2+1][k]*r*nw[2*c2+1]);
    }
}

// conv1d + silu, 128 threads handle channel pairs, packed bf16 out
__global__ void k_conv1d(const float* __restrict__ xz, const float* __restrict__ w,
                         const float* __restrict__ bias, uint32_t* __restrict__ xcp){
    int s = blockIdx.x; int c2 = threadIdx.x;   // 4096 blocks x 128 thr
    float2 in[TT];
    #pragma unroll
    for (int t=0;t<TT;t++)
        in[t] = *(const float2*)(xz + ((long)s*TT + t)*(2*DI) + 2*c2);
    int ch0 = 2*c2, ch1 = 2*c2+1;
    float a0_[4] = {w[ch0*4+0], w[ch0*4+1], w[ch0*4+2], w[ch0*4+3]};
    float a1_[4] = {w[ch1*4+0], w[ch1*4+1], w[ch1*4+2], w[ch1*4+3]};
    float b0 = bias[ch0], b1 = bias[ch1];
    #pragma unroll
    for (int t=0;t<TT;t++){
        float v0 = b0 + in[t].x*a0_[3];
        float v1 = b1 + in[t].y*a1_[3];
        if (t>=1){ v0 += in[t-1].x*a0_[2]; v1 += in[t-1].y*a1_[2]; }
        if (t>=2){ v0 += in[t-2].x*a0_[1]; v1 += in[t-2].y*a1_[1]; }
        if (t>=3){ v0 += in[t-3].x*a0_[0]; v1 += in[t-3].y*a1_[0]; }
        xcp[((long)s*TT + t)*128 + c2] = pk(siluf(v0), siluf(v1));
    }
}

// fused conv-recompute + dt_proj + scan + gate, packed bf16 out
__global__ void k_scan3(const float* __restrict__ xz, const float* __restrict__ xdbl,
                        const float* __restrict__ dtw, const float* __restrict__ dtbias,
                        const float* __restrict__ Alog, const float* __restrict__ Dp,
                        const float* __restrict__ cw, const float* __restrict__ cb,
                        uint32_t* __restrict__ ygp){
    __shared__ float xd[TT][40];
    __shared__ float ys[TT][256];
    int s = blockIdx.x; int ch = threadIdx.x;
    for (int i = ch; i < TT*40; i += 256)
        xd[i/40][i%40] = xdbl[(long)s*TT*40 + i];
    float w8[DTR];
    #pragma unroll
    for (int r=0;r<DTR;r++) w8[r] = dtw[ch*DTR + r];
    float db = dtbias[ch];
    float cw0=cw[ch*4+0], cw1=cw[ch*4+1], cw2=cw[ch*4+2], cw3=cw[ch*4+3];
    float cbb = cb[ch];
    float in[TT];
    #pragma unroll
    for (int t=0;t<TT;t++) in[t] = xz[(((long)s*TT + t)*(2*DI)) + ch];
    float Arow[DS];
    #pragma unroll
    for (int d=0;d<DS;d++) Arow[d] = -__expf(Alog[ch*DS + d]);
    float A0 = Arow[0];
    bool geom = true;
    #pragma unroll
    for (int d=1;d<DS;d++)
        geom = geom && (fabsf(Arow[d] - A0*(float)(d+1)) <= 1e-5f*fabsf(A0*(float)(d+1)) + 1e-12f);
    float Dv = Dp[ch];
    __syncthreads();
    float h[DS];
    #pragma unroll
    for (int d=0;d<DS;d++) h[d] = 0.f;
    #pragma unroll
    for (int t=0;t<TT;t++){
        long row = (long)s*TT + t;
        float a = cbb + in[t]*cw3;
        if (t>=1) a += in[t-1]*cw2;
        if (t>=2) a += in[t-2]*cw1;
        if (t>=3) a += in[t-3]*cw0;
        float u = siluf(a);
        float dtr = db;
        #pragma unroll
        for (int r=0;r<DTR;r++) dtr += xd[t][r]*w8[r];
        float dt = softplusf(dtr);
        float du = dt*u;
        float y = 0.f;
        if (geom){
            float e1 = __expf(dt*A0);
            float ed = 1.f;
            #pragma unroll
            for (int d=0;d<DS;d++){
                ed *= e1;
                float Bv = xd[t][DTR + d];
                float Cv = xd[t][DTR + DS + d];
                h[d] = h[d]*ed + du*Bv;
                y += h[d]*Cv;
            }
        } else {
            #pragma unroll
            for (int d=0;d<DS;d++){
                float Bv = xd[t][DTR + d];
                float Cv = xd[t][DTR + DS + d];
                h[d] = h[d]*__expf(dt*Arow[d]) + du*Bv;
                y += h[d]*Cv;
            }
        }
        float zg = xz[row*(2*DI) + DI + ch];
        ys[t][ch] = (y + u*Dv) * siluf(zg);
    }
    __syncthreads();
    for (int i = ch; i < TT*128; i += 256){
        int t = i >> 7, c2 = i & 127;
        ygp[((long)s*TT + t)*128 + c2] = pk(ys[t][2*c2], ys[t][2*c2+1]);
    }
}

// ---------------- host launch ----------------
static void* symv(const void* s){ void* p = nullptr; cudaGetSymbolAddress(&p, s); return p; }

extern "C" void kernel_launch(void* const* d_in, const int* in_sizes, int n_in,
                              void* d_out, int out_size)
{
    const float* x_in      = (const float*)d_in[0];
    const float* norm1_w   = (const float*)d_in[1];
    const float* in_proj_w = (const float*)d_in[2];
    const float* conv1d_w  = (const float*)d_in[3];
    const float* conv1d_b  = (const float*)d_in[4];
    const float* x_proj_w  = (const float*)d_in[5];
    const float* dt_proj_w = (const float*)d_in[6];
    const float* dt_proj_b = (const float*)d_in[7];
    const float* A_log     = (const float*)d_in[8];
    const float* Dp        = (const float*)d_in[9];
    const float* out_proj_w= (const float*)d_in[10];
    const float* r1_w      = (const float*)d_in[11];
    const float* r1_b      = (const float*)d_in[12];
    const float* r2_w      = (const float*)d_in[13];
    const float* r2_b      = (const float*)d_in[14];
    const float* attn_in_w = (const float*)d_in[15];
    const float* attn_in_b = (const float*)d_in[16];
    const float* attn_out_w= (const float*)d_in[17];
    const float* attn_out_b= (const float*)d_in[18];
    const float* ln_w      = (const float*)d_in[19];
    const float* ln_b      = (const float*)d_in[20];
    float* out = (float*)d_out;

    float *xm = (float*)symv(g_xm), *h1 = (float*)symv(g_h1);
    float *scl = (float*)symv(g_scl), *xz = (float*)symv(g_xz);
    float *xdbl = (float*)symv(g_xdbl), *zsb = (float*)symv(g_zs);
    uint32_t *z0p = (uint32_t*)symv(g_z0p), *xcp = (uint32_t*)symv(g_xcp);
    uint32_t *ygp = (uint32_t*)symv(g_ygp), *qkvp = (uint32_t*)symv(g_qkvp);
    uint32_t *orpp = (uint32_t*)symv(g_orpp);
    int* idx = (int*)symv(g_idx);

    static int smem_set = 0;
    if (!smem_set){
        cudaFuncSetAttribute(k_flash2, cudaFuncAttributeMaxDynamicSharedMemorySize, 57344);
        smem_set = 1;
    }

    // 1) router
    k_mean<<<(BB*CC*NSP+255)/256, 256>>>(x_in, xm);
    k_conv3<<<BB*32, 1024>>>(xm, r1_w, r1_b, h1);
    k_scoretopk<<<BB, 1024>>>(h1, r2_w, r2_b, idx, scl);
    // 2) gather + rmsnorm (bf16 out)   (profiled launch slot)
    k_gather2<<<dim3(BB*TT, 16), 256>>>(x_in, idx, scl, norm1_w, z0p);
    // 3) mamba
    gemm_bf<128,0,true><<<dim3(4,256),256>>>(z0p, in_proj_w, nullptr, xz,
        ROWS, 2*DI, CC, 64, CC, 2*DI, nullptr, nullptr, nullptr, nullptr);
    k_conv1d<<<ROWS/TT, 128>>>(xz, conv1d_w, conv1d_b, xcp);
    gemm_bf<64,0,true><<<dim3(1,256),256>>>(xcp, x_proj_w, nullptr, xdbl,
        ROWS, 40, DI, 128, DI, 40, nullptr, nullptr, nullptr, nullptr);
    k_scan3<<<ROWS/TT, DI>>>(xz, xdbl, dt_proj_w, dt_proj_b, A_log, Dp,
        conv1d_w, conv1d_b, ygp);
    gemm_bf<128,1,true><<<dim3(1,256),256>>>(ygp, out_proj_w, nullptr, zsb,
        ROWS, CC, DI, 128, DI, CC, nullptr, nullptr, nullptr, nullptr);
    // 4) attention (qkv packed bf16, Q pre-scaled)
    gemm_bf<128,4,false><<<dim3(3,256),256>>>(zsb, attn_in_w, attn_in_b, qkvp,
        ROWS, 3*CC, CC, CC, CC, 192, nullptr, nullptr, nullptr, nullptr);
    k_flash2<<<dim3(4, NBATCH), 256, 56320>>>(qkvp, orpp);
    // 5) out = x_in, then attn_out + LayerNorm + coalesced scatter-add
    {
        int n4 = (BB*TT*CC*NSP)/4;
        k_copy<<<(n4+255)/256, 256>>>((const float4*)x_in, (float4*)out, n4);
    }
    gemm_bf<128,2,true><<<dim3(1,256),256>>>(orpp, attn_out_w, attn_out_b, out,
        ROWS, CC, CC, 64, CC, NSP, zsb, ln_w, ln_b, idx);
}